// round 3
// baseline (speedup 1.0000x reference)
#include <cuda_runtime.h>
#include <cuda_bf16.h>
#include <math.h>

// Problem constants
#define B_E 128
#define L_L 256
#define HH  12
#define DH  64
#define DD  768           // H*DH
#define N3  2304          // 3*D
#define MROWS (B_E * L_L) // 32768
#define EPS 1e-5f
#define NEGV -10000.0f
#define QSCALE 0.125f     // DH^-0.5

// -------- scratch (allocation-free: __device__ globals) --------
__device__ float g_qkv[(size_t)MROWS * N3];   // 302 MB, reused by both stages
__device__ float g_att[(size_t)MROWS * DD];   // attention output
__device__ float g_out1[(size_t)MROWS * DD];  // after first LayerNorm

// ============================================================
// GEMM: C[m,n] = sum_k A[m,k] * W[n,k] + bias[n]
// A: [M,K] row-major, W: [N,K] row-major. 64x64 tile, 4x4/thread.
// ============================================================
__global__ void __launch_bounds__(256) gemm_bias_kernel(
    const float* __restrict__ A, const float* __restrict__ W,
    const float* __restrict__ bias, float* __restrict__ C,
    int M, int N, int K)
{
    __shared__ float As[16][68];
    __shared__ float Bs[16][68];

    const int tx = threadIdx.x;      // 0..15
    const int ty = threadIdx.y;      // 0..15
    const int t  = ty * 16 + tx;
    const int m0 = blockIdx.y * 64;
    const int n0 = blockIdx.x * 64;

    const int lm = t >> 2;           // 0..63  (row within tile)
    const int lk = (t & 3) * 4;      // 0,4,8,12

    float acc[4][4];
#pragma unroll
    for (int i = 0; i < 4; i++)
#pragma unroll
        for (int j = 0; j < 4; j++) acc[i][j] = 0.f;

    for (int k0 = 0; k0 < K; k0 += 16) {
        __syncthreads();
        float4 av = *(const float4*)(A + (size_t)(m0 + lm) * K + k0 + lk);
        float4 wv = *(const float4*)(W + (size_t)(n0 + lm) * K + k0 + lk);
        As[lk + 0][lm] = av.x; As[lk + 1][lm] = av.y;
        As[lk + 2][lm] = av.z; As[lk + 3][lm] = av.w;
        Bs[lk + 0][lm] = wv.x; Bs[lk + 1][lm] = wv.y;
        Bs[lk + 2][lm] = wv.z; Bs[lk + 3][lm] = wv.w;
        __syncthreads();

#pragma unroll
        for (int kk = 0; kk < 16; kk++) {
            float4 a4 = *(const float4*)&As[kk][ty * 4];
            float4 b4 = *(const float4*)&Bs[kk][tx * 4];
            float a[4] = {a4.x, a4.y, a4.z, a4.w};
            float b[4] = {b4.x, b4.y, b4.z, b4.w};
#pragma unroll
            for (int i = 0; i < 4; i++)
#pragma unroll
                for (int j = 0; j < 4; j++)
                    acc[i][j] += a[i] * b[j];
        }
    }

#pragma unroll
    for (int i = 0; i < 4; i++) {
        const int m = m0 + ty * 4 + i;
#pragma unroll
        for (int j = 0; j < 4; j++) {
            const int n = n0 + tx * 4 + j;
            C[(size_t)m * N + n] = acc[i][j] + bias[n];
        }
    }
}

// ============================================================
// Row attention: per (e,h) block; 256 threads = 256 queries (L).
// Online softmax over 256 keys (chunks of 64 staged in smem).
// scores[i,j] = q[e,i,h,:].k[e,j,h,:]*scale + (mask[e,j]?NEG:0)
// ============================================================
__global__ void __launch_bounds__(256, 1) row_attn_kernel(
    const float* __restrict__ qkv, const int* __restrict__ mask,
    float* __restrict__ out)
{
    const int e = blockIdx.x;
    const int h = blockIdx.y;
    const int i = threadIdx.x;   // query index (L)

    __shared__ float ks[64][64];
    __shared__ float vs[64][64];
    __shared__ float nm[64];

    float q[64];
    {
        const float* qp = qkv + (size_t)(e * L_L + i) * N3 + h * DH;
#pragma unroll
        for (int d = 0; d < 64; d++) q[d] = qp[d] * QSCALE;
    }

    float mrun = -1e30f, ssum = 0.f;
    float acc[64];
#pragma unroll
    for (int d = 0; d < 64; d++) acc[d] = 0.f;

    for (int c = 0; c < 4; c++) {
        __syncthreads();
        // cooperative load of 64 keys + 64 values (64x64 floats each)
        const int jbase = c * 64;
#pragma unroll
        for (int r = 0; r < 4; r++) {
            int p  = threadIdx.x + r * 256;   // 0..1023 float4 slots
            int jj = p >> 4;
            int d4 = (p & 15) * 4;
            const float* kb = qkv + (size_t)(e * L_L + jbase + jj) * N3 + DD  + h * DH + d4;
            const float* vb = qkv + (size_t)(e * L_L + jbase + jj) * N3 + 2*DD + h * DH + d4;
            *(float4*)&ks[jj][d4] = *(const float4*)kb;
            *(float4*)&vs[jj][d4] = *(const float4*)vb;
        }
        if (threadIdx.x < 64)
            nm[threadIdx.x] = mask[e * L_L + jbase + threadIdx.x] ? NEGV : 0.f;
        __syncthreads();

        for (int j = 0; j < 64; j++) {
            float s = 0.f;
#pragma unroll
            for (int d = 0; d < 64; d++) s += q[d] * ks[j][d];
            s += nm[j];
            float mn   = fmaxf(mrun, s);
            float corr = __expf(mrun - mn);
            float p    = __expf(s - mn);
            ssum = ssum * corr + p;
#pragma unroll
            for (int d = 0; d < 64; d++) acc[d] = acc[d] * corr + p * vs[j][d];
            mrun = mn;
        }
    }

    const float inv = 1.f / ssum;
    float* op = out + (size_t)(e * L_L + i) * DD + h * DH;
#pragma unroll
    for (int d = 0; d < 64; d++) op[d] = acc[d] * inv;
}

// ============================================================
// Column attention: per (l,h) block; 128 threads = 128 queries (E).
// scores[i,j] = q[i,l,h,:].k[j,l,h,:]*scale + (mask[j,l]?NEG:0), softmax over j
// ============================================================
__global__ void __launch_bounds__(128, 1) col_attn_kernel(
    const float* __restrict__ qkv, const int* __restrict__ mask,
    float* __restrict__ out)
{
    const int l = blockIdx.x;
    const int h = blockIdx.y;
    const int i = threadIdx.x;   // query index (E)

    __shared__ float ks[64][64];
    __shared__ float vs[64][64];
    __shared__ float nm[64];

    float q[64];
    {
        const float* qp = qkv + (size_t)(i * L_L + l) * N3 + h * DH;
#pragma unroll
        for (int d = 0; d < 64; d++) q[d] = qp[d] * QSCALE;
    }

    float mrun = -1e30f, ssum = 0.f;
    float acc[64];
#pragma unroll
    for (int d = 0; d < 64; d++) acc[d] = 0.f;

    for (int c = 0; c < 2; c++) {
        __syncthreads();
        const int jbase = c * 64;
#pragma unroll
        for (int r = 0; r < 8; r++) {
            int p  = threadIdx.x + r * 128;   // 0..1023 float4 slots
            int jj = p >> 4;
            int d4 = (p & 15) * 4;
            const float* kb = qkv + (size_t)((jbase + jj) * L_L + l) * N3 + DD   + h * DH + d4;
            const float* vb = qkv + (size_t)((jbase + jj) * L_L + l) * N3 + 2*DD + h * DH + d4;
            *(float4*)&ks[jj][d4] = *(const float4*)kb;
            *(float4*)&vs[jj][d4] = *(const float4*)vb;
        }
        if (threadIdx.x < 64)
            nm[threadIdx.x] = mask[(jbase + threadIdx.x) * L_L + l] ? NEGV : 0.f;
        __syncthreads();

        for (int j = 0; j < 64; j++) {
            float s = 0.f;
#pragma unroll
            for (int d = 0; d < 64; d++) s += q[d] * ks[j][d];
            s += nm[j];
            float mn   = fmaxf(mrun, s);
            float corr = __expf(mrun - mn);
            float p    = __expf(s - mn);
            ssum = ssum * corr + p;
#pragma unroll
            for (int d = 0; d < 64; d++) acc[d] = acc[d] * corr + p * vs[j][d];
            mrun = mn;
        }
    }

    const float inv = 1.f / ssum;
    float* op = out + (size_t)(i * L_L + l) * DD + h * DH;
#pragma unroll
    for (int d = 0; d < 64; d++) op[d] = acc[d] * inv;
}

// ============================================================
// Fused residual-add + LayerNorm over D=768. One block per row.
// dst[m,:] = LN(a[m,:] + b[m,:]) * g + beta
// ============================================================
__global__ void __launch_bounds__(256) add_ln_kernel(
    const float* __restrict__ a, const float* __restrict__ b,
    const float* __restrict__ g, const float* __restrict__ beta,
    float* __restrict__ dst)
{
    const int m = blockIdx.x;
    const int t = threadIdx.x;
    __shared__ float red[256];

    float v[3];
    float s = 0.f;
#pragma unroll
    for (int r = 0; r < 3; r++) {
        int idx = t + r * 256;
        v[r] = a[(size_t)m * DD + idx] + b[(size_t)m * DD + idx];
        s += v[r];
    }
    red[t] = s;
    __syncthreads();
    for (int o = 128; o > 0; o >>= 1) {
        if (t < o) red[t] += red[t + o];
        __syncthreads();
    }
    const float mu = red[0] * (1.f / DD);
    __syncthreads();

    float sq = 0.f;
#pragma unroll
    for (int r = 0; r < 3; r++) {
        float d = v[r] - mu;
        sq += d * d;
    }
    red[t] = sq;
    __syncthreads();
    for (int o = 128; o > 0; o >>= 1) {
        if (t < o) red[t] += red[t + o];
        __syncthreads();
    }
    const float rstd = rsqrtf(red[0] * (1.f / DD) + EPS);

#pragma unroll
    for (int r = 0; r < 3; r++) {
        int idx = t + r * 256;
        dst[(size_t)m * DD + idx] = (v[r] - mu) * rstd * g[idx] + beta[idx];
    }
}

// ============================================================
// Launch
// ============================================================
extern "C" void kernel_launch(void* const* d_in, const int* in_sizes, int n_in,
                              void* d_out, int out_size)
{
    const float* x     = (const float*)d_in[0];
    const float* w_row = (const float*)d_in[1];
    const float* b_row = (const float*)d_in[2];
    const float* w_col = (const float*)d_in[3];
    const float* b_col = (const float*)d_in[4];
    const float* g1    = (const float*)d_in[5];
    const float* beta1 = (const float*)d_in[6];
    const float* g2    = (const float*)d_in[7];
    const float* beta2 = (const float*)d_in[8];
    const int*   mask  = (const int*)d_in[9];   // padding_mask as int32
    float* out = (float*)d_out;

    float *qkv, *att, *out1;
    cudaGetSymbolAddress((void**)&qkv,  g_qkv);
    cudaGetSymbolAddress((void**)&att,  g_att);
    cudaGetSymbolAddress((void**)&out1, g_out1);

    dim3 gblk(16, 16);
    dim3 ggrd(N3 / 64, MROWS / 64);   // (36, 512)

    // ---- stage 1: row attention ----
    gemm_bias_kernel<<<ggrd, gblk>>>(x, w_row, b_row, qkv, MROWS, N3, DD);
    row_attn_kernel<<<dim3(B_E, HH), 256>>>(qkv, mask, att);
    add_ln_kernel<<<MROWS, 256>>>(x, att, g1, beta1, out1);

    // ---- stage 2: column attention ----
    gemm_bias_kernel<<<ggrd, gblk>>>(out1, w_col, b_col, qkv, MROWS, N3, DD);
    col_attn_kernel<<<dim3(L_L, HH), 128>>>(qkv, mask, att);
    add_ln_kernel<<<MROWS, 256>>>(out1, att, g2, beta2, out);
}

// round 6
// speedup vs baseline: 3.1042x; 3.1042x over previous
#include <cuda_runtime.h>
#include <cuda_bf16.h>
#include <math.h>
#include <cstdint>

// Problem constants
#define B_E 128
#define L_L 256
#define HH  12
#define DH  64
#define DD  768           // H*DH
#define N3  2304          // 3*D
#define MROWS (B_E * L_L) // 32768
#define EPS 1e-5f
#define NEGV -10000.0f
#define QSCALE 0.125f     // DH^-0.5

// -------- scratch (allocation-free: __device__ globals) --------
__device__ float g_qkv[(size_t)MROWS * N3];   // 302 MB, reused by both stages
__device__ float g_att[(size_t)MROWS * DD];   // attention output
__device__ float g_out1[(size_t)MROWS * DD];  // after first LayerNorm
__device__ __nv_bfloat16 g_ahi[(size_t)MROWS * DD];  // activation hi
__device__ __nv_bfloat16 g_alo[(size_t)MROWS * DD];  // activation lo
__device__ __nv_bfloat16 g_whi[(size_t)N3 * DD];     // weight hi
__device__ __nv_bfloat16 g_wlo[(size_t)N3 * DD];     // weight lo

// ============================================================
// fp32 -> (bf16 hi, bf16 lo) split.  a = hi + lo
// ============================================================
__global__ void __launch_bounds__(256) split_kernel(
    const float* __restrict__ in,
    __nv_bfloat16* __restrict__ hi, __nv_bfloat16* __restrict__ lo, int n4)
{
    int i = blockIdx.x * blockDim.x + threadIdx.x;
    int stride = gridDim.x * blockDim.x;
    for (; i < n4; i += stride) {
        float4 v = ((const float4*)in)[i];
        __nv_bfloat16 h0 = __float2bfloat16(v.x);
        __nv_bfloat16 h1 = __float2bfloat16(v.y);
        __nv_bfloat16 h2 = __float2bfloat16(v.z);
        __nv_bfloat16 h3 = __float2bfloat16(v.w);
        __nv_bfloat16 l0 = __float2bfloat16(v.x - __bfloat162float(h0));
        __nv_bfloat16 l1 = __float2bfloat16(v.y - __bfloat162float(h1));
        __nv_bfloat16 l2 = __float2bfloat16(v.z - __bfloat162float(h2));
        __nv_bfloat16 l3 = __float2bfloat16(v.w - __bfloat162float(h3));
        ((__nv_bfloat162*)hi)[2 * i + 0] = __halves2bfloat162(h0, h1);
        ((__nv_bfloat162*)hi)[2 * i + 1] = __halves2bfloat162(h2, h3);
        ((__nv_bfloat162*)lo)[2 * i + 0] = __halves2bfloat162(l0, l1);
        ((__nv_bfloat162*)lo)[2 * i + 1] = __halves2bfloat162(l2, l3);
    }
}

// ============================================================
// Warp-MMA bf16 GEMM (legacy mma.sync path — tcgen05 not available
// through this toolchain's compute_103 virtual arch).
//   C[m,n] = sum_k A[m,k]*W[n,k] + bias[n]
//   A = ahi+alo, W = whi+wlo; C ~= ah*wh + ah*wl + al*wh (fp32 acc)
// Block tile 128x128, 8 warps (2x4), warp tile 64x32, K-chunk 32,
// cp.async double-buffered smem, rows padded to 40 halves
// (word index = 20*row + tig covers all 32 banks -> conflict-free LDS).
// ============================================================
#define BK 32
#define ASTR 40                       // padded row stride in halves
#define ROWB (ASTR * 2)               // 80 bytes per row
#define TILE_BYTES (128 * ROWB)       // 10240
#define STAGE_BYTES (4 * TILE_BYTES)  // 40960: Ah, Al, Bh, Bl
#define GEMM_SMEM (2 * STAGE_BYTES)   // 81920 double-buffered

__device__ __forceinline__ uint32_t smem_u32(const void* p) {
    uint32_t a;
    asm("{ .reg .u64 t; cvta.to.shared.u64 t, %1; cvt.u32.u64 %0, t; }"
        : "=r"(a) : "l"(p));
    return a;
}

#define MMA_BF16(d, a, b)                                                     \
    asm volatile(                                                             \
        "mma.sync.aligned.m16n8k16.row.col.f32.bf16.bf16.f32 "                \
        "{%0,%1,%2,%3}, {%4,%5,%6,%7}, {%8,%9}, {%0,%1,%2,%3};"               \
        : "+f"(d[0]), "+f"(d[1]), "+f"(d[2]), "+f"(d[3])                      \
        : "r"(a[0]), "r"(a[1]), "r"(a[2]), "r"(a[3]), "r"(b[0]), "r"(b[1]))

__device__ __forceinline__ void load_stage_async(
    uint32_t sb, int stage,
    const __nv_bfloat16* __restrict__ Ahi, const __nv_bfloat16* __restrict__ Alo,
    const __nv_bfloat16* __restrict__ Whi, const __nv_bfloat16* __restrict__ Wlo,
    size_t m0, size_t n0, int k0, int tid)
{
    // 4 arrays x 128 rows x 4 x 16B chunks = 2048 chunks over 256 threads
#pragma unroll
    for (int i = 0; i < 8; i++) {
        const int arr = i >> 1;                 // 0:Ah 1:Al 2:Bh 3:Bl
        const int rem = (i & 1) * 256 + tid;    // 0..511
        const int row = rem >> 2;
        const int seg = rem & 3;
        const __nv_bfloat16* src;
        size_t r0;
        if      (arr == 0) { src = Ahi; r0 = m0; }
        else if (arr == 1) { src = Alo; r0 = m0; }
        else if (arr == 2) { src = Whi; r0 = n0; }
        else               { src = Wlo; r0 = n0; }
        const void* g = src + (r0 + row) * DD + k0 + seg * 8;
        uint32_t s = sb + stage * STAGE_BYTES + arr * TILE_BYTES
                   + row * ROWB + seg * 16;
        asm volatile("cp.async.cg.shared.global [%0], [%1], 16;"
                     :: "r"(s), "l"(g));
    }
}

__global__ void __launch_bounds__(256, 1) mma_gemm_kernel(
    const __nv_bfloat16* __restrict__ Ahi, const __nv_bfloat16* __restrict__ Alo,
    const __nv_bfloat16* __restrict__ Whi, const __nv_bfloat16* __restrict__ Wlo,
    const float* __restrict__ bias, float* __restrict__ C)
{
    extern __shared__ char sm[];
    const int tid  = threadIdx.x;
    const int wid  = tid >> 5;
    const int lane = tid & 31;
    const int wm   = wid >> 2;        // 0..1  (64 rows each)
    const int wn   = wid & 3;         // 0..3  (32 cols each)
    const int g    = lane >> 2;       // group id 0..7
    const int tig  = lane & 3;        // thread in group

    const size_t m0 = (size_t)blockIdx.y * 128;
    const size_t n0 = (size_t)blockIdx.x * 128;
    const uint32_t sb = smem_u32(sm);

    float acc[4][4][4];
#pragma unroll
    for (int mt = 0; mt < 4; mt++)
#pragma unroll
        for (int nt = 0; nt < 4; nt++)
#pragma unroll
            for (int r = 0; r < 4; r++) acc[mt][nt][r] = 0.f;

    load_stage_async(sb, 0, Ahi, Alo, Whi, Wlo, m0, n0, 0, tid);
    asm volatile("cp.async.commit_group;" ::: "memory");

    const int NKT = DD / BK;   // 24
    for (int kt = 0; kt < NKT; kt++) {
        if (kt < NKT - 1) {
            load_stage_async(sb, (kt + 1) & 1, Ahi, Alo, Whi, Wlo,
                             m0, n0, (kt + 1) * BK, tid);
            asm volatile("cp.async.commit_group;" ::: "memory");
            asm volatile("cp.async.wait_group 1;" ::: "memory");
        } else {
            asm volatile("cp.async.wait_group 0;" ::: "memory");
        }
        __syncthreads();

        const char* sA_h = sm + (kt & 1) * STAGE_BYTES;
        const char* sA_l = sA_h + TILE_BYTES;
        const char* sB_h = sA_h + 2 * TILE_BYTES;
        const char* sB_l = sA_h + 3 * TILE_BYTES;

#pragma unroll
        for (int kk = 0; kk < 2; kk++) {
            const int kb = kk * 16;
            uint32_t ah[4][4], al[4][4];
#pragma unroll
            for (int mt = 0; mt < 4; mt++) {
                const int row = wm * 64 + mt * 16 + g;
                const char* ph = sA_h + row * ROWB + (kb + tig * 2) * 2;
                const char* pl = sA_l + row * ROWB + (kb + tig * 2) * 2;
                ah[mt][0] = *(const uint32_t*)(ph);
                ah[mt][1] = *(const uint32_t*)(ph + 8 * ROWB);
                ah[mt][2] = *(const uint32_t*)(ph + 16);
                ah[mt][3] = *(const uint32_t*)(ph + 8 * ROWB + 16);
                al[mt][0] = *(const uint32_t*)(pl);
                al[mt][1] = *(const uint32_t*)(pl + 8 * ROWB);
                al[mt][2] = *(const uint32_t*)(pl + 16);
                al[mt][3] = *(const uint32_t*)(pl + 8 * ROWB + 16);
            }
            uint32_t bh[4][2], bl[4][2];
#pragma unroll
            for (int nt = 0; nt < 4; nt++) {
                const int col = wn * 32 + nt * 8 + g;
                const char* ph = sB_h + col * ROWB + (kb + tig * 2) * 2;
                const char* pl = sB_l + col * ROWB + (kb + tig * 2) * 2;
                bh[nt][0] = *(const uint32_t*)(ph);
                bh[nt][1] = *(const uint32_t*)(ph + 16);
                bl[nt][0] = *(const uint32_t*)(pl);
                bl[nt][1] = *(const uint32_t*)(pl + 16);
            }
#pragma unroll
            for (int mt = 0; mt < 4; mt++)
#pragma unroll
                for (int nt = 0; nt < 4; nt++) {
                    MMA_BF16(acc[mt][nt], ah[mt], bh[nt]);
                    MMA_BF16(acc[mt][nt], ah[mt], bl[nt]);
                    MMA_BF16(acc[mt][nt], al[mt], bh[nt]);
                }
        }
        __syncthreads();
    }

    // Epilogue: c0,c1 -> (row g, col tig*2..+1); c2,c3 -> row g+8
#pragma unroll
    for (int mt = 0; mt < 4; mt++) {
        const size_t row = m0 + wm * 64 + mt * 16 + g;
#pragma unroll
        for (int nt = 0; nt < 4; nt++) {
            const size_t col = n0 + wn * 32 + nt * 8 + tig * 2;
            const float b0 = bias[col], b1 = bias[col + 1];
            float2 o0 = {acc[mt][nt][0] + b0, acc[mt][nt][1] + b1};
            float2 o1 = {acc[mt][nt][2] + b0, acc[mt][nt][3] + b1};
            *(float2*)(C + row * N3 + col)       = o0;
            *(float2*)(C + (row + 8) * N3 + col) = o1;
        }
    }
}

// ============================================================
// Row attention: per (e,h) block; 256 threads = 256 queries (L).
// ============================================================
__global__ void __launch_bounds__(256, 1) row_attn_kernel(
    const float* __restrict__ qkv, const int* __restrict__ mask,
    float* __restrict__ out)
{
    const int e = blockIdx.x;
    const int h = blockIdx.y;
    const int i = threadIdx.x;   // query index (L)

    __shared__ float ks[64][64];
    __shared__ float vs[64][64];
    __shared__ float nm[64];

    float q[64];
    {
        const float* qp = qkv + (size_t)(e * L_L + i) * N3 + h * DH;
#pragma unroll
        for (int d = 0; d < 64; d++) q[d] = qp[d] * QSCALE;
    }

    float mrun = -1e30f, ssum = 0.f;
    float acc[64];
#pragma unroll
    for (int d = 0; d < 64; d++) acc[d] = 0.f;

    for (int c = 0; c < 4; c++) {
        __syncthreads();
        const int jbase = c * 64;
#pragma unroll
        for (int r = 0; r < 4; r++) {
            int p  = threadIdx.x + r * 256;
            int jj = p >> 4;
            int d4 = (p & 15) * 4;
            const float* kb = qkv + (size_t)(e * L_L + jbase + jj) * N3 + DD   + h * DH + d4;
            const float* vb = qkv + (size_t)(e * L_L + jbase + jj) * N3 + 2*DD + h * DH + d4;
            *(float4*)&ks[jj][d4] = *(const float4*)kb;
            *(float4*)&vs[jj][d4] = *(const float4*)vb;
        }
        if (threadIdx.x < 64)
            nm[threadIdx.x] = mask[e * L_L + jbase + threadIdx.x] ? NEGV : 0.f;
        __syncthreads();

        for (int j = 0; j < 64; j++) {
            float s = 0.f;
#pragma unroll
            for (int d = 0; d < 64; d++) s += q[d] * ks[j][d];
            s += nm[j];
            float mn   = fmaxf(mrun, s);
            float corr = __expf(mrun - mn);
            float p    = __expf(s - mn);
            ssum = ssum * corr + p;
#pragma unroll
            for (int d = 0; d < 64; d++) acc[d] = acc[d] * corr + p * vs[j][d];
            mrun = mn;
        }
    }

    const float inv = 1.f / ssum;
    float* op = out + (size_t)(e * L_L + i) * DD + h * DH;
#pragma unroll
    for (int d = 0; d < 64; d++) op[d] = acc[d] * inv;
}

// ============================================================
// Column attention: per (l,h) block; 128 threads = 128 queries (E).
// ============================================================
__global__ void __launch_bounds__(128, 1) col_attn_kernel(
    const float* __restrict__ qkv, const int* __restrict__ mask,
    float* __restrict__ out)
{
    const int l = blockIdx.x;
    const int h = blockIdx.y;
    const int i = threadIdx.x;   // query index (E)

    __shared__ float ks[64][64];
    __shared__ float vs[64][64];
    __shared__ float nm[64];

    float q[64];
    {
        const float* qp = qkv + (size_t)(i * L_L + l) * N3 + h * DH;
#pragma unroll
        for (int d = 0; d < 64; d++) q[d] = qp[d] * QSCALE;
    }

    float mrun = -1e30f, ssum = 0.f;
    float acc[64];
#pragma unroll
    for (int d = 0; d < 64; d++) acc[d] = 0.f;

    for (int c = 0; c < 2; c++) {
        __syncthreads();
        const int jbase = c * 64;
#pragma unroll
        for (int r = 0; r < 8; r++) {
            int p  = threadIdx.x + r * 128;
            int jj = p >> 4;
            int d4 = (p & 15) * 4;
            const float* kb = qkv + (size_t)((jbase + jj) * L_L + l) * N3 + DD   + h * DH + d4;
            const float* vb = qkv + (size_t)((jbase + jj) * L_L + l) * N3 + 2*DD + h * DH + d4;
            *(float4*)&ks[jj][d4] = *(const float4*)kb;
            *(float4*)&vs[jj][d4] = *(const float4*)vb;
        }
        if (threadIdx.x < 64)
            nm[threadIdx.x] = mask[(jbase + threadIdx.x) * L_L + l] ? NEGV : 0.f;
        __syncthreads();

        for (int j = 0; j < 64; j++) {
            float s = 0.f;
#pragma unroll
            for (int d = 0; d < 64; d++) s += q[d] * ks[j][d];
            s += nm[j];
            float mn   = fmaxf(mrun, s);
            float corr = __expf(mrun - mn);
            float p    = __expf(s - mn);
            ssum = ssum * corr + p;
#pragma unroll
            for (int d = 0; d < 64; d++) acc[d] = acc[d] * corr + p * vs[j][d];
            mrun = mn;
        }
    }

    const float inv = 1.f / ssum;
    float* op = out + (size_t)(i * L_L + l) * DD + h * DH;
#pragma unroll
    for (int d = 0; d < 64; d++) op[d] = acc[d] * inv;
}

// ============================================================
// Fused residual-add + LayerNorm over D=768. One block per row.
// ============================================================
__global__ void __launch_bounds__(256) add_ln_kernel(
    const float* __restrict__ a, const float* __restrict__ b,
    const float* __restrict__ g, const float* __restrict__ beta,
    float* __restrict__ dst)
{
    const int m = blockIdx.x;
    const int t = threadIdx.x;
    __shared__ float red[256];

    float v[3];
    float s = 0.f;
#pragma unroll
    for (int r = 0; r < 3; r++) {
        int idx = t + r * 256;
        v[r] = a[(size_t)m * DD + idx] + b[(size_t)m * DD + idx];
        s += v[r];
    }
    red[t] = s;
    __syncthreads();
    for (int o = 128; o > 0; o >>= 1) {
        if (t < o) red[t] += red[t + o];
        __syncthreads();
    }
    const float mu = red[0] * (1.f / DD);
    __syncthreads();

    float sq = 0.f;
#pragma unroll
    for (int r = 0; r < 3; r++) {
        float d = v[r] - mu;
        sq += d * d;
    }
    red[t] = sq;
    __syncthreads();
    for (int o = 128; o > 0; o >>= 1) {
        if (t < o) red[t] += red[t + o];
        __syncthreads();
    }
    const float rstd = rsqrtf(red[0] * (1.f / DD) + EPS);

#pragma unroll
    for (int r = 0; r < 3; r++) {
        int idx = t + r * 256;
        dst[(size_t)m * DD + idx] = (v[r] - mu) * rstd * g[idx] + beta[idx];
    }
}

// ============================================================
// Launch
// ============================================================
extern "C" void kernel_launch(void* const* d_in, const int* in_sizes, int n_in,
                              void* d_out, int out_size)
{
    const float* x     = (const float*)d_in[0];
    const float* w_row = (const float*)d_in[1];
    const float* b_row = (const float*)d_in[2];
    const float* w_col = (const float*)d_in[3];
    const float* b_col = (const float*)d_in[4];
    const float* g1    = (const float*)d_in[5];
    const float* beta1 = (const float*)d_in[6];
    const float* g2    = (const float*)d_in[7];
    const float* beta2 = (const float*)d_in[8];
    const int*   mask  = (const int*)d_in[9];
    float* out = (float*)d_out;

    float *qkv, *att, *out1;
    __nv_bfloat16 *ahi, *alo, *whi, *wlo;
    cudaGetSymbolAddress((void**)&qkv,  g_qkv);
    cudaGetSymbolAddress((void**)&att,  g_att);
    cudaGetSymbolAddress((void**)&out1, g_out1);
    cudaGetSymbolAddress((void**)&ahi,  g_ahi);
    cudaGetSymbolAddress((void**)&alo,  g_alo);
    cudaGetSymbolAddress((void**)&whi,  g_whi);
    cudaGetSymbolAddress((void**)&wlo,  g_wlo);

    cudaFuncSetAttribute(mma_gemm_kernel,
                         cudaFuncAttributeMaxDynamicSharedMemorySize, GEMM_SMEM);

    const int nA4 = MROWS * DD / 4;   // activation float4 count
    const int nW4 = N3 * DD / 4;      // weight float4 count
    dim3 tcg(N3 / 128, MROWS / 128);  // (18, 256)

    // ---- stage 1: row attention ----
    split_kernel<<<4096, 256>>>(x, ahi, alo, nA4);
    split_kernel<<<1024, 256>>>(w_row, whi, wlo, nW4);
    mma_gemm_kernel<<<tcg, 256, GEMM_SMEM>>>(ahi, alo, whi, wlo, b_row, qkv);
    row_attn_kernel<<<dim3(B_E, HH), 256>>>(qkv, mask, att);
    add_ln_kernel<<<MROWS, 256>>>(x, att, g1, beta1, out1);

    // ---- stage 2: column attention ----
    split_kernel<<<4096, 256>>>(out1, ahi, alo, nA4);
    split_kernel<<<1024, 256>>>(w_col, whi, wlo, nW4);
    mma_gemm_kernel<<<tcg, 256, GEMM_SMEM>>>(ahi, alo, whi, wlo, b_col, qkv);
    col_attn_kernel<<<dim3(L_L, HH), 128>>>(qkv, mask, att);
    add_ln_kernel<<<MROWS, 256>>>(out1, att, g2, beta2, out);
}

// round 7
// speedup vs baseline: 4.3149x; 1.3900x over previous
#include <cuda_runtime.h>
#include <cuda_bf16.h>
#include <math.h>
#include <cstdint>

// Problem constants
#define B_E 128
#define L_L 256
#define HH  12
#define DH  64
#define DD  768           // H*DH
#define N3  2304          // 3*D
#define MROWS (B_E * L_L) // 32768
#define EPS 1e-5f
#define NEGV -10000.0f
#define QSCALE 0.125f     // DH^-0.5

// -------- scratch (allocation-free: __device__ globals) --------
// g_qkv (fp32-sized) is carved into two bf16 arrays: qkv_hi | qkv_lo
__device__ float g_qkv[(size_t)MROWS * N3];
__device__ float g_att[(size_t)MROWS * DD];
__device__ float g_out1[(size_t)MROWS * DD];
__device__ __nv_bfloat16 g_ahi[(size_t)MROWS * DD];
__device__ __nv_bfloat16 g_alo[(size_t)MROWS * DD];
__device__ __nv_bfloat16 g_whi[(size_t)N3 * DD];
__device__ __nv_bfloat16 g_wlo[(size_t)N3 * DD];

// ============================================================
// helpers
// ============================================================
__device__ __forceinline__ uint32_t pack_bf16(float a, float b) {
    __nv_bfloat162 t = __halves2bfloat162(__float2bfloat16(a), __float2bfloat16(b));
    return *(uint32_t*)&t;
}
__device__ __forceinline__ void split_pack(float a, float b,
                                           uint32_t& h, uint32_t& l) {
    __nv_bfloat16 ha = __float2bfloat16(a), hb = __float2bfloat16(b);
    float ra = a - __bfloat162float(ha), rb = b - __bfloat162float(hb);
    h = pack_bf16(__bfloat162float(ha), __bfloat162float(hb));
    __nv_bfloat162 t = __halves2bfloat162(__float2bfloat16(ra), __float2bfloat16(rb));
    l = *(uint32_t*)&t;
}

#define MMA_BF16(d, a, b)                                                     \
    asm volatile(                                                             \
        "mma.sync.aligned.m16n8k16.row.col.f32.bf16.bf16.f32 "                \
        "{%0,%1,%2,%3}, {%4,%5,%6,%7}, {%8,%9}, {%0,%1,%2,%3};"               \
        : "+f"(d[0]), "+f"(d[1]), "+f"(d[2]), "+f"(d[3])                      \
        : "r"(a[0]), "r"(a[1]), "r"(a[2]), "r"(a[3]), "r"(b[0]), "r"(b[1]))

// ============================================================
// fp32 -> (bf16 hi, bf16 lo) split (standalone, for x and weights)
// ============================================================
__global__ void __launch_bounds__(256) split_kernel(
    const float* __restrict__ in,
    __nv_bfloat16* __restrict__ hi, __nv_bfloat16* __restrict__ lo, int n4)
{
    int i = blockIdx.x * blockDim.x + threadIdx.x;
    int stride = gridDim.x * blockDim.x;
    for (; i < n4; i += stride) {
        float4 v = ((const float4*)in)[i];
        uint32_t h0, l0, h1, l1;
        split_pack(v.x, v.y, h0, l0);
        split_pack(v.z, v.w, h1, l1);
        ((uint32_t*)hi)[2 * i + 0] = h0;
        ((uint32_t*)hi)[2 * i + 1] = h1;
        ((uint32_t*)lo)[2 * i + 0] = l0;
        ((uint32_t*)lo)[2 * i + 1] = l1;
    }
}

// ============================================================
// Warp-MMA bf16 GEMM. C = A*W^T + bias, written as bf16 hi/lo split.
// q columns (first 6 tiles of 18) pre-scaled by QSCALE (exact pow2).
// ============================================================
#define BK 32
#define ASTR 40
#define ROWB (ASTR * 2)
#define TILE_BYTES (128 * ROWB)
#define STAGE_BYTES (4 * TILE_BYTES)
#define GEMM_SMEM (2 * STAGE_BYTES)

__device__ __forceinline__ uint32_t smem_u32(const void* p) {
    uint32_t a;
    asm("{ .reg .u64 t; cvta.to.shared.u64 t, %1; cvt.u32.u64 %0, t; }"
        : "=r"(a) : "l"(p));
    return a;
}

__device__ __forceinline__ void load_stage_async(
    uint32_t sb, int stage,
    const __nv_bfloat16* __restrict__ Ahi, const __nv_bfloat16* __restrict__ Alo,
    const __nv_bfloat16* __restrict__ Whi, const __nv_bfloat16* __restrict__ Wlo,
    size_t m0, size_t n0, int k0, int tid)
{
#pragma unroll
    for (int i = 0; i < 8; i++) {
        const int arr = i >> 1;
        const int rem = (i & 1) * 256 + tid;
        const int row = rem >> 2;
        const int seg = rem & 3;
        const __nv_bfloat16* src;
        size_t r0;
        if      (arr == 0) { src = Ahi; r0 = m0; }
        else if (arr == 1) { src = Alo; r0 = m0; }
        else if (arr == 2) { src = Whi; r0 = n0; }
        else               { src = Wlo; r0 = n0; }
        const void* g = src + (r0 + row) * DD + k0 + seg * 8;
        uint32_t s = sb + stage * STAGE_BYTES + arr * TILE_BYTES
                   + row * ROWB + seg * 16;
        asm volatile("cp.async.cg.shared.global [%0], [%1], 16;"
                     :: "r"(s), "l"(g));
    }
}

__global__ void __launch_bounds__(256, 1) mma_gemm_kernel(
    const __nv_bfloat16* __restrict__ Ahi, const __nv_bfloat16* __restrict__ Alo,
    const __nv_bfloat16* __restrict__ Whi, const __nv_bfloat16* __restrict__ Wlo,
    const float* __restrict__ bias,
    __nv_bfloat16* __restrict__ Chi, __nv_bfloat16* __restrict__ Clo)
{
    extern __shared__ char sm[];
    const int tid  = threadIdx.x;
    const int wid  = tid >> 5;
    const int lane = tid & 31;
    const int wm   = wid >> 2;
    const int wn   = wid & 3;
    const int g    = lane >> 2;
    const int tig  = lane & 3;

    const size_t m0 = (size_t)blockIdx.y * 128;
    const size_t n0 = (size_t)blockIdx.x * 128;
    const uint32_t sb = smem_u32(sm);
    const float scale = (blockIdx.x < 6) ? QSCALE : 1.0f;

    float acc[4][4][4];
#pragma unroll
    for (int mt = 0; mt < 4; mt++)
#pragma unroll
        for (int nt = 0; nt < 4; nt++)
#pragma unroll
            for (int r = 0; r < 4; r++) acc[mt][nt][r] = 0.f;

    load_stage_async(sb, 0, Ahi, Alo, Whi, Wlo, m0, n0, 0, tid);
    asm volatile("cp.async.commit_group;" ::: "memory");

    const int NKT = DD / BK;
    for (int kt = 0; kt < NKT; kt++) {
        if (kt < NKT - 1) {
            load_stage_async(sb, (kt + 1) & 1, Ahi, Alo, Whi, Wlo,
                             m0, n0, (kt + 1) * BK, tid);
            asm volatile("cp.async.commit_group;" ::: "memory");
            asm volatile("cp.async.wait_group 1;" ::: "memory");
        } else {
            asm volatile("cp.async.wait_group 0;" ::: "memory");
        }
        __syncthreads();

        const char* sA_h = sm + (kt & 1) * STAGE_BYTES;
        const char* sA_l = sA_h + TILE_BYTES;
        const char* sB_h = sA_h + 2 * TILE_BYTES;
        const char* sB_l = sA_h + 3 * TILE_BYTES;

#pragma unroll
        for (int kk = 0; kk < 2; kk++) {
            const int kb = kk * 16;
            uint32_t ah[4][4], al[4][4];
#pragma unroll
            for (int mt = 0; mt < 4; mt++) {
                const int row = wm * 64 + mt * 16 + g;
                const char* ph = sA_h + row * ROWB + (kb + tig * 2) * 2;
                const char* pl = sA_l + row * ROWB + (kb + tig * 2) * 2;
                ah[mt][0] = *(const uint32_t*)(ph);
                ah[mt][1] = *(const uint32_t*)(ph + 8 * ROWB);
                ah[mt][2] = *(const uint32_t*)(ph + 16);
                ah[mt][3] = *(const uint32_t*)(ph + 8 * ROWB + 16);
                al[mt][0] = *(const uint32_t*)(pl);
                al[mt][1] = *(const uint32_t*)(pl + 8 * ROWB);
                al[mt][2] = *(const uint32_t*)(pl + 16);
                al[mt][3] = *(const uint32_t*)(pl + 8 * ROWB + 16);
            }
            uint32_t bh[4][2], bl[4][2];
#pragma unroll
            for (int nt = 0; nt < 4; nt++) {
                const int col = wn * 32 + nt * 8 + g;
                const char* ph = sB_h + col * ROWB + (kb + tig * 2) * 2;
                const char* pl = sB_l + col * ROWB + (kb + tig * 2) * 2;
                bh[nt][0] = *(const uint32_t*)(ph);
                bh[nt][1] = *(const uint32_t*)(ph + 16);
                bl[nt][0] = *(const uint32_t*)(pl);
                bl[nt][1] = *(const uint32_t*)(pl + 16);
            }
#pragma unroll
            for (int mt = 0; mt < 4; mt++)
#pragma unroll
                for (int nt = 0; nt < 4; nt++) {
                    MMA_BF16(acc[mt][nt], ah[mt], bh[nt]);
                    MMA_BF16(acc[mt][nt], ah[mt], bl[nt]);
                    MMA_BF16(acc[mt][nt], al[mt], bh[nt]);
                }
        }
        __syncthreads();
    }

    // Epilogue: bias, q-scale, bf16 hi/lo split write
#pragma unroll
    for (int mt = 0; mt < 4; mt++) {
        const size_t row = m0 + wm * 64 + mt * 16 + g;
#pragma unroll
        for (int nt = 0; nt < 4; nt++) {
            const size_t col = n0 + wn * 32 + nt * 8 + tig * 2;
            const float b0 = bias[col], b1 = bias[col + 1];
            float v0 = (acc[mt][nt][0] + b0) * scale;
            float v1 = (acc[mt][nt][1] + b1) * scale;
            float v2 = (acc[mt][nt][2] + b0) * scale;
            float v3 = (acc[mt][nt][3] + b1) * scale;
            uint32_t h, l;
            size_t idx = (row * N3 + col) >> 1;
            split_pack(v0, v1, h, l);
            ((uint32_t*)Chi)[idx] = h;
            ((uint32_t*)Clo)[idx] = l;
            split_pack(v2, v3, h, l);
            idx = ((row + 8) * N3 + col) >> 1;
            ((uint32_t*)Chi)[idx] = h;
            ((uint32_t*)Clo)[idx] = l;
        }
    }
}

// ============================================================
// MMA flash attention core (shared by row/col via parameters).
// Block: NW warps * 32 queries. Keys processed in 64-chunks.
// smem: Qh, Ql [NQ][72bf16]; Kh,Kl [64][72]; Vth,Vtl [64 dims][72toks]; nm[NQKEYS]
// Token index: tok(e_or_row) = row*TSTRIDE + TBASE (elements of qkv arrays)
// ============================================================
// Row:  NQ=256 NW=8 NKEY=256 token = e*L + i     (qstride=N3,    contiguous rows)
// Col:  NQ=128 NW=4 NKEY=128 token = i*L + l     (row stride L*N3)

template<int NQ, int NW, int NKEY>
__device__ __forceinline__ void attn_mma_core(
    const __nv_bfloat16* __restrict__ qh_g, const __nv_bfloat16* __restrict__ ql_g,
    const int* __restrict__ mask, float* __restrict__ out,
    size_t tok0, size_t tokstride,          // token = tok0 + row * tokstride
    int mask0, int maskstride,              // mask idx = mask0 + j * maskstride
    int h, char* sm)
{
    const int NT = NW * 32;
    const int tid = threadIdx.x, wid = tid >> 5, lane = tid & 31;
    const int g = lane >> 2, tig = lane & 3;

    uint32_t* Qh32 = (uint32_t*)(sm);
    uint32_t* Ql32 = (uint32_t*)(sm + NQ * 144);
    uint32_t* Kh32 = (uint32_t*)(sm + 2 * NQ * 144);
    uint32_t* Kl32 = (uint32_t*)(sm + 2 * NQ * 144 + 9216);
    uint32_t* Vh32 = (uint32_t*)(sm + 2 * NQ * 144 + 2 * 9216);
    uint32_t* Vl32 = (uint32_t*)(sm + 2 * NQ * 144 + 3 * 9216);
    float*    nm   = (float*)   (sm + 2 * NQ * 144 + 4 * 9216);

    const uint32_t* qhg32 = (const uint32_t*)qh_g;
    const uint32_t* qlg32 = (const uint32_t*)ql_g;

    // ---- load Q ----
    for (int it = 0; it < NQ * 32 / NT; it++) {
        int p = tid + it * NT;
        int row = p >> 5, w = p & 31;
        size_t gi = ((tok0 + (size_t)row * tokstride) * N3 + (size_t)h * DH) / 2 + w;
        Qh32[row * 36 + w] = qhg32[gi];
        Ql32[row * 36 + w] = qlg32[gi];
    }
    for (int j = tid; j < NKEY; j += NT)
        nm[j] = mask[mask0 + j * maskstride] ? NEGV : 0.f;

    float m_[2][2], l_[2][2], O[2][8][4];
#pragma unroll
    for (int a = 0; a < 2; a++)
#pragma unroll
        for (int b = 0; b < 2; b++) { m_[a][b] = -1e30f; l_[a][b] = 0.f; }
#pragma unroll
    for (int a = 0; a < 2; a++)
#pragma unroll
        for (int b = 0; b < 8; b++)
#pragma unroll
            for (int r = 0; r < 4; r++) O[a][b][r] = 0.f;

    for (int c = 0; c < NKEY / 64; c++) {
        __syncthreads();
        const int jb = c * 64;
        // K chunk (token-major)
        for (int it = 0; it < 64 * 32 / NT; it++) {
            int p = tid + it * NT;
            int row = p >> 5, w = p & 31;
            size_t gi = ((tok0 + (size_t)(jb + row) * tokstride) * N3 + DD + (size_t)h * DH) / 2 + w;
            Kh32[row * 36 + w] = qhg32[gi];
            Kl32[row * 36 + w] = qlg32[gi];
        }
        // V chunk, transposed to [dim][tok]
        {
            int tok = tid & 63;
            int ds  = tid >> 6;                  // NT/64 segments
            const int nseg = NT / 64;            // 4 (row) or 2 (col)
            const int uper = 32 / nseg;          // u32 per thread
            size_t vb = ((tok0 + (size_t)(jb + tok) * tokstride) * N3 + 2 * DD + (size_t)h * DH) / 2;
            for (int q = 0; q < uper; q++) {
                int w = ds * uper + q;
                uint32_t vh = qhg32[vb + w];
                uint32_t vl = qlg32[vb + w];
                __nv_bfloat162 ph = *(__nv_bfloat162*)&vh;
                __nv_bfloat162 pl = *(__nv_bfloat162*)&vl;
                int d0 = w * 2;
                ((__nv_bfloat16*)Vh32)[(d0    ) * 72 + tok] = ph.x;
                ((__nv_bfloat16*)Vh32)[(d0 + 1) * 72 + tok] = ph.y;
                ((__nv_bfloat16*)Vl32)[(d0    ) * 72 + tok] = pl.x;
                ((__nv_bfloat16*)Vl32)[(d0 + 1) * 72 + tok] = pl.y;
            }
        }
        __syncthreads();

        // ---- S = Q K^T (3-MMA split) ----
        float S[2][8][4];
#pragma unroll
        for (int a = 0; a < 2; a++)
#pragma unroll
            for (int b = 0; b < 8; b++)
#pragma unroll
                for (int r = 0; r < 4; r++) S[a][b][r] = 0.f;

        const int qr0 = wid * 32;
#pragma unroll
        for (int kt = 0; kt < 4; kt++) {
            uint32_t qh[2][4], ql[2][4];
#pragma unroll
            for (int mt = 0; mt < 2; mt++) {
                int r = qr0 + mt * 16 + g;
                qh[mt][0] = Qh32[r * 36 + kt * 8 + tig];
                qh[mt][1] = Qh32[(r + 8) * 36 + kt * 8 + tig];
                qh[mt][2] = Qh32[r * 36 + kt * 8 + tig + 4];
                qh[mt][3] = Qh32[(r + 8) * 36 + kt * 8 + tig + 4];
                ql[mt][0] = Ql32[r * 36 + kt * 8 + tig];
                ql[mt][1] = Ql32[(r + 8) * 36 + kt * 8 + tig];
                ql[mt][2] = Ql32[r * 36 + kt * 8 + tig + 4];
                ql[mt][3] = Ql32[(r + 8) * 36 + kt * 8 + tig + 4];
            }
#pragma unroll
            for (int nt = 0; nt < 8; nt++) {
                uint32_t bh[2], bl[2];
                int kr = nt * 8 + g;
                bh[0] = Kh32[kr * 36 + kt * 8 + tig];
                bh[1] = Kh32[kr * 36 + kt * 8 + tig + 4];
                bl[0] = Kl32[kr * 36 + kt * 8 + tig];
                bl[1] = Kl32[kr * 36 + kt * 8 + tig + 4];
#pragma unroll
                for (int mt = 0; mt < 2; mt++) {
                    MMA_BF16(S[mt][nt], qh[mt], bh);
                    MMA_BF16(S[mt][nt], qh[mt], bl);
                    MMA_BF16(S[mt][nt], ql[mt], bh);
                }
            }
        }

        // ---- mask + online softmax ----
#pragma unroll
        for (int mt = 0; mt < 2; mt++)
#pragma unroll
            for (int rh = 0; rh < 2; rh++) {
                float mx = -1e30f;
#pragma unroll
                for (int nt = 0; nt < 8; nt++) {
                    float v0 = S[mt][nt][rh * 2 + 0] + nm[jb + nt * 8 + 2 * tig];
                    float v1 = S[mt][nt][rh * 2 + 1] + nm[jb + nt * 8 + 2 * tig + 1];
                    S[mt][nt][rh * 2 + 0] = v0;
                    S[mt][nt][rh * 2 + 1] = v1;
                    mx = fmaxf(mx, fmaxf(v0, v1));
                }
                mx = fmaxf(mx, __shfl_xor_sync(0xffffffffu, mx, 1));
                mx = fmaxf(mx, __shfl_xor_sync(0xffffffffu, mx, 2));
                float mnew = fmaxf(m_[mt][rh], mx);
                float corr = __expf(m_[mt][rh] - mnew);
                m_[mt][rh] = mnew;
                float ps = 0.f;
#pragma unroll
                for (int nt = 0; nt < 8; nt++) {
                    float p0 = __expf(S[mt][nt][rh * 2 + 0] - mnew);
                    float p1 = __expf(S[mt][nt][rh * 2 + 1] - mnew);
                    S[mt][nt][rh * 2 + 0] = p0;
                    S[mt][nt][rh * 2 + 1] = p1;
                    ps += p0 + p1;
                }
                ps += __shfl_xor_sync(0xffffffffu, ps, 1);
                ps += __shfl_xor_sync(0xffffffffu, ps, 2);
                l_[mt][rh] = l_[mt][rh] * corr + ps;
#pragma unroll
                for (int nt = 0; nt < 8; nt++) {
                    O[mt][nt][rh * 2 + 0] *= corr;
                    O[mt][nt][rh * 2 + 1] *= corr;
                }
            }

        // ---- O += P V (3-MMA split), P repacked from S frags ----
#pragma unroll
        for (int kt = 0; kt < 4; kt++) {
            uint32_t ph[2][4], pl[2][4];
#pragma unroll
            for (int mt = 0; mt < 2; mt++) {
                split_pack(S[mt][2 * kt][0],     S[mt][2 * kt][1],     ph[mt][0], pl[mt][0]);
                split_pack(S[mt][2 * kt][2],     S[mt][2 * kt][3],     ph[mt][1], pl[mt][1]);
                split_pack(S[mt][2 * kt + 1][0], S[mt][2 * kt + 1][1], ph[mt][2], pl[mt][2]);
                split_pack(S[mt][2 * kt + 1][2], S[mt][2 * kt + 1][3], ph[mt][3], pl[mt][3]);
            }
#pragma unroll
            for (int nt = 0; nt < 8; nt++) {
                uint32_t bh[2], bl[2];
                int dr = nt * 8 + g;
                bh[0] = Vh32[dr * 36 + kt * 8 + tig];
                bh[1] = Vh32[dr * 36 + kt * 8 + tig + 4];
                bl[0] = Vl32[dr * 36 + kt * 8 + tig];
                bl[1] = Vl32[dr * 36 + kt * 8 + tig + 4];
#pragma unroll
                for (int mt = 0; mt < 2; mt++) {
                    MMA_BF16(O[mt][nt], ph[mt], bh);
                    MMA_BF16(O[mt][nt], ph[mt], bl);
                    MMA_BF16(O[mt][nt], pl[mt], bh);
                }
            }
        }
    }

    // ---- finalize + write ----
#pragma unroll
    for (int mt = 0; mt < 2; mt++)
#pragma unroll
        for (int rh = 0; rh < 2; rh++) {
            float inv = 1.f / l_[mt][rh];
            int qr = wid * 32 + mt * 16 + g + rh * 8;
            size_t tok = tok0 + (size_t)qr * tokstride;
            float* op = out + tok * DD + h * DH;
#pragma unroll
            for (int nt = 0; nt < 8; nt++) {
                float2 o;
                o.x = O[mt][nt][rh * 2 + 0] * inv;
                o.y = O[mt][nt][rh * 2 + 1] * inv;
                *(float2*)(op + nt * 8 + 2 * tig) = o;
            }
        }
}

#define ROW_ATTN_SMEM (2 * 256 * 144 + 4 * 9216 + 256 * 4)   // 111616
#define COL_ATTN_SMEM (2 * 128 * 144 + 4 * 9216 + 128 * 4)   //  74240

__global__ void __launch_bounds__(256, 1) row_attn_mma_kernel(
    const __nv_bfloat16* __restrict__ qh_g, const __nv_bfloat16* __restrict__ ql_g,
    const int* __restrict__ mask, float* __restrict__ out)
{
    extern __shared__ char sm[];
    const int e = blockIdx.x, h = blockIdx.y;
    attn_mma_core<256, 8, 256>(qh_g, ql_g, mask, out,
                               (size_t)e * L_L, 1,    // token = e*L + i
                               e * L_L, 1,            // mask = [e*L + j]
                               h, sm);
}

__global__ void __launch_bounds__(128, 1) col_attn_mma_kernel(
    const __nv_bfloat16* __restrict__ qh_g, const __nv_bfloat16* __restrict__ ql_g,
    const int* __restrict__ mask, float* __restrict__ out)
{
    extern __shared__ char sm[];
    const int l = blockIdx.x, h = blockIdx.y;
    attn_mma_core<128, 4, 128>(qh_g, ql_g, mask, out,
                               (size_t)l, L_L,        // token = i*L + l
                               l, L_L,                // mask = [j*L + l]
                               h, sm);
}

// ============================================================
// Fused residual-add + LayerNorm (+ optional bf16 hi/lo split out)
// ============================================================
__global__ void __launch_bounds__(256) add_ln_kernel(
    const float* __restrict__ a, const float* __restrict__ b,
    const float* __restrict__ g, const float* __restrict__ beta,
    float* __restrict__ dst,
    __nv_bfloat16* __restrict__ hi, __nv_bfloat16* __restrict__ lo)
{
    const int m = blockIdx.x;
    const int t = threadIdx.x;
    __shared__ float red[256];

    float v[3];
    float s = 0.f;
#pragma unroll
    for (int r = 0; r < 3; r++) {
        int idx = t + r * 256;
        v[r] = a[(size_t)m * DD + idx] + b[(size_t)m * DD + idx];
        s += v[r];
    }
    red[t] = s;
    __syncthreads();
    for (int o = 128; o > 0; o >>= 1) {
        if (t < o) red[t] += red[t + o];
        __syncthreads();
    }
    const float mu = red[0] * (1.f / DD);
    __syncthreads();

    float sq = 0.f;
#pragma unroll
    for (int r = 0; r < 3; r++) {
        float d = v[r] - mu;
        sq += d * d;
    }
    red[t] = sq;
    __syncthreads();
    for (int o = 128; o > 0; o >>= 1) {
        if (t < o) red[t] += red[t + o];
        __syncthreads();
    }
    const float rstd = rsqrtf(red[0] * (1.f / DD) + EPS);

#pragma unroll
    for (int r = 0; r < 3; r++) {
        int idx = t + r * 256;
        float y = (v[r] - mu) * rstd * g[idx] + beta[idx];
        dst[(size_t)m * DD + idx] = y;
        if (hi) {
            __nv_bfloat16 hbf = __float2bfloat16(y);
            hi[(size_t)m * DD + idx] = hbf;
            lo[(size_t)m * DD + idx] = __float2bfloat16(y - __bfloat162float(hbf));
        }
    }
}

// ============================================================
// Launch
// ============================================================
extern "C" void kernel_launch(void* const* d_in, const int* in_sizes, int n_in,
                              void* d_out, int out_size)
{
    const float* x     = (const float*)d_in[0];
    const float* w_row = (const float*)d_in[1];
    const float* b_row = (const float*)d_in[2];
    const float* w_col = (const float*)d_in[3];
    const float* b_col = (const float*)d_in[4];
    const float* g1    = (const float*)d_in[5];
    const float* beta1 = (const float*)d_in[6];
    const float* g2    = (const float*)d_in[7];
    const float* beta2 = (const float*)d_in[8];
    const int*   mask  = (const int*)d_in[9];
    float* out = (float*)d_out;

    float *qkvf, *att, *out1;
    __nv_bfloat16 *ahi, *alo, *whi, *wlo;
    cudaGetSymbolAddress((void**)&qkvf, g_qkv);
    cudaGetSymbolAddress((void**)&att,  g_att);
    cudaGetSymbolAddress((void**)&out1, g_out1);
    cudaGetSymbolAddress((void**)&ahi,  g_ahi);
    cudaGetSymbolAddress((void**)&alo,  g_alo);
    cudaGetSymbolAddress((void**)&whi,  g_whi);
    cudaGetSymbolAddress((void**)&wlo,  g_wlo);
    __nv_bfloat16* qh = (__nv_bfloat16*)qkvf;
    __nv_bfloat16* ql = qh + (size_t)MROWS * N3;

    cudaFuncSetAttribute(mma_gemm_kernel,
                         cudaFuncAttributeMaxDynamicSharedMemorySize, GEMM_SMEM);
    cudaFuncSetAttribute(row_attn_mma_kernel,
                         cudaFuncAttributeMaxDynamicSharedMemorySize, ROW_ATTN_SMEM);
    cudaFuncSetAttribute(col_attn_mma_kernel,
                         cudaFuncAttributeMaxDynamicSharedMemorySize, COL_ATTN_SMEM);

    const int nA4 = MROWS * DD / 4;
    const int nW4 = N3 * DD / 4;
    dim3 tcg(N3 / 128, MROWS / 128);   // (18, 256)

    // ---- stage 1: row attention ----
    split_kernel<<<4096, 256>>>(x, ahi, alo, nA4);
    split_kernel<<<1024, 256>>>(w_row, whi, wlo, nW4);
    mma_gemm_kernel<<<tcg, 256, GEMM_SMEM>>>(ahi, alo, whi, wlo, b_row, qh, ql);
    row_attn_mma_kernel<<<dim3(B_E, HH), 256, ROW_ATTN_SMEM>>>(qh, ql, mask, att);
    add_ln_kernel<<<MROWS, 256>>>(x, att, g1, beta1, out1, ahi, alo);

    // ---- stage 2: column attention ----
    split_kernel<<<1024, 256>>>(w_col, whi, wlo, nW4);
    mma_gemm_kernel<<<tcg, 256, GEMM_SMEM>>>(ahi, alo, whi, wlo, b_col, qh, ql);
    col_attn_mma_kernel<<<dim3(L_L, HH), 128, COL_ATTN_SMEM>>>(qh, ql, mask, att);
    add_ln_kernel<<<MROWS, 256>>>(out1, att, g2, beta2, out, (__nv_bfloat16*)nullptr,
                                  (__nv_bfloat16*)nullptr);
}

// round 8
// speedup vs baseline: 4.9357x; 1.1439x over previous
#include <cuda_runtime.h>
#include <cuda_bf16.h>
#include <math.h>
#include <cstdint>

// Problem constants
#define B_E 128
#define L_L 256
#define HH  12
#define DH  64
#define DD  768           // H*DH
#define N3  2304          // 3*D
#define MROWS (B_E * L_L) // 32768
#define EPS 1e-5f
#define NEGV -10000.0f
#define QSCALE 0.125f     // DH^-0.5

// -------- scratch (allocation-free: __device__ globals) --------
__device__ float g_qkv[(size_t)MROWS * N3];   // carved into qkv_hi | qkv_lo bf16
__device__ float g_att[(size_t)MROWS * DD];
__device__ float g_out1[(size_t)MROWS * DD];
__device__ __nv_bfloat16 g_ahi[(size_t)MROWS * DD];
__device__ __nv_bfloat16 g_alo[(size_t)MROWS * DD];
__device__ __nv_bfloat16 g_whi[(size_t)N3 * DD];
__device__ __nv_bfloat16 g_wlo[(size_t)N3 * DD];

// ============================================================
// helpers
// ============================================================
__device__ __forceinline__ uint32_t pack_bf16(float a, float b) {
    __nv_bfloat162 t = __halves2bfloat162(__float2bfloat16(a), __float2bfloat16(b));
    return *(uint32_t*)&t;
}
__device__ __forceinline__ void split_pack(float a, float b,
                                           uint32_t& h, uint32_t& l) {
    __nv_bfloat16 ha = __float2bfloat16(a), hb = __float2bfloat16(b);
    float ra = a - __bfloat162float(ha), rb = b - __bfloat162float(hb);
    h = pack_bf16(__bfloat162float(ha), __bfloat162float(hb));
    __nv_bfloat162 t = __halves2bfloat162(__float2bfloat16(ra), __float2bfloat16(rb));
    l = *(uint32_t*)&t;
}
__device__ __forceinline__ uint32_t smem_u32(const void* p) {
    uint32_t a;
    asm("{ .reg .u64 t; cvta.to.shared.u64 t, %1; cvt.u32.u64 %0, t; }"
        : "=r"(a) : "l"(p));
    return a;
}

#define MMA_BF16(d, a, b)                                                     \
    asm volatile(                                                             \
        "mma.sync.aligned.m16n8k16.row.col.f32.bf16.bf16.f32 "                \
        "{%0,%1,%2,%3}, {%4,%5,%6,%7}, {%8,%9}, {%0,%1,%2,%3};"               \
        : "+f"(d[0]), "+f"(d[1]), "+f"(d[2]), "+f"(d[3])                      \
        : "r"(a[0]), "r"(a[1]), "r"(a[2]), "r"(a[3]), "r"(b[0]), "r"(b[1]))

#define LDSM_X4(r0, r1, r2, r3, addr)                                         \
    asm volatile("ldmatrix.sync.aligned.m8n8.x4.shared.b16 {%0,%1,%2,%3}, [%4];" \
        : "=r"(r0), "=r"(r1), "=r"(r2), "=r"(r3) : "r"(addr))
#define LDSM_X4_T(r0, r1, r2, r3, addr)                                       \
    asm volatile("ldmatrix.sync.aligned.m8n8.x4.trans.shared.b16 {%0,%1,%2,%3}, [%4];" \
        : "=r"(r0), "=r"(r1), "=r"(r2), "=r"(r3) : "r"(addr))
#define CP_ASYNC16(s, g)                                                      \
    asm volatile("cp.async.cg.shared.global [%0], [%1], 16;" :: "r"(s), "l"(g))
#define CP_COMMIT  asm volatile("cp.async.commit_group;" ::: "memory")
#define CP_WAIT0   asm volatile("cp.async.wait_group 0;" ::: "memory")
#define CP_WAIT1   asm volatile("cp.async.wait_group 1;" ::: "memory")

// ============================================================
// fp32 -> (bf16 hi, bf16 lo) split
// ============================================================
__global__ void __launch_bounds__(256) split_kernel(
    const float* __restrict__ in,
    __nv_bfloat16* __restrict__ hi, __nv_bfloat16* __restrict__ lo, int n4)
{
    int i = blockIdx.x * blockDim.x + threadIdx.x;
    int stride = gridDim.x * blockDim.x;
    for (; i < n4; i += stride) {
        float4 v = ((const float4*)in)[i];
        uint32_t h0, l0, h1, l1;
        split_pack(v.x, v.y, h0, l0);
        split_pack(v.z, v.w, h1, l1);
        ((uint32_t*)hi)[2 * i + 0] = h0;
        ((uint32_t*)hi)[2 * i + 1] = h1;
        ((uint32_t*)lo)[2 * i + 0] = l0;
        ((uint32_t*)lo)[2 * i + 1] = l1;
    }
}

// ============================================================
// Warp-MMA bf16 GEMM with ldmatrix fragment loads.
// C = A*W^T + bias -> bf16 hi/lo split out (q pre-scaled).
// ============================================================
#define BK 32
#define ASTR 40
#define ROWB (ASTR * 2)               // 80 B
#define TILE_BYTES (128 * ROWB)
#define STAGE_BYTES (4 * TILE_BYTES)
#define GEMM_SMEM (2 * STAGE_BYTES)

__device__ __forceinline__ void load_stage_async(
    uint32_t sb, int stage,
    const __nv_bfloat16* __restrict__ Ahi, const __nv_bfloat16* __restrict__ Alo,
    const __nv_bfloat16* __restrict__ Whi, const __nv_bfloat16* __restrict__ Wlo,
    size_t m0, size_t n0, int k0, int tid)
{
#pragma unroll
    for (int i = 0; i < 8; i++) {
        const int arr = i >> 1;
        const int rem = (i & 1) * 256 + tid;
        const int row = rem >> 2;
        const int seg = rem & 3;
        const __nv_bfloat16* src;
        size_t r0;
        if      (arr == 0) { src = Ahi; r0 = m0; }
        else if (arr == 1) { src = Alo; r0 = m0; }
        else if (arr == 2) { src = Whi; r0 = n0; }
        else               { src = Wlo; r0 = n0; }
        const void* g = src + (r0 + row) * DD + k0 + seg * 8;
        uint32_t s = sb + stage * STAGE_BYTES + arr * TILE_BYTES
                   + row * ROWB + seg * 16;
        CP_ASYNC16(s, g);
    }
}

__global__ void __launch_bounds__(256, 1) mma_gemm_kernel(
    const __nv_bfloat16* __restrict__ Ahi, const __nv_bfloat16* __restrict__ Alo,
    const __nv_bfloat16* __restrict__ Whi, const __nv_bfloat16* __restrict__ Wlo,
    const float* __restrict__ bias,
    __nv_bfloat16* __restrict__ Chi, __nv_bfloat16* __restrict__ Clo)
{
    extern __shared__ char sm[];
    const int tid  = threadIdx.x;
    const int wid  = tid >> 5;
    const int lane = tid & 31;
    const int wm   = wid >> 2;
    const int wn   = wid & 3;
    const int g    = lane >> 2;
    const int tig  = lane & 3;
    const int grp  = lane >> 3;

    const size_t m0 = (size_t)blockIdx.y * 128;
    const size_t n0 = (size_t)blockIdx.x * 128;
    const uint32_t sb = smem_u32(sm);
    const float scale = (blockIdx.x < 6) ? QSCALE : 1.0f;

    // ldmatrix lane-address offsets (16B aligned: ROWB=80=5*16)
    const uint32_t aoff = (uint32_t)((wm * 64 + (grp & 1) * 8 + (lane & 7)) * ROWB
                                     + ((grp >> 1) * 8) * 2);
    const uint32_t boff = (uint32_t)((wn * 32 + (grp >> 1) * 8 + (lane & 7)) * ROWB
                                     + ((grp & 1) * 8) * 2);

    float acc[4][4][4];
#pragma unroll
    for (int mt = 0; mt < 4; mt++)
#pragma unroll
        for (int nt = 0; nt < 4; nt++)
#pragma unroll
            for (int r = 0; r < 4; r++) acc[mt][nt][r] = 0.f;

    load_stage_async(sb, 0, Ahi, Alo, Whi, Wlo, m0, n0, 0, tid);
    CP_COMMIT;

    const int NKT = DD / BK;
    for (int kt = 0; kt < NKT; kt++) {
        if (kt < NKT - 1) {
            load_stage_async(sb, (kt + 1) & 1, Ahi, Alo, Whi, Wlo,
                             m0, n0, (kt + 1) * BK, tid);
            CP_COMMIT;
            CP_WAIT1;
        } else {
            CP_WAIT0;
        }
        __syncthreads();

        const uint32_t sA_h = sb + (kt & 1) * STAGE_BYTES;
        const uint32_t sA_l = sA_h + TILE_BYTES;
        const uint32_t sB_h = sA_h + 2 * TILE_BYTES;
        const uint32_t sB_l = sA_h + 3 * TILE_BYTES;

#pragma unroll
        for (int kk = 0; kk < 2; kk++) {
            const int kb = kk * 32;   // bytes
            uint32_t ah[4][4], al[4][4];
#pragma unroll
            for (int mt = 0; mt < 4; mt++) {
                LDSM_X4(ah[mt][0], ah[mt][1], ah[mt][2], ah[mt][3],
                        sA_h + aoff + mt * 16 * ROWB + kb);
                LDSM_X4(al[mt][0], al[mt][1], al[mt][2], al[mt][3],
                        sA_l + aoff + mt * 16 * ROWB + kb);
            }
            uint32_t bh[2][4], bl[2][4];
#pragma unroll
            for (int ntp = 0; ntp < 2; ntp++) {
                LDSM_X4(bh[ntp][0], bh[ntp][1], bh[ntp][2], bh[ntp][3],
                        sB_h + boff + ntp * 16 * ROWB + kb);
                LDSM_X4(bl[ntp][0], bl[ntp][1], bl[ntp][2], bl[ntp][3],
                        sB_l + boff + ntp * 16 * ROWB + kb);
            }
#pragma unroll
            for (int mt = 0; mt < 4; mt++)
#pragma unroll
                for (int ntp = 0; ntp < 2; ntp++) {
                    MMA_BF16(acc[mt][2 * ntp],     ah[mt], (&bh[ntp][0]));
                    MMA_BF16(acc[mt][2 * ntp],     ah[mt], (&bl[ntp][0]));
                    MMA_BF16(acc[mt][2 * ntp],     al[mt], (&bh[ntp][0]));
                    MMA_BF16(acc[mt][2 * ntp + 1], ah[mt], (&bh[ntp][2]));
                    MMA_BF16(acc[mt][2 * ntp + 1], ah[mt], (&bl[ntp][2]));
                    MMA_BF16(acc[mt][2 * ntp + 1], al[mt], (&bh[ntp][2]));
                }
        }
        __syncthreads();
    }

    // Epilogue
#pragma unroll
    for (int mt = 0; mt < 4; mt++) {
        const size_t row = m0 + wm * 64 + mt * 16 + g;
#pragma unroll
        for (int nt = 0; nt < 4; nt++) {
            const size_t col = n0 + wn * 32 + nt * 8 + tig * 2;
            const float b0 = bias[col], b1 = bias[col + 1];
            float v0 = (acc[mt][nt][0] + b0) * scale;
            float v1 = (acc[mt][nt][1] + b1) * scale;
            float v2 = (acc[mt][nt][2] + b0) * scale;
            float v3 = (acc[mt][nt][3] + b1) * scale;
            uint32_t h, l;
            size_t idx = (row * N3 + col) >> 1;
            split_pack(v0, v1, h, l);
            ((uint32_t*)Chi)[idx] = h;
            ((uint32_t*)Clo)[idx] = l;
            split_pack(v2, v3, h, l);
            idx = ((row + 8) * N3 + col) >> 1;
            ((uint32_t*)Chi)[idx] = h;
            ((uint32_t*)Clo)[idx] = l;
        }
    }
}

// ============================================================
// Flash MMA attention, 128 queries/block, 4 warps, 2 CTAs/SM.
// K/V double-buffered via cp.async; V via ldmatrix.trans.
// smem: Qh,Ql [128][72]; 2 stages x (Kh,Kl,Vh,Vl)[64][72]; nm[256]
// ============================================================
#define QROWB 144                       // 72 halves * 2B
#define ATT_SMEM (2 * 18432 + 2 * 36864 + 1024)   // 111616

template<int NKEY>
__device__ __forceinline__ void attn_core(
    const __nv_bfloat16* __restrict__ qh_g, const __nv_bfloat16* __restrict__ ql_g,
    const int* __restrict__ mask, float* __restrict__ out,
    size_t qtok0, size_t ktok0, size_t ts,
    int mask0, int mstride, int h, char* sm)
{
    const int tid = threadIdx.x, wid = tid >> 5, lane = tid & 31;
    const int g = lane >> 2, tig = lane & 3, grp = lane >> 3;
    const uint32_t sb = smem_u32(sm);
    const uint32_t sQh = sb, sQl = sb + 18432;
    float* nm = (float*)(sm + 110592);

    // ---- prologue: Q + chunk0 via cp.async (one group) ----
#pragma unroll
    for (int arr = 0; arr < 2; arr++) {
        const __nv_bfloat16* src = arr ? ql_g : qh_g;
        uint32_t sq = arr ? sQl : sQh;
#pragma unroll
        for (int it = 0; it < 8; it++) {
            int p = it * 128 + tid;
            int row = p >> 3, seg = p & 7;
            const __nv_bfloat16* gp = src + (qtok0 + (size_t)row * ts) * N3
                                    + (size_t)h * DH + seg * 8;
            CP_ASYNC16(sq + row * QROWB + seg * 16, gp);
        }
    }
    // chunk loader (stage = c&1)
    auto load_chunk = [&](int c) {
        const uint32_t sbase = sb + 36864 + (uint32_t)(c & 1) * 36864;
        const int jb = c * 64;
#pragma unroll
        for (int arr = 0; arr < 2; arr++) {
            const __nv_bfloat16* src = arr ? ql_g : qh_g;
#pragma unroll
            for (int it = 0; it < 4; it++) {
                int p = it * 128 + tid;
                int tok = p >> 3, seg = p & 7;
                const __nv_bfloat16* base = src
                    + (ktok0 + (size_t)(jb + tok) * ts) * N3 + (size_t)h * DH;
                CP_ASYNC16(sbase + arr * 9216 + tok * QROWB + seg * 16,
                           base + DD + seg * 8);                       // K
                CP_ASYNC16(sbase + 18432 + arr * 9216 + tok * QROWB + seg * 16,
                           base + 2 * DD + seg * 8);                   // V
            }
        }
    };
    load_chunk(0);
    CP_COMMIT;

    for (int j = tid; j < NKEY; j += 128)
        nm[j] = mask[mask0 + j * mstride] ? NEGV : 0.f;

    // ldmatrix lane-address offsets
    const uint32_t qA_off = (uint32_t)((wid * 32 + (grp & 1) * 8 + (lane & 7)) * QROWB
                                       + ((grp >> 1) * 8) * 2);
    const uint32_t kB_off = (uint32_t)(((grp >> 1) * 8 + (lane & 7)) * QROWB
                                       + ((grp & 1) * 8) * 2);
    const uint32_t vB_off = (uint32_t)(((grp & 1) * 8 + (lane & 7)) * QROWB
                                       + ((grp >> 1) * 8) * 2);

    float m_[2][2], l_[2][2], O[2][8][4];
#pragma unroll
    for (int a = 0; a < 2; a++)
#pragma unroll
        for (int b = 0; b < 2; b++) { m_[a][b] = -1e30f; l_[a][b] = 0.f; }
#pragma unroll
    for (int a = 0; a < 2; a++)
#pragma unroll
        for (int b = 0; b < 8; b++)
#pragma unroll
            for (int r = 0; r < 4; r++) O[a][b][r] = 0.f;

    const int NC = NKEY / 64;
    for (int c = 0; c < NC; c++) {
        CP_WAIT0;
        __syncthreads();
        if (c + 1 < NC) { load_chunk(c + 1); CP_COMMIT; }

        const uint32_t sK = sb + 36864 + (uint32_t)(c & 1) * 36864;
        const uint32_t sV = sK + 18432;
        const int jb = c * 64;

        // ---- S = Q K^T ----
        float S[2][8][4];
#pragma unroll
        for (int a = 0; a < 2; a++)
#pragma unroll
            for (int b = 0; b < 8; b++)
#pragma unroll
                for (int r = 0; r < 4; r++) S[a][b][r] = 0.f;

#pragma unroll
        for (int kt = 0; kt < 4; kt++) {
            uint32_t aqh[2][4], aql[2][4];
#pragma unroll
            for (int mt = 0; mt < 2; mt++) {
                LDSM_X4(aqh[mt][0], aqh[mt][1], aqh[mt][2], aqh[mt][3],
                        sQh + qA_off + mt * 16 * QROWB + kt * 32);
                LDSM_X4(aql[mt][0], aql[mt][1], aql[mt][2], aql[mt][3],
                        sQl + qA_off + mt * 16 * QROWB + kt * 32);
            }
#pragma unroll
            for (int ntp = 0; ntp < 4; ntp++) {
                uint32_t kh[4], kl[4];
                LDSM_X4(kh[0], kh[1], kh[2], kh[3],
                        sK + kB_off + ntp * 16 * QROWB + kt * 32);
                LDSM_X4(kl[0], kl[1], kl[2], kl[3],
                        sK + 9216 + kB_off + ntp * 16 * QROWB + kt * 32);
#pragma unroll
                for (int mt = 0; mt < 2; mt++) {
                    MMA_BF16(S[mt][2 * ntp],     aqh[mt], (&kh[0]));
                    MMA_BF16(S[mt][2 * ntp],     aqh[mt], (&kl[0]));
                    MMA_BF16(S[mt][2 * ntp],     aql[mt], (&kh[0]));
                    MMA_BF16(S[mt][2 * ntp + 1], aqh[mt], (&kh[2]));
                    MMA_BF16(S[mt][2 * ntp + 1], aqh[mt], (&kl[2]));
                    MMA_BF16(S[mt][2 * ntp + 1], aql[mt], (&kh[2]));
                }
            }
        }

        // ---- mask + online softmax ----
#pragma unroll
        for (int mt = 0; mt < 2; mt++)
#pragma unroll
            for (int rh = 0; rh < 2; rh++) {
                float mx = -1e30f;
#pragma unroll
                for (int nt = 0; nt < 8; nt++) {
                    float v0 = S[mt][nt][rh * 2 + 0] + nm[jb + nt * 8 + 2 * tig];
                    float v1 = S[mt][nt][rh * 2 + 1] + nm[jb + nt * 8 + 2 * tig + 1];
                    S[mt][nt][rh * 2 + 0] = v0;
                    S[mt][nt][rh * 2 + 1] = v1;
                    mx = fmaxf(mx, fmaxf(v0, v1));
                }
                mx = fmaxf(mx, __shfl_xor_sync(0xffffffffu, mx, 1));
                mx = fmaxf(mx, __shfl_xor_sync(0xffffffffu, mx, 2));
                float mnew = fmaxf(m_[mt][rh], mx);
                float corr = __expf(m_[mt][rh] - mnew);
                m_[mt][rh] = mnew;
                float ps = 0.f;
#pragma unroll
                for (int nt = 0; nt < 8; nt++) {
                    float p0 = __expf(S[mt][nt][rh * 2 + 0] - mnew);
                    float p1 = __expf(S[mt][nt][rh * 2 + 1] - mnew);
                    S[mt][nt][rh * 2 + 0] = p0;
                    S[mt][nt][rh * 2 + 1] = p1;
                    ps += p0 + p1;
                }
                ps += __shfl_xor_sync(0xffffffffu, ps, 1);
                ps += __shfl_xor_sync(0xffffffffu, ps, 2);
                l_[mt][rh] = l_[mt][rh] * corr + ps;
#pragma unroll
                for (int nt = 0; nt < 8; nt++) {
                    O[mt][nt][rh * 2 + 0] *= corr;
                    O[mt][nt][rh * 2 + 1] *= corr;
                }
            }

        // ---- O += P V ----
#pragma unroll
        for (int kt = 0; kt < 4; kt++) {
            uint32_t ph[2][4], pl[2][4];
#pragma unroll
            for (int mt = 0; mt < 2; mt++) {
                split_pack(S[mt][2 * kt][0],     S[mt][2 * kt][1],     ph[mt][0], pl[mt][0]);
                split_pack(S[mt][2 * kt][2],     S[mt][2 * kt][3],     ph[mt][1], pl[mt][1]);
                split_pack(S[mt][2 * kt + 1][0], S[mt][2 * kt + 1][1], ph[mt][2], pl[mt][2]);
                split_pack(S[mt][2 * kt + 1][2], S[mt][2 * kt + 1][3], ph[mt][3], pl[mt][3]);
            }
#pragma unroll
            for (int ntp = 0; ntp < 4; ntp++) {
                uint32_t vh[4], vl[4];
                LDSM_X4_T(vh[0], vh[1], vh[2], vh[3],
                          sV + vB_off + kt * 16 * QROWB + ntp * 32);
                LDSM_X4_T(vl[0], vl[1], vl[2], vl[3],
                          sV + 9216 + vB_off + kt * 16 * QROWB + ntp * 32);
#pragma unroll
                for (int mt = 0; mt < 2; mt++) {
                    MMA_BF16(O[mt][2 * ntp],     ph[mt], (&vh[0]));
                    MMA_BF16(O[mt][2 * ntp],     ph[mt], (&vl[0]));
                    MMA_BF16(O[mt][2 * ntp],     pl[mt], (&vh[0]));
                    MMA_BF16(O[mt][2 * ntp + 1], ph[mt], (&vh[2]));
                    MMA_BF16(O[mt][2 * ntp + 1], ph[mt], (&vl[2]));
                    MMA_BF16(O[mt][2 * ntp + 1], pl[mt], (&vh[2]));
                }
            }
        }
    }

    // ---- finalize + write ----
#pragma unroll
    for (int mt = 0; mt < 2; mt++)
#pragma unroll
        for (int rh = 0; rh < 2; rh++) {
            float inv = 1.f / l_[mt][rh];
            int qr = wid * 32 + mt * 16 + g + rh * 8;
            size_t tok = qtok0 + (size_t)qr * ts;
            float* op = out + tok * DD + h * DH;
#pragma unroll
            for (int nt = 0; nt < 8; nt++) {
                float2 o;
                o.x = O[mt][nt][rh * 2 + 0] * inv;
                o.y = O[mt][nt][rh * 2 + 1] * inv;
                *(float2*)(op + nt * 8 + 2 * tig) = o;
            }
        }
}

__global__ void __launch_bounds__(128, 2) row_attn_mma_kernel(
    const __nv_bfloat16* __restrict__ qh_g, const __nv_bfloat16* __restrict__ ql_g,
    const int* __restrict__ mask, float* __restrict__ out)
{
    extern __shared__ char sm[];
    const int e = blockIdx.x >> 1, qt = blockIdx.x & 1, h = blockIdx.y;
    attn_core<256>(qh_g, ql_g, mask, out,
                   (size_t)e * L_L + qt * 128, (size_t)e * L_L, 1,
                   e * L_L, 1, h, sm);
}

__global__ void __launch_bounds__(128, 2) col_attn_mma_kernel(
    const __nv_bfloat16* __restrict__ qh_g, const __nv_bfloat16* __restrict__ ql_g,
    const int* __restrict__ mask, float* __restrict__ out)
{
    extern __shared__ char sm[];
    const int l = blockIdx.x, h = blockIdx.y;
    attn_core<128>(qh_g, ql_g, mask, out,
                   (size_t)l, (size_t)l, L_L,
                   l, L_L, h, sm);
}

// ============================================================
// Fused residual-add + LayerNorm (+ optional bf16 hi/lo split out)
// ============================================================
__global__ void __launch_bounds__(256) add_ln_kernel(
    const float* __restrict__ a, const float* __restrict__ b,
    const float* __restrict__ g, const float* __restrict__ beta,
    float* __restrict__ dst,
    __nv_bfloat16* __restrict__ hi, __nv_bfloat16* __restrict__ lo)
{
    const int m = blockIdx.x;
    const int t = threadIdx.x;
    __shared__ float red[256];

    float v[3];
    float s = 0.f;
#pragma unroll
    for (int r = 0; r < 3; r++) {
        int idx = t + r * 256;
        v[r] = a[(size_t)m * DD + idx] + b[(size_t)m * DD + idx];
        s += v[r];
    }
    red[t] = s;
    __syncthreads();
    for (int o = 128; o > 0; o >>= 1) {
        if (t < o) red[t] += red[t + o];
        __syncthreads();
    }
    const float mu = red[0] * (1.f / DD);
    __syncthreads();

    float sq = 0.f;
#pragma unroll
    for (int r = 0; r < 3; r++) {
        float d = v[r] - mu;
        sq += d * d;
    }
    red[t] = sq;
    __syncthreads();
    for (int o = 128; o > 0; o >>= 1) {
        if (t < o) red[t] += red[t + o];
        __syncthreads();
    }
    const float rstd = rsqrtf(red[0] * (1.f / DD) + EPS);

#pragma unroll
    for (int r = 0; r < 3; r++) {
        int idx = t + r * 256;
        float y = (v[r] - mu) * rstd * g[idx] + beta[idx];
        dst[(size_t)m * DD + idx] = y;
        if (hi) {
            __nv_bfloat16 hbf = __float2bfloat16(y);
            hi[(size_t)m * DD + idx] = hbf;
            lo[(size_t)m * DD + idx] = __float2bfloat16(y - __bfloat162float(hbf));
        }
    }
}

// ============================================================
// Launch
// ============================================================
extern "C" void kernel_launch(void* const* d_in, const int* in_sizes, int n_in,
                              void* d_out, int out_size)
{
    const float* x     = (const float*)d_in[0];
    const float* w_row = (const float*)d_in[1];
    const float* b_row = (const float*)d_in[2];
    const float* w_col = (const float*)d_in[3];
    const float* b_col = (const float*)d_in[4];
    const float* g1    = (const float*)d_in[5];
    const float* beta1 = (const float*)d_in[6];
    const float* g2    = (const float*)d_in[7];
    const float* beta2 = (const float*)d_in[8];
    const int*   mask  = (const int*)d_in[9];
    float* out = (float*)d_out;

    float *qkvf, *att, *out1;
    __nv_bfloat16 *ahi, *alo, *whi, *wlo;
    cudaGetSymbolAddress((void**)&qkvf, g_qkv);
    cudaGetSymbolAddress((void**)&att,  g_att);
    cudaGetSymbolAddress((void**)&out1, g_out1);
    cudaGetSymbolAddress((void**)&ahi,  g_ahi);
    cudaGetSymbolAddress((void**)&alo,  g_alo);
    cudaGetSymbolAddress((void**)&whi,  g_whi);
    cudaGetSymbolAddress((void**)&wlo,  g_wlo);
    __nv_bfloat16* qh = (__nv_bfloat16*)qkvf;
    __nv_bfloat16* ql = qh + (size_t)MROWS * N3;

    cudaFuncSetAttribute(mma_gemm_kernel,
                         cudaFuncAttributeMaxDynamicSharedMemorySize, GEMM_SMEM);
    cudaFuncSetAttribute(row_attn_mma_kernel,
                         cudaFuncAttributeMaxDynamicSharedMemorySize, ATT_SMEM);
    cudaFuncSetAttribute(col_attn_mma_kernel,
                         cudaFuncAttributeMaxDynamicSharedMemorySize, ATT_SMEM);

    const int nA4 = MROWS * DD / 4;
    const int nW4 = N3 * DD / 4;
    dim3 tcg(N3 / 128, MROWS / 128);   // (18, 256)

    // ---- stage 1: row attention ----
    split_kernel<<<4096, 256>>>(x, ahi, alo, nA4);
    split_kernel<<<1024, 256>>>(w_row, whi, wlo, nW4);
    mma_gemm_kernel<<<tcg, 256, GEMM_SMEM>>>(ahi, alo, whi, wlo, b_row, qh, ql);
    row_attn_mma_kernel<<<dim3(256, HH), 128, ATT_SMEM>>>(qh, ql, mask, att);
    add_ln_kernel<<<MROWS, 256>>>(x, att, g1, beta1, out1, ahi, alo);

    // ---- stage 2: column attention ----
    split_kernel<<<1024, 256>>>(w_col, whi, wlo, nW4);
    mma_gemm_kernel<<<tcg, 256, GEMM_SMEM>>>(ahi, alo, whi, wlo, b_col, qh, ql);
    col_attn_mma_kernel<<<dim3(L_L, HH), 128, ATT_SMEM>>>(qh, ql, mask, att);
    add_ln_kernel<<<MROWS, 256>>>(out1, att, g2, beta2, out, (__nv_bfloat16*)nullptr,
                                  (__nv_bfloat16*)nullptr);
}

// round 9
// speedup vs baseline: 5.0469x; 1.0225x over previous
#include <cuda_runtime.h>
#include <cuda_bf16.h>
#include <math.h>
#include <cstdint>

// Problem constants
#define B_E 128
#define L_L 256
#define HH  12
#define DH  64
#define DD  768           // H*DH
#define N3  2304          // 3*D
#define MROWS (B_E * L_L) // 32768
#define EPS 1e-5f
#define NEGV -10000.0f
#define QSCALE 0.125f     // DH^-0.5

// -------- scratch (allocation-free: __device__ globals) --------
__device__ float g_qkv[(size_t)MROWS * N3];   // carved into qkv_hi | qkv_lo bf16
__device__ float g_att[(size_t)MROWS * DD];
__device__ float g_out1[(size_t)MROWS * DD];
__device__ __nv_bfloat16 g_ahi[(size_t)MROWS * DD];
__device__ __nv_bfloat16 g_alo[(size_t)MROWS * DD];
__device__ __nv_bfloat16 g_whi[(size_t)N3 * DD];
__device__ __nv_bfloat16 g_wlo[(size_t)N3 * DD];

// ============================================================
// helpers
// ============================================================
__device__ __forceinline__ uint32_t pack_bf16(float a, float b) {
    __nv_bfloat162 t = __halves2bfloat162(__float2bfloat16(a), __float2bfloat16(b));
    return *(uint32_t*)&t;
}
__device__ __forceinline__ void split_pack(float a, float b,
                                           uint32_t& h, uint32_t& l) {
    __nv_bfloat16 ha = __float2bfloat16(a), hb = __float2bfloat16(b);
    float ra = a - __bfloat162float(ha), rb = b - __bfloat162float(hb);
    h = pack_bf16(__bfloat162float(ha), __bfloat162float(hb));
    __nv_bfloat162 t = __halves2bfloat162(__float2bfloat16(ra), __float2bfloat16(rb));
    l = *(uint32_t*)&t;
}
__device__ __forceinline__ uint32_t smem_u32(const void* p) {
    uint32_t a;
    asm("{ .reg .u64 t; cvta.to.shared.u64 t, %1; cvt.u32.u64 %0, t; }"
        : "=r"(a) : "l"(p));
    return a;
}

#define MMA_BF16(d, a, b)                                                     \
    asm volatile(                                                             \
        "mma.sync.aligned.m16n8k16.row.col.f32.bf16.bf16.f32 "                \
        "{%0,%1,%2,%3}, {%4,%5,%6,%7}, {%8,%9}, {%0,%1,%2,%3};"               \
        : "+f"(d[0]), "+f"(d[1]), "+f"(d[2]), "+f"(d[3])                      \
        : "r"(a[0]), "r"(a[1]), "r"(a[2]), "r"(a[3]), "r"(b[0]), "r"(b[1]))

#define LDSM_X4(r0, r1, r2, r3, addr)                                         \
    asm volatile("ldmatrix.sync.aligned.m8n8.x4.shared.b16 {%0,%1,%2,%3}, [%4];" \
        : "=r"(r0), "=r"(r1), "=r"(r2), "=r"(r3) : "r"(addr))
#define LDSM_X4_T(r0, r1, r2, r3, addr)                                       \
    asm volatile("ldmatrix.sync.aligned.m8n8.x4.trans.shared.b16 {%0,%1,%2,%3}, [%4];" \
        : "=r"(r0), "=r"(r1), "=r"(r2), "=r"(r3) : "r"(addr))
#define CP_ASYNC16(s, g)                                                      \
    asm volatile("cp.async.cg.shared.global [%0], [%1], 16;" :: "r"(s), "l"(g))
#define CP_COMMIT  asm volatile("cp.async.commit_group;" ::: "memory")
#define CP_WAIT0   asm volatile("cp.async.wait_group 0;" ::: "memory")
#define CP_WAIT2   asm volatile("cp.async.wait_group 2;" ::: "memory")

// ============================================================
// fp32 -> (bf16 hi, bf16 lo) split
// ============================================================
__global__ void __launch_bounds__(256) split_kernel(
    const float* __restrict__ in,
    __nv_bfloat16* __restrict__ hi, __nv_bfloat16* __restrict__ lo, int n4)
{
    int i = blockIdx.x * blockDim.x + threadIdx.x;
    int stride = gridDim.x * blockDim.x;
    for (; i < n4; i += stride) {
        float4 v = ((const float4*)in)[i];
        uint32_t h0, l0, h1, l1;
        split_pack(v.x, v.y, h0, l0);
        split_pack(v.z, v.w, h1, l1);
        ((uint32_t*)hi)[2 * i + 0] = h0;
        ((uint32_t*)hi)[2 * i + 1] = h1;
        ((uint32_t*)lo)[2 * i + 0] = l0;
        ((uint32_t*)lo)[2 * i + 1] = l1;
    }
}

// ============================================================
// Warp-MMA bf16 GEMM, 4-stage cp.async ring, ldmatrix frags.
// C = A*W^T + bias -> bf16 hi/lo split out (q pre-scaled).
// ============================================================
#define BK 32
#define ASTR 40
#define ROWB (ASTR * 2)               // 80 B
#define TILE_BYTES (128 * ROWB)
#define STAGE_BYTES (4 * TILE_BYTES)  // 40960
#define NSTAGE 4
#define GEMM_SMEM (NSTAGE * STAGE_BYTES)   // 163840

__device__ __forceinline__ void load_stage_async(
    uint32_t sb, int stage,
    const __nv_bfloat16* __restrict__ Ahi, const __nv_bfloat16* __restrict__ Alo,
    const __nv_bfloat16* __restrict__ Whi, const __nv_bfloat16* __restrict__ Wlo,
    size_t m0, size_t n0, int k0, int tid)
{
#pragma unroll
    for (int i = 0; i < 8; i++) {
        const int arr = i >> 1;
        const int rem = (i & 1) * 256 + tid;
        const int row = rem >> 2;
        const int seg = rem & 3;
        const __nv_bfloat16* src;
        size_t r0;
        if      (arr == 0) { src = Ahi; r0 = m0; }
        else if (arr == 1) { src = Alo; r0 = m0; }
        else if (arr == 2) { src = Whi; r0 = n0; }
        else               { src = Wlo; r0 = n0; }
        const void* g = src + (r0 + row) * DD + k0 + seg * 8;
        uint32_t s = sb + stage * STAGE_BYTES + arr * TILE_BYTES
                   + row * ROWB + seg * 16;
        CP_ASYNC16(s, g);
    }
}

__global__ void __launch_bounds__(256, 1) mma_gemm_kernel(
    const __nv_bfloat16* __restrict__ Ahi, const __nv_bfloat16* __restrict__ Alo,
    const __nv_bfloat16* __restrict__ Whi, const __nv_bfloat16* __restrict__ Wlo,
    const float* __restrict__ bias,
    __nv_bfloat16* __restrict__ Chi, __nv_bfloat16* __restrict__ Clo)
{
    extern __shared__ char sm[];
    const int tid  = threadIdx.x;
    const int wid  = tid >> 5;
    const int lane = tid & 31;
    const int wm   = wid >> 2;
    const int wn   = wid & 3;
    const int g    = lane >> 2;
    const int tig  = lane & 3;
    const int grp  = lane >> 3;

    const size_t m0 = (size_t)blockIdx.y * 128;
    const size_t n0 = (size_t)blockIdx.x * 128;
    const uint32_t sb = smem_u32(sm);
    const float scale = (blockIdx.x < 6) ? QSCALE : 1.0f;

    const uint32_t aoff = (uint32_t)((wm * 64 + (grp & 1) * 8 + (lane & 7)) * ROWB
                                     + ((grp >> 1) * 8) * 2);
    const uint32_t boff = (uint32_t)((wn * 32 + (grp >> 1) * 8 + (lane & 7)) * ROWB
                                     + ((grp & 1) * 8) * 2);

    float acc[4][4][4];
#pragma unroll
    for (int mt = 0; mt < 4; mt++)
#pragma unroll
        for (int nt = 0; nt < 4; nt++)
#pragma unroll
            for (int r = 0; r < 4; r++) acc[mt][nt][r] = 0.f;

    const int NKT = DD / BK;   // 24
    // prologue: stages 0..2 in flight
    load_stage_async(sb, 0, Ahi, Alo, Whi, Wlo, m0, n0, 0, tid);      CP_COMMIT;
    load_stage_async(sb, 1, Ahi, Alo, Whi, Wlo, m0, n0, BK, tid);     CP_COMMIT;
    load_stage_async(sb, 2, Ahi, Alo, Whi, Wlo, m0, n0, 2 * BK, tid); CP_COMMIT;

    for (int kt = 0; kt < NKT; kt++) {
        CP_WAIT2;             // all but 2 newest groups done => stage kt landed
        __syncthreads();
        // issue stage kt+3 (empty commit in tail keeps group math uniform)
        if (kt + 3 < NKT)
            load_stage_async(sb, (kt + 3) & (NSTAGE - 1),
                             Ahi, Alo, Whi, Wlo, m0, n0, (kt + 3) * BK, tid);
        CP_COMMIT;

        const uint32_t sA_h = sb + (uint32_t)(kt & (NSTAGE - 1)) * STAGE_BYTES;
        const uint32_t sA_l = sA_h + TILE_BYTES;
        const uint32_t sB_h = sA_h + 2 * TILE_BYTES;
        const uint32_t sB_l = sA_h + 3 * TILE_BYTES;

#pragma unroll
        for (int kk = 0; kk < 2; kk++) {
            const int kb = kk * 32;   // bytes
            uint32_t ah[4][4], al[4][4];
#pragma unroll
            for (int mt = 0; mt < 4; mt++) {
                LDSM_X4(ah[mt][0], ah[mt][1], ah[mt][2], ah[mt][3],
                        sA_h + aoff + mt * 16 * ROWB + kb);
                LDSM_X4(al[mt][0], al[mt][1], al[mt][2], al[mt][3],
                        sA_l + aoff + mt * 16 * ROWB + kb);
            }
            uint32_t bh[2][4], bl[2][4];
#pragma unroll
            for (int ntp = 0; ntp < 2; ntp++) {
                LDSM_X4(bh[ntp][0], bh[ntp][1], bh[ntp][2], bh[ntp][3],
                        sB_h + boff + ntp * 16 * ROWB + kb);
                LDSM_X4(bl[ntp][0], bl[ntp][1], bl[ntp][2], bl[ntp][3],
                        sB_l + boff + ntp * 16 * ROWB + kb);
            }
#pragma unroll
            for (int mt = 0; mt < 4; mt++)
#pragma unroll
                for (int ntp = 0; ntp < 2; ntp++) {
                    MMA_BF16(acc[mt][2 * ntp],     ah[mt], (&bh[ntp][0]));
                    MMA_BF16(acc[mt][2 * ntp],     ah[mt], (&bl[ntp][0]));
                    MMA_BF16(acc[mt][2 * ntp],     al[mt], (&bh[ntp][0]));
                    MMA_BF16(acc[mt][2 * ntp + 1], ah[mt], (&bh[ntp][2]));
                    MMA_BF16(acc[mt][2 * ntp + 1], ah[mt], (&bl[ntp][2]));
                    MMA_BF16(acc[mt][2 * ntp + 1], al[mt], (&bh[ntp][2]));
                }
        }
    }

    // Epilogue
#pragma unroll
    for (int mt = 0; mt < 4; mt++) {
        const size_t row = m0 + wm * 64 + mt * 16 + g;
#pragma unroll
        for (int nt = 0; nt < 4; nt++) {
            const size_t col = n0 + wn * 32 + nt * 8 + tig * 2;
            const float b0 = bias[col], b1 = bias[col + 1];
            float v0 = (acc[mt][nt][0] + b0) * scale;
            float v1 = (acc[mt][nt][1] + b1) * scale;
            float v2 = (acc[mt][nt][2] + b0) * scale;
            float v3 = (acc[mt][nt][3] + b1) * scale;
            uint32_t h, l;
            size_t idx = (row * N3 + col) >> 1;
            split_pack(v0, v1, h, l);
            ((uint32_t*)Chi)[idx] = h;
            ((uint32_t*)Clo)[idx] = l;
            split_pack(v2, v3, h, l);
            idx = ((row + 8) * N3 + col) >> 1;
            ((uint32_t*)Chi)[idx] = h;
            ((uint32_t*)Clo)[idx] = l;
        }
    }
}

// ============================================================
// Flash MMA attention, 128 queries/block, 4 warps, 2 CTAs/SM.
// K/V double-buffered via cp.async; V via ldmatrix.trans.
// ============================================================
#define QROWB 144                       // 72 halves * 2B
#define ATT_SMEM (2 * 18432 + 2 * 36864 + 1024)   // 111616

template<int NKEY>
__device__ __forceinline__ void attn_core(
    const __nv_bfloat16* __restrict__ qh_g, const __nv_bfloat16* __restrict__ ql_g,
    const int* __restrict__ mask, float* __restrict__ out,
    size_t qtok0, size_t ktok0, size_t ts,
    int mask0, int mstride, int h, char* sm)
{
    const int tid = threadIdx.x, wid = tid >> 5, lane = tid & 31;
    const int g = lane >> 2, tig = lane & 3, grp = lane >> 3;
    const uint32_t sb = smem_u32(sm);
    const uint32_t sQh = sb, sQl = sb + 18432;
    float* nm = (float*)(sm + 110592);

    // ---- prologue: Q + chunk0 via cp.async ----
#pragma unroll
    for (int arr = 0; arr < 2; arr++) {
        const __nv_bfloat16* src = arr ? ql_g : qh_g;
        uint32_t sq = arr ? sQl : sQh;
#pragma unroll
        for (int it = 0; it < 8; it++) {
            int p = it * 128 + tid;
            int row = p >> 3, seg = p & 7;
            const __nv_bfloat16* gp = src + (qtok0 + (size_t)row * ts) * N3
                                    + (size_t)h * DH + seg * 8;
            CP_ASYNC16(sq + row * QROWB + seg * 16, gp);
        }
    }
    auto load_chunk = [&](int c) {
        const uint32_t sbase = sb + 36864 + (uint32_t)(c & 1) * 36864;
        const int jb = c * 64;
#pragma unroll
        for (int arr = 0; arr < 2; arr++) {
            const __nv_bfloat16* src = arr ? ql_g : qh_g;
#pragma unroll
            for (int it = 0; it < 4; it++) {
                int p = it * 128 + tid;
                int tok = p >> 3, seg = p & 7;
                const __nv_bfloat16* base = src
                    + (ktok0 + (size_t)(jb + tok) * ts) * N3 + (size_t)h * DH;
                CP_ASYNC16(sbase + arr * 9216 + tok * QROWB + seg * 16,
                           base + DD + seg * 8);                       // K
                CP_ASYNC16(sbase + 18432 + arr * 9216 + tok * QROWB + seg * 16,
                           base + 2 * DD + seg * 8);                   // V
            }
        }
    };
    load_chunk(0);
    CP_COMMIT;

    for (int j = tid; j < NKEY; j += 128)
        nm[j] = mask[mask0 + j * mstride] ? NEGV : 0.f;

    const uint32_t qA_off = (uint32_t)((wid * 32 + (grp & 1) * 8 + (lane & 7)) * QROWB
                                       + ((grp >> 1) * 8) * 2);
    const uint32_t kB_off = (uint32_t)(((grp >> 1) * 8 + (lane & 7)) * QROWB
                                       + ((grp & 1) * 8) * 2);
    const uint32_t vB_off = (uint32_t)(((grp & 1) * 8 + (lane & 7)) * QROWB
                                       + ((grp >> 1) * 8) * 2);

    float m_[2][2], l_[2][2], O[2][8][4];
#pragma unroll
    for (int a = 0; a < 2; a++)
#pragma unroll
        for (int b = 0; b < 2; b++) { m_[a][b] = -1e30f; l_[a][b] = 0.f; }
#pragma unroll
    for (int a = 0; a < 2; a++)
#pragma unroll
        for (int b = 0; b < 8; b++)
#pragma unroll
            for (int r = 0; r < 4; r++) O[a][b][r] = 0.f;

    const int NC = NKEY / 64;
    for (int c = 0; c < NC; c++) {
        CP_WAIT0;
        __syncthreads();
        if (c + 1 < NC) { load_chunk(c + 1); CP_COMMIT; }

        const uint32_t sK = sb + 36864 + (uint32_t)(c & 1) * 36864;
        const uint32_t sV = sK + 18432;
        const int jb = c * 64;

        // ---- S = Q K^T ----
        float S[2][8][4];
#pragma unroll
        for (int a = 0; a < 2; a++)
#pragma unroll
            for (int b = 0; b < 8; b++)
#pragma unroll
                for (int r = 0; r < 4; r++) S[a][b][r] = 0.f;

#pragma unroll
        for (int kt = 0; kt < 4; kt++) {
            uint32_t aqh[2][4], aql[2][4];
#pragma unroll
            for (int mt = 0; mt < 2; mt++) {
                LDSM_X4(aqh[mt][0], aqh[mt][1], aqh[mt][2], aqh[mt][3],
                        sQh + qA_off + mt * 16 * QROWB + kt * 32);
                LDSM_X4(aql[mt][0], aql[mt][1], aql[mt][2], aql[mt][3],
                        sQl + qA_off + mt * 16 * QROWB + kt * 32);
            }
#pragma unroll
            for (int ntp = 0; ntp < 4; ntp++) {
                uint32_t kh[4], kl[4];
                LDSM_X4(kh[0], kh[1], kh[2], kh[3],
                        sK + kB_off + ntp * 16 * QROWB + kt * 32);
                LDSM_X4(kl[0], kl[1], kl[2], kl[3],
                        sK + 9216 + kB_off + ntp * 16 * QROWB + kt * 32);
#pragma unroll
                for (int mt = 0; mt < 2; mt++) {
                    MMA_BF16(S[mt][2 * ntp],     aqh[mt], (&kh[0]));
                    MMA_BF16(S[mt][2 * ntp],     aqh[mt], (&kl[0]));
                    MMA_BF16(S[mt][2 * ntp],     aql[mt], (&kh[0]));
                    MMA_BF16(S[mt][2 * ntp + 1], aqh[mt], (&kh[2]));
                    MMA_BF16(S[mt][2 * ntp + 1], aqh[mt], (&kl[2]));
                    MMA_BF16(S[mt][2 * ntp + 1], aql[mt], (&kh[2]));
                }
            }
        }

        // ---- mask + online softmax ----
#pragma unroll
        for (int mt = 0; mt < 2; mt++)
#pragma unroll
            for (int rh = 0; rh < 2; rh++) {
                float mx = -1e30f;
#pragma unroll
                for (int nt = 0; nt < 8; nt++) {
                    float v0 = S[mt][nt][rh * 2 + 0] + nm[jb + nt * 8 + 2 * tig];
                    float v1 = S[mt][nt][rh * 2 + 1] + nm[jb + nt * 8 + 2 * tig + 1];
                    S[mt][nt][rh * 2 + 0] = v0;
                    S[mt][nt][rh * 2 + 1] = v1;
                    mx = fmaxf(mx, fmaxf(v0, v1));
                }
                mx = fmaxf(mx, __shfl_xor_sync(0xffffffffu, mx, 1));
                mx = fmaxf(mx, __shfl_xor_sync(0xffffffffu, mx, 2));
                float mnew = fmaxf(m_[mt][rh], mx);
                float corr = __expf(m_[mt][rh] - mnew);
                m_[mt][rh] = mnew;
                float ps = 0.f;
#pragma unroll
                for (int nt = 0; nt < 8; nt++) {
                    float p0 = __expf(S[mt][nt][rh * 2 + 0] - mnew);
                    float p1 = __expf(S[mt][nt][rh * 2 + 1] - mnew);
                    S[mt][nt][rh * 2 + 0] = p0;
                    S[mt][nt][rh * 2 + 1] = p1;
                    ps += p0 + p1;
                }
                ps += __shfl_xor_sync(0xffffffffu, ps, 1);
                ps += __shfl_xor_sync(0xffffffffu, ps, 2);
                l_[mt][rh] = l_[mt][rh] * corr + ps;
#pragma unroll
                for (int nt = 0; nt < 8; nt++) {
                    O[mt][nt][rh * 2 + 0] *= corr;
                    O[mt][nt][rh * 2 + 1] *= corr;
                }
            }

        // ---- O += P V ----
#pragma unroll
        for (int kt = 0; kt < 4; kt++) {
            uint32_t ph[2][4], pl[2][4];
#pragma unroll
            for (int mt = 0; mt < 2; mt++) {
                split_pack(S[mt][2 * kt][0],     S[mt][2 * kt][1],     ph[mt][0], pl[mt][0]);
                split_pack(S[mt][2 * kt][2],     S[mt][2 * kt][3],     ph[mt][1], pl[mt][1]);
                split_pack(S[mt][2 * kt + 1][0], S[mt][2 * kt + 1][1], ph[mt][2], pl[mt][2]);
                split_pack(S[mt][2 * kt + 1][2], S[mt][2 * kt + 1][3], ph[mt][3], pl[mt][3]);
            }
#pragma unroll
            for (int ntp = 0; ntp < 4; ntp++) {
                uint32_t vh[4], vl[4];
                LDSM_X4_T(vh[0], vh[1], vh[2], vh[3],
                          sV + vB_off + kt * 16 * QROWB + ntp * 32);
                LDSM_X4_T(vl[0], vl[1], vl[2], vl[3],
                          sV + 9216 + vB_off + kt * 16 * QROWB + ntp * 32);
#pragma unroll
                for (int mt = 0; mt < 2; mt++) {
                    MMA_BF16(O[mt][2 * ntp],     ph[mt], (&vh[0]));
                    MMA_BF16(O[mt][2 * ntp],     ph[mt], (&vl[0]));
                    MMA_BF16(O[mt][2 * ntp],     pl[mt], (&vh[0]));
                    MMA_BF16(O[mt][2 * ntp + 1], ph[mt], (&vh[2]));
                    MMA_BF16(O[mt][2 * ntp + 1], ph[mt], (&vl[2]));
                    MMA_BF16(O[mt][2 * ntp + 1], pl[mt], (&vh[2]));
                }
            }
        }
    }

    // ---- finalize + write ----
#pragma unroll
    for (int mt = 0; mt < 2; mt++)
#pragma unroll
        for (int rh = 0; rh < 2; rh++) {
            float inv = 1.f / l_[mt][rh];
            int qr = wid * 32 + mt * 16 + g + rh * 8;
            size_t tok = qtok0 + (size_t)qr * ts;
            float* op = out + tok * DD + h * DH;
#pragma unroll
            for (int nt = 0; nt < 8; nt++) {
                float2 o;
                o.x = O[mt][nt][rh * 2 + 0] * inv;
                o.y = O[mt][nt][rh * 2 + 1] * inv;
                *(float2*)(op + nt * 8 + 2 * tig) = o;
            }
        }
}

__global__ void __launch_bounds__(128, 2) row_attn_mma_kernel(
    const __nv_bfloat16* __restrict__ qh_g, const __nv_bfloat16* __restrict__ ql_g,
    const int* __restrict__ mask, float* __restrict__ out)
{
    extern __shared__ char sm[];
    const int e = blockIdx.x >> 1, qt = blockIdx.x & 1, h = blockIdx.y;
    attn_core<256>(qh_g, ql_g, mask, out,
                   (size_t)e * L_L + qt * 128, (size_t)e * L_L, 1,
                   e * L_L, 1, h, sm);
}

__global__ void __launch_bounds__(128, 2) col_attn_mma_kernel(
    const __nv_bfloat16* __restrict__ qh_g, const __nv_bfloat16* __restrict__ ql_g,
    const int* __restrict__ mask, float* __restrict__ out)
{
    extern __shared__ char sm[];
    const int l = blockIdx.x, h = blockIdx.y;
    attn_core<128>(qh_g, ql_g, mask, out,
                   (size_t)l, (size_t)l, L_L,
                   l, L_L, h, sm);
}

// ============================================================
// Fused residual-add + LayerNorm (+ optional bf16 hi/lo split out)
// ============================================================
__global__ void __launch_bounds__(256) add_ln_kernel(
    const float* __restrict__ a, const float* __restrict__ b,
    const float* __restrict__ g, const float* __restrict__ beta,
    float* __restrict__ dst,
    __nv_bfloat16* __restrict__ hi, __nv_bfloat16* __restrict__ lo)
{
    const int m = blockIdx.x;
    const int t = threadIdx.x;
    __shared__ float red[256];

    float v[3];
    float s = 0.f;
#pragma unroll
    for (int r = 0; r < 3; r++) {
        int idx = t + r * 256;
        v[r] = a[(size_t)m * DD + idx] + b[(size_t)m * DD + idx];
        s += v[r];
    }
    red[t] = s;
    __syncthreads();
    for (int o = 128; o > 0; o >>= 1) {
        if (t < o) red[t] += red[t + o];
        __syncthreads();
    }
    const float mu = red[0] * (1.f / DD);
    __syncthreads();

    float sq = 0.f;
#pragma unroll
    for (int r = 0; r < 3; r++) {
        float d = v[r] - mu;
        sq += d * d;
    }
    red[t] = sq;
    __syncthreads();
    for (int o = 128; o > 0; o >>= 1) {
        if (t < o) red[t] += red[t + o];
        __syncthreads();
    }
    const float rstd = rsqrtf(red[0] * (1.f / DD) + EPS);

#pragma unroll
    for (int r = 0; r < 3; r++) {
        int idx = t + r * 256;
        float y = (v[r] - mu) * rstd * g[idx] + beta[idx];
        dst[(size_t)m * DD + idx] = y;
        if (hi) {
            __nv_bfloat16 hbf = __float2bfloat16(y);
            hi[(size_t)m * DD + idx] = hbf;
            lo[(size_t)m * DD + idx] = __float2bfloat16(y - __bfloat162float(hbf));
        }
    }
}

// ============================================================
// Launch
// ============================================================
extern "C" void kernel_launch(void* const* d_in, const int* in_sizes, int n_in,
                              void* d_out, int out_size)
{
    const float* x     = (const float*)d_in[0];
    const float* w_row = (const float*)d_in[1];
    const float* b_row = (const float*)d_in[2];
    const float* w_col = (const float*)d_in[3];
    const float* b_col = (const float*)d_in[4];
    const float* g1    = (const float*)d_in[5];
    const float* beta1 = (const float*)d_in[6];
    const float* g2    = (const float*)d_in[7];
    const float* beta2 = (const float*)d_in[8];
    const int*   mask  = (const int*)d_in[9];
    float* out = (float*)d_out;

    float *qkvf, *att, *out1;
    __nv_bfloat16 *ahi, *alo, *whi, *wlo;
    cudaGetSymbolAddress((void**)&qkvf, g_qkv);
    cudaGetSymbolAddress((void**)&att,  g_att);
    cudaGetSymbolAddress((void**)&out1, g_out1);
    cudaGetSymbolAddress((void**)&ahi,  g_ahi);
    cudaGetSymbolAddress((void**)&alo,  g_alo);
    cudaGetSymbolAddress((void**)&whi,  g_whi);
    cudaGetSymbolAddress((void**)&wlo,  g_wlo);
    __nv_bfloat16* qh = (__nv_bfloat16*)qkvf;
    __nv_bfloat16* ql = qh + (size_t)MROWS * N3;

    cudaFuncSetAttribute(mma_gemm_kernel,
                         cudaFuncAttributeMaxDynamicSharedMemorySize, GEMM_SMEM);
    cudaFuncSetAttribute(row_attn_mma_kernel,
                         cudaFuncAttributeMaxDynamicSharedMemorySize, ATT_SMEM);
    cudaFuncSetAttribute(col_attn_mma_kernel,
                         cudaFuncAttributeMaxDynamicSharedMemorySize, ATT_SMEM);

    const int nA4 = MROWS * DD / 4;
    const int nW4 = N3 * DD / 4;
    dim3 tcg(N3 / 128, MROWS / 128);   // (18, 256)

    // ---- stage 1: row attention ----
    split_kernel<<<4096, 256>>>(x, ahi, alo, nA4);
    split_kernel<<<1024, 256>>>(w_row, whi, wlo, nW4);
    mma_gemm_kernel<<<tcg, 256, GEMM_SMEM>>>(ahi, alo, whi, wlo, b_row, qh, ql);
    row_attn_mma_kernel<<<dim3(256, HH), 128, ATT_SMEM>>>(qh, ql, mask, att);
    add_ln_kernel<<<MROWS, 256>>>(x, att, g1, beta1, out1, ahi, alo);

    // ---- stage 2: column attention ----
    split_kernel<<<1024, 256>>>(w_col, whi, wlo, nW4);
    mma_gemm_kernel<<<tcg, 256, GEMM_SMEM>>>(ahi, alo, whi, wlo, b_col, qh, ql);
    col_attn_mma_kernel<<<dim3(L_L, HH), 128, ATT_SMEM>>>(qh, ql, mask, att);
    add_ln_kernel<<<MROWS, 256>>>(out1, att, g2, beta2, out, (__nv_bfloat16*)nullptr,
                                  (__nv_bfloat16*)nullptr);
}

// round 10
// speedup vs baseline: 6.3397x; 1.2561x over previous
#include <cuda_runtime.h>
#include <cuda_fp16.h>
#include <math.h>
#include <cstdint>

// Problem constants
#define B_E 128
#define L_L 256
#define HH  12
#define DH  64
#define DD  768           // H*DH
#define N3  2304          // 3*D
#define MROWS (B_E * L_L) // 32768
#define EPS 1e-5f
#define NEGV -10000.0f
#define QSCALE 0.125f     // DH^-0.5

// -------- scratch (allocation-free: __device__ globals) --------
__device__ float g_qkv[(size_t)MROWS * N3];   // carved into qkv_hi | qkv_lo fp16
__device__ float g_att[(size_t)MROWS * DD];
__device__ float g_out1[(size_t)MROWS * DD];
__device__ __half g_ahi[(size_t)MROWS * DD];
__device__ __half g_alo[(size_t)MROWS * DD];
__device__ __half g_whi[(size_t)N3 * DD];

// ============================================================
// helpers
// ============================================================
__device__ __forceinline__ void split_pack_h(float a, float b,
                                             uint32_t& h, uint32_t& l) {
    __half ha = __float2half_rn(a), hb = __float2half_rn(b);
    float ra = a - __half2float(ha), rb = b - __half2float(hb);
    __half2 th = __halves2half2(ha, hb);
    __half2 tl = __halves2half2(__float2half_rn(ra), __float2half_rn(rb));
    h = *(uint32_t*)&th;
    l = *(uint32_t*)&tl;
}
__device__ __forceinline__ uint32_t smem_u32(const void* p) {
    uint32_t a;
    asm("{ .reg .u64 t; cvta.to.shared.u64 t, %1; cvt.u32.u64 %0, t; }"
        : "=r"(a) : "l"(p));
    return a;
}

#define MMA_F16(d, a, b)                                                      \
    asm volatile(                                                             \
        "mma.sync.aligned.m16n8k16.row.col.f32.f16.f16.f32 "                  \
        "{%0,%1,%2,%3}, {%4,%5,%6,%7}, {%8,%9}, {%0,%1,%2,%3};"               \
        : "+f"(d[0]), "+f"(d[1]), "+f"(d[2]), "+f"(d[3])                      \
        : "r"(a[0]), "r"(a[1]), "r"(a[2]), "r"(a[3]), "r"(b[0]), "r"(b[1]))

#define LDSM_X4(r0, r1, r2, r3, addr)                                         \
    asm volatile("ldmatrix.sync.aligned.m8n8.x4.shared.b16 {%0,%1,%2,%3}, [%4];" \
        : "=r"(r0), "=r"(r1), "=r"(r2), "=r"(r3) : "r"(addr))
#define LDSM_X4_T(r0, r1, r2, r3, addr)                                       \
    asm volatile("ldmatrix.sync.aligned.m8n8.x4.trans.shared.b16 {%0,%1,%2,%3}, [%4];" \
        : "=r"(r0), "=r"(r1), "=r"(r2), "=r"(r3) : "r"(addr))
#define CP_ASYNC16(s, g)                                                      \
    asm volatile("cp.async.cg.shared.global [%0], [%1], 16;" :: "r"(s), "l"(g))
#define CP_COMMIT  asm volatile("cp.async.commit_group;" ::: "memory")
#define CP_WAIT0   asm volatile("cp.async.wait_group 0;" ::: "memory")
#define CP_WAIT2   asm volatile("cp.async.wait_group 2;" ::: "memory")

// ============================================================
// fp32 -> (fp16 hi, fp16 lo) split
// ============================================================
__global__ void __launch_bounds__(256) split_kernel(
    const float* __restrict__ in,
    __half* __restrict__ hi, __half* __restrict__ lo, int n4)
{
    int i = blockIdx.x * blockDim.x + threadIdx.x;
    int stride = gridDim.x * blockDim.x;
    for (; i < n4; i += stride) {
        float4 v = ((const float4*)in)[i];
        uint32_t h0, l0, h1, l1;
        split_pack_h(v.x, v.y, h0, l0);
        split_pack_h(v.z, v.w, h1, l1);
        ((uint32_t*)hi)[2 * i + 0] = h0;
        ((uint32_t*)hi)[2 * i + 1] = h1;
        ((uint32_t*)lo)[2 * i + 0] = l0;
        ((uint32_t*)lo)[2 * i + 1] = l1;
    }
}

// fp32 -> fp16 convert (weights: single fp16, no split needed)
__global__ void __launch_bounds__(256) cvt_kernel(
    const float* __restrict__ in, __half* __restrict__ out, int n4)
{
    int i = blockIdx.x * blockDim.x + threadIdx.x;
    int stride = gridDim.x * blockDim.x;
    for (; i < n4; i += stride) {
        float4 v = ((const float4*)in)[i];
        __half2 a = __halves2half2(__float2half_rn(v.x), __float2half_rn(v.y));
        __half2 b = __halves2half2(__float2half_rn(v.z), __float2half_rn(v.w));
        ((__half2*)out)[2 * i + 0] = a;
        ((__half2*)out)[2 * i + 1] = b;
    }
}

// ============================================================
// Warp-MMA fp16 GEMM, 2-term split: C = (ah+al)*bh + bias.
// 4-stage cp.async ring, ldmatrix frags. Out: fp16 hi/lo split.
// ============================================================
#define BK 32
#define ASTR 40
#define ROWB (ASTR * 2)               // 80 B
#define TILE_BYTES (128 * ROWB)       // 10240
#define STAGE_BYTES (3 * TILE_BYTES)  // 30720: Ah, Al, Bh
#define NSTAGE 4
#define GEMM_SMEM (NSTAGE * STAGE_BYTES)   // 122880

__device__ __forceinline__ void load_stage_async(
    uint32_t sb, int stage,
    const __half* __restrict__ Ahi, const __half* __restrict__ Alo,
    const __half* __restrict__ Whi,
    size_t m0, size_t n0, int k0, int tid)
{
#pragma unroll
    for (int i = 0; i < 6; i++) {
        const int arr = i >> 1;                 // 0:Ah 1:Al 2:Bh
        const int rem = (i & 1) * 256 + tid;    // 0..511
        const int row = rem >> 2;
        const int seg = rem & 3;
        const __half* src;
        size_t r0;
        if      (arr == 0) { src = Ahi; r0 = m0; }
        else if (arr == 1) { src = Alo; r0 = m0; }
        else               { src = Whi; r0 = n0; }
        const void* g = src + (r0 + row) * DD + k0 + seg * 8;
        uint32_t s = sb + stage * STAGE_BYTES + arr * TILE_BYTES
                   + row * ROWB + seg * 16;
        CP_ASYNC16(s, g);
    }
}

__global__ void __launch_bounds__(256, 1) mma_gemm_kernel(
    const __half* __restrict__ Ahi, const __half* __restrict__ Alo,
    const __half* __restrict__ Whi,
    const float* __restrict__ bias,
    __half* __restrict__ Chi, __half* __restrict__ Clo)
{
    extern __shared__ char sm[];
    const int tid  = threadIdx.x;
    const int wid  = tid >> 5;
    const int lane = tid & 31;
    const int wm   = wid >> 2;
    const int wn   = wid & 3;
    const int g    = lane >> 2;
    const int tig  = lane & 3;
    const int grp  = lane >> 3;

    const size_t m0 = (size_t)blockIdx.y * 128;
    const size_t n0 = (size_t)blockIdx.x * 128;
    const uint32_t sb = smem_u32(sm);
    const float scale = (blockIdx.x < 6) ? QSCALE : 1.0f;

    const uint32_t aoff = (uint32_t)((wm * 64 + (grp & 1) * 8 + (lane & 7)) * ROWB
                                     + ((grp >> 1) * 8) * 2);
    const uint32_t boff = (uint32_t)((wn * 32 + (grp >> 1) * 8 + (lane & 7)) * ROWB
                                     + ((grp & 1) * 8) * 2);

    float acc[4][4][4];
#pragma unroll
    for (int mt = 0; mt < 4; mt++)
#pragma unroll
        for (int nt = 0; nt < 4; nt++)
#pragma unroll
            for (int r = 0; r < 4; r++) acc[mt][nt][r] = 0.f;

    const int NKT = DD / BK;   // 24
    load_stage_async(sb, 0, Ahi, Alo, Whi, m0, n0, 0, tid);      CP_COMMIT;
    load_stage_async(sb, 1, Ahi, Alo, Whi, m0, n0, BK, tid);     CP_COMMIT;
    load_stage_async(sb, 2, Ahi, Alo, Whi, m0, n0, 2 * BK, tid); CP_COMMIT;

    for (int kt = 0; kt < NKT; kt++) {
        CP_WAIT2;
        __syncthreads();
        if (kt + 3 < NKT)
            load_stage_async(sb, (kt + 3) & (NSTAGE - 1),
                             Ahi, Alo, Whi, m0, n0, (kt + 3) * BK, tid);
        CP_COMMIT;

        const uint32_t sA_h = sb + (uint32_t)(kt & (NSTAGE - 1)) * STAGE_BYTES;
        const uint32_t sA_l = sA_h + TILE_BYTES;
        const uint32_t sB_h = sA_h + 2 * TILE_BYTES;

#pragma unroll
        for (int kk = 0; kk < 2; kk++) {
            const int kb = kk * 32;   // bytes
            uint32_t ah[4][4], al[4][4];
#pragma unroll
            for (int mt = 0; mt < 4; mt++) {
                LDSM_X4(ah[mt][0], ah[mt][1], ah[mt][2], ah[mt][3],
                        sA_h + aoff + mt * 16 * ROWB + kb);
                LDSM_X4(al[mt][0], al[mt][1], al[mt][2], al[mt][3],
                        sA_l + aoff + mt * 16 * ROWB + kb);
            }
            uint32_t bh[2][4];
#pragma unroll
            for (int ntp = 0; ntp < 2; ntp++) {
                LDSM_X4(bh[ntp][0], bh[ntp][1], bh[ntp][2], bh[ntp][3],
                        sB_h + boff + ntp * 16 * ROWB + kb);
            }
#pragma unroll
            for (int mt = 0; mt < 4; mt++)
#pragma unroll
                for (int ntp = 0; ntp < 2; ntp++) {
                    MMA_F16(acc[mt][2 * ntp],     ah[mt], (&bh[ntp][0]));
                    MMA_F16(acc[mt][2 * ntp],     al[mt], (&bh[ntp][0]));
                    MMA_F16(acc[mt][2 * ntp + 1], ah[mt], (&bh[ntp][2]));
                    MMA_F16(acc[mt][2 * ntp + 1], al[mt], (&bh[ntp][2]));
                }
        }
    }

    // Epilogue: bias, q-scale, fp16 hi/lo split write
#pragma unroll
    for (int mt = 0; mt < 4; mt++) {
        const size_t row = m0 + wm * 64 + mt * 16 + g;
#pragma unroll
        for (int nt = 0; nt < 4; nt++) {
            const size_t col = n0 + wn * 32 + nt * 8 + tig * 2;
            const float b0 = bias[col], b1 = bias[col + 1];
            float v0 = (acc[mt][nt][0] + b0) * scale;
            float v1 = (acc[mt][nt][1] + b1) * scale;
            float v2 = (acc[mt][nt][2] + b0) * scale;
            float v3 = (acc[mt][nt][3] + b1) * scale;
            uint32_t h, l;
            size_t idx = (row * N3 + col) >> 1;
            split_pack_h(v0, v1, h, l);
            ((uint32_t*)Chi)[idx] = h;
            ((uint32_t*)Clo)[idx] = l;
            split_pack_h(v2, v3, h, l);
            idx = ((row + 8) * N3 + col) >> 1;
            ((uint32_t*)Chi)[idx] = h;
            ((uint32_t*)Clo)[idx] = l;
        }
    }
}

// ============================================================
// Flash MMA attention (fp16, 3-term split), 128 queries/block,
// 4 warps, 2 CTAs/SM. K/V double-buffered; V via ldmatrix.trans.
// ============================================================
#define QROWB 144                       // 72 halves * 2B
#define ATT_SMEM (2 * 18432 + 2 * 36864 + 1024)   // 111616

template<int NKEY>
__device__ __forceinline__ void attn_core(
    const __half* __restrict__ qh_g, const __half* __restrict__ ql_g,
    const int* __restrict__ mask, float* __restrict__ out,
    size_t qtok0, size_t ktok0, size_t ts,
    int mask0, int mstride, int h, char* sm)
{
    const int tid = threadIdx.x, wid = tid >> 5, lane = tid & 31;
    const int g = lane >> 2, tig = lane & 3, grp = lane >> 3;
    const uint32_t sb = smem_u32(sm);
    const uint32_t sQh = sb, sQl = sb + 18432;
    float* nm = (float*)(sm + 110592);

    // ---- prologue: Q + chunk0 via cp.async ----
#pragma unroll
    for (int arr = 0; arr < 2; arr++) {
        const __half* src = arr ? ql_g : qh_g;
        uint32_t sq = arr ? sQl : sQh;
#pragma unroll
        for (int it = 0; it < 8; it++) {
            int p = it * 128 + tid;
            int row = p >> 3, seg = p & 7;
            const __half* gp = src + (qtok0 + (size_t)row * ts) * N3
                             + (size_t)h * DH + seg * 8;
            CP_ASYNC16(sq + row * QROWB + seg * 16, gp);
        }
    }
    auto load_chunk = [&](int c) {
        const uint32_t sbase = sb + 36864 + (uint32_t)(c & 1) * 36864;
        const int jb = c * 64;
#pragma unroll
        for (int arr = 0; arr < 2; arr++) {
            const __half* src = arr ? ql_g : qh_g;
#pragma unroll
            for (int it = 0; it < 4; it++) {
                int p = it * 128 + tid;
                int tok = p >> 3, seg = p & 7;
                const __half* base = src
                    + (ktok0 + (size_t)(jb + tok) * ts) * N3 + (size_t)h * DH;
                CP_ASYNC16(sbase + arr * 9216 + tok * QROWB + seg * 16,
                           base + DD + seg * 8);                       // K
                CP_ASYNC16(sbase + 18432 + arr * 9216 + tok * QROWB + seg * 16,
                           base + 2 * DD + seg * 8);                   // V
            }
        }
    };
    load_chunk(0);
    CP_COMMIT;

    for (int j = tid; j < NKEY; j += 128)
        nm[j] = mask[mask0 + j * mstride] ? NEGV : 0.f;

    const uint32_t qA_off = (uint32_t)((wid * 32 + (grp & 1) * 8 + (lane & 7)) * QROWB
                                       + ((grp >> 1) * 8) * 2);
    const uint32_t kB_off = (uint32_t)(((grp >> 1) * 8 + (lane & 7)) * QROWB
                                       + ((grp & 1) * 8) * 2);
    const uint32_t vB_off = (uint32_t)(((grp & 1) * 8 + (lane & 7)) * QROWB
                                       + ((grp >> 1) * 8) * 2);

    float m_[2][2], l_[2][2], O[2][8][4];
#pragma unroll
    for (int a = 0; a < 2; a++)
#pragma unroll
        for (int b = 0; b < 2; b++) { m_[a][b] = -1e30f; l_[a][b] = 0.f; }
#pragma unroll
    for (int a = 0; a < 2; a++)
#pragma unroll
        for (int b = 0; b < 8; b++)
#pragma unroll
            for (int r = 0; r < 4; r++) O[a][b][r] = 0.f;

    const int NC = NKEY / 64;
    for (int c = 0; c < NC; c++) {
        CP_WAIT0;
        __syncthreads();
        if (c + 1 < NC) { load_chunk(c + 1); CP_COMMIT; }

        const uint32_t sK = sb + 36864 + (uint32_t)(c & 1) * 36864;
        const uint32_t sV = sK + 18432;
        const int jb = c * 64;

        // ---- S = Q K^T (3-term) ----
        float S[2][8][4];
#pragma unroll
        for (int a = 0; a < 2; a++)
#pragma unroll
            for (int b = 0; b < 8; b++)
#pragma unroll
                for (int r = 0; r < 4; r++) S[a][b][r] = 0.f;

#pragma unroll
        for (int kt = 0; kt < 4; kt++) {
            uint32_t aqh[2][4], aql[2][4];
#pragma unroll
            for (int mt = 0; mt < 2; mt++) {
                LDSM_X4(aqh[mt][0], aqh[mt][1], aqh[mt][2], aqh[mt][3],
                        sQh + qA_off + mt * 16 * QROWB + kt * 32);
                LDSM_X4(aql[mt][0], aql[mt][1], aql[mt][2], aql[mt][3],
                        sQl + qA_off + mt * 16 * QROWB + kt * 32);
            }
#pragma unroll
            for (int ntp = 0; ntp < 4; ntp++) {
                uint32_t kh[4], kl[4];
                LDSM_X4(kh[0], kh[1], kh[2], kh[3],
                        sK + kB_off + ntp * 16 * QROWB + kt * 32);
                LDSM_X4(kl[0], kl[1], kl[2], kl[3],
                        sK + 9216 + kB_off + ntp * 16 * QROWB + kt * 32);
#pragma unroll
                for (int mt = 0; mt < 2; mt++) {
                    MMA_F16(S[mt][2 * ntp],     aqh[mt], (&kh[0]));
                    MMA_F16(S[mt][2 * ntp],     aqh[mt], (&kl[0]));
                    MMA_F16(S[mt][2 * ntp],     aql[mt], (&kh[0]));
                    MMA_F16(S[mt][2 * ntp + 1], aqh[mt], (&kh[2]));
                    MMA_F16(S[mt][2 * ntp + 1], aqh[mt], (&kl[2]));
                    MMA_F16(S[mt][2 * ntp + 1], aql[mt], (&kh[2]));
                }
            }
        }

        // ---- mask + online softmax ----
#pragma unroll
        for (int mt = 0; mt < 2; mt++)
#pragma unroll
            for (int rh = 0; rh < 2; rh++) {
                float mx = -1e30f;
#pragma unroll
                for (int nt = 0; nt < 8; nt++) {
                    float v0 = S[mt][nt][rh * 2 + 0] + nm[jb + nt * 8 + 2 * tig];
                    float v1 = S[mt][nt][rh * 2 + 1] + nm[jb + nt * 8 + 2 * tig + 1];
                    S[mt][nt][rh * 2 + 0] = v0;
                    S[mt][nt][rh * 2 + 1] = v1;
                    mx = fmaxf(mx, fmaxf(v0, v1));
                }
                mx = fmaxf(mx, __shfl_xor_sync(0xffffffffu, mx, 1));
                mx = fmaxf(mx, __shfl_xor_sync(0xffffffffu, mx, 2));
                float mnew = fmaxf(m_[mt][rh], mx);
                float corr = __expf(m_[mt][rh] - mnew);
                m_[mt][rh] = mnew;
                float ps = 0.f;
#pragma unroll
                for (int nt = 0; nt < 8; nt++) {
                    float p0 = __expf(S[mt][nt][rh * 2 + 0] - mnew);
                    float p1 = __expf(S[mt][nt][rh * 2 + 1] - mnew);
                    S[mt][nt][rh * 2 + 0] = p0;
                    S[mt][nt][rh * 2 + 1] = p1;
                    ps += p0 + p1;
                }
                ps += __shfl_xor_sync(0xffffffffu, ps, 1);
                ps += __shfl_xor_sync(0xffffffffu, ps, 2);
                l_[mt][rh] = l_[mt][rh] * corr + ps;
#pragma unroll
                for (int nt = 0; nt < 8; nt++) {
                    O[mt][nt][rh * 2 + 0] *= corr;
                    O[mt][nt][rh * 2 + 1] *= corr;
                }
            }

        // ---- O += P V (3-term) ----
#pragma unroll
        for (int kt = 0; kt < 4; kt++) {
            uint32_t ph[2][4], pl[2][4];
#pragma unroll
            for (int mt = 0; mt < 2; mt++) {
                split_pack_h(S[mt][2 * kt][0],     S[mt][2 * kt][1],     ph[mt][0], pl[mt][0]);
                split_pack_h(S[mt][2 * kt][2],     S[mt][2 * kt][3],     ph[mt][1], pl[mt][1]);
                split_pack_h(S[mt][2 * kt + 1][0], S[mt][2 * kt + 1][1], ph[mt][2], pl[mt][2]);
                split_pack_h(S[mt][2 * kt + 1][2], S[mt][2 * kt + 1][3], ph[mt][3], pl[mt][3]);
            }
#pragma unroll
            for (int ntp = 0; ntp < 4; ntp++) {
                uint32_t vh[4], vl[4];
                LDSM_X4_T(vh[0], vh[1], vh[2], vh[3],
                          sV + vB_off + kt * 16 * QROWB + ntp * 32);
                LDSM_X4_T(vl[0], vl[1], vl[2], vl[3],
                          sV + 9216 + vB_off + kt * 16 * QROWB + ntp * 32);
#pragma unroll
                for (int mt = 0; mt < 2; mt++) {
                    MMA_F16(O[mt][2 * ntp],     ph[mt], (&vh[0]));
                    MMA_F16(O[mt][2 * ntp],     ph[mt], (&vl[0]));
                    MMA_F16(O[mt][2 * ntp],     pl[mt], (&vh[0]));
                    MMA_F16(O[mt][2 * ntp + 1], ph[mt], (&vh[2]));
                    MMA_F16(O[mt][2 * ntp + 1], ph[mt], (&vl[2]));
                    MMA_F16(O[mt][2 * ntp + 1], pl[mt], (&vh[2]));
                }
            }
        }
    }

    // ---- finalize + write ----
#pragma unroll
    for (int mt = 0; mt < 2; mt++)
#pragma unroll
        for (int rh = 0; rh < 2; rh++) {
            float inv = 1.f / l_[mt][rh];
            int qr = wid * 32 + mt * 16 + g + rh * 8;
            size_t tok = qtok0 + (size_t)qr * ts;
            float* op = out + tok * DD + h * DH;
#pragma unroll
            for (int nt = 0; nt < 8; nt++) {
                float2 o;
                o.x = O[mt][nt][rh * 2 + 0] * inv;
                o.y = O[mt][nt][rh * 2 + 1] * inv;
                *(float2*)(op + nt * 8 + 2 * tig) = o;
            }
        }
}

__global__ void __launch_bounds__(128, 2) row_attn_mma_kernel(
    const __half* __restrict__ qh_g, const __half* __restrict__ ql_g,
    const int* __restrict__ mask, float* __restrict__ out)
{
    extern __shared__ char sm[];
    const int e = blockIdx.x >> 1, qt = blockIdx.x & 1, h = blockIdx.y;
    attn_core<256>(qh_g, ql_g, mask, out,
                   (size_t)e * L_L + qt * 128, (size_t)e * L_L, 1,
                   e * L_L, 1, h, sm);
}

__global__ void __launch_bounds__(128, 2) col_attn_mma_kernel(
    const __half* __restrict__ qh_g, const __half* __restrict__ ql_g,
    const int* __restrict__ mask, float* __restrict__ out)
{
    extern __shared__ char sm[];
    const int l = blockIdx.x, h = blockIdx.y;
    attn_core<128>(qh_g, ql_g, mask, out,
                   (size_t)l, (size_t)l, L_L,
                   l, L_L, h, sm);
}

// ============================================================
// Fused residual-add + LayerNorm (+ optional fp16 hi/lo split out)
// ============================================================
__global__ void __launch_bounds__(256) add_ln_kernel(
    const float* __restrict__ a, const float* __restrict__ b,
    const float* __restrict__ g, const float* __restrict__ beta,
    float* __restrict__ dst,
    __half* __restrict__ hi, __half* __restrict__ lo)
{
    const int m = blockIdx.x;
    const int t = threadIdx.x;
    __shared__ float red[256];

    float v[3];
    float s = 0.f;
#pragma unroll
    for (int r = 0; r < 3; r++) {
        int idx = t + r * 256;
        v[r] = a[(size_t)m * DD + idx] + b[(size_t)m * DD + idx];
        s += v[r];
    }
    red[t] = s;
    __syncthreads();
    for (int o = 128; o > 0; o >>= 1) {
        if (t < o) red[t] += red[t + o];
        __syncthreads();
    }
    const float mu = red[0] * (1.f / DD);
    __syncthreads();

    float sq = 0.f;
#pragma unroll
    for (int r = 0; r < 3; r++) {
        float d = v[r] - mu;
        sq += d * d;
    }
    red[t] = sq;
    __syncthreads();
    for (int o = 128; o > 0; o >>= 1) {
        if (t < o) red[t] += red[t + o];
        __syncthreads();
    }
    const float rstd = rsqrtf(red[0] * (1.f / DD) + EPS);

#pragma unroll
    for (int r = 0; r < 3; r++) {
        int idx = t + r * 256;
        float y = (v[r] - mu) * rstd * g[idx] + beta[idx];
        dst[(size_t)m * DD + idx] = y;
        if (hi) {
            __half hh = __float2half_rn(y);
            hi[(size_t)m * DD + idx] = hh;
            lo[(size_t)m * DD + idx] = __float2half_rn(y - __half2float(hh));
        }
    }
}

// ============================================================
// Launch
// ============================================================
extern "C" void kernel_launch(void* const* d_in, const int* in_sizes, int n_in,
                              void* d_out, int out_size)
{
    const float* x     = (const float*)d_in[0];
    const float* w_row = (const float*)d_in[1];
    const float* b_row = (const float*)d_in[2];
    const float* w_col = (const float*)d_in[3];
    const float* b_col = (const float*)d_in[4];
    const float* g1    = (const float*)d_in[5];
    const float* beta1 = (const float*)d_in[6];
    const float* g2    = (const float*)d_in[7];
    const float* beta2 = (const float*)d_in[8];
    const int*   mask  = (const int*)d_in[9];
    float* out = (float*)d_out;

    float *qkvf, *att, *out1;
    __half *ahi, *alo, *whi;
    cudaGetSymbolAddress((void**)&qkvf, g_qkv);
    cudaGetSymbolAddress((void**)&att,  g_att);
    cudaGetSymbolAddress((void**)&out1, g_out1);
    cudaGetSymbolAddress((void**)&ahi,  g_ahi);
    cudaGetSymbolAddress((void**)&alo,  g_alo);
    cudaGetSymbolAddress((void**)&whi,  g_whi);
    __half* qh = (__half*)qkvf;
    __half* ql = qh + (size_t)MROWS * N3;

    cudaFuncSetAttribute(mma_gemm_kernel,
                         cudaFuncAttributeMaxDynamicSharedMemorySize, GEMM_SMEM);
    cudaFuncSetAttribute(row_attn_mma_kernel,
                         cudaFuncAttributeMaxDynamicSharedMemorySize, ATT_SMEM);
    cudaFuncSetAttribute(col_attn_mma_kernel,
                         cudaFuncAttributeMaxDynamicSharedMemorySize, ATT_SMEM);

    const int nA4 = MROWS * DD / 4;
    const int nW4 = N3 * DD / 4;
    dim3 tcg(N3 / 128, MROWS / 128);   // (18, 256)

    // ---- stage 1: row attention ----
    split_kernel<<<4096, 256>>>(x, ahi, alo, nA4);
    cvt_kernel<<<1024, 256>>>(w_row, whi, nW4);
    mma_gemm_kernel<<<tcg, 256, GEMM_SMEM>>>(ahi, alo, whi, b_row, qh, ql);
    row_attn_mma_kernel<<<dim3(256, HH), 128, ATT_SMEM>>>(qh, ql, mask, att);
    add_ln_kernel<<<MROWS, 256>>>(x, att, g1, beta1, out1, ahi, alo);

    // ---- stage 2: column attention ----
    cvt_kernel<<<1024, 256>>>(w_col, whi, nW4);
    mma_gemm_kernel<<<tcg, 256, GEMM_SMEM>>>(ahi, alo, whi, b_col, qh, ql);
    col_attn_mma_kernel<<<dim3(L_L, HH), 128, ATT_SMEM>>>(qh, ql, mask, att);
    add_ln_kernel<<<MROWS, 256>>>(out1, att, g2, beta2, out, (__half*)nullptr,
                                  (__half*)nullptr);
}

// round 12
// speedup vs baseline: 10.1502x; 1.6011x over previous
#include <cuda_runtime.h>
#include <cuda_fp16.h>
#include <math.h>
#include <cstdint>

// Problem constants
#define B_E 128
#define L_L 256
#define HH  12
#define DH  64
#define DD  768           // H*DH
#define N3  2304          // 3*D
#define MROWS (B_E * L_L) // 32768
#define EPS 1e-5f
#define NEGV -10000.0f
#define QSCALE 0.125f     // DH^-0.5

// -------- scratch (allocation-free: __device__ globals) --------
__device__ float g_qkv[(size_t)MROWS * N3];   // carved into qkv_hi | qkv_lo fp16
__device__ float g_att[(size_t)MROWS * DD];
__device__ float g_out1[(size_t)MROWS * DD];
__device__ __half g_ahi[(size_t)MROWS * DD];
__device__ __half g_whi[(size_t)N3 * DD];

// ============================================================
// helpers
// ============================================================
__device__ __forceinline__ void split_pack_h(float a, float b,
                                             uint32_t& h, uint32_t& l) {
    __half ha = __float2half_rn(a), hb = __float2half_rn(b);
    float ra = a - __half2float(ha), rb = b - __half2float(hb);
    __half2 th = __halves2half2(ha, hb);
    __half2 tl = __halves2half2(__float2half_rn(ra), __float2half_rn(rb));
    h = *(uint32_t*)&th;
    l = *(uint32_t*)&tl;
}
__device__ __forceinline__ uint32_t smem_u32(const void* p) {
    uint32_t a;
    asm("{ .reg .u64 t; cvta.to.shared.u64 t, %1; cvt.u32.u64 %0, t; }"
        : "=r"(a) : "l"(p));
    return a;
}

#define MMA_F16(d, a, b)                                                      \
    asm volatile(                                                             \
        "mma.sync.aligned.m16n8k16.row.col.f32.f16.f16.f32 "                  \
        "{%0,%1,%2,%3}, {%4,%5,%6,%7}, {%8,%9}, {%0,%1,%2,%3};"               \
        : "+f"(d[0]), "+f"(d[1]), "+f"(d[2]), "+f"(d[3])                      \
        : "r"(a[0]), "r"(a[1]), "r"(a[2]), "r"(a[3]), "r"(b[0]), "r"(b[1]))

#define LDSM_X4(r0, r1, r2, r3, addr)                                         \
    asm volatile("ldmatrix.sync.aligned.m8n8.x4.shared.b16 {%0,%1,%2,%3}, [%4];" \
        : "=r"(r0), "=r"(r1), "=r"(r2), "=r"(r3) : "r"(addr))
#define LDSM_X4_T(r0, r1, r2, r3, addr)                                       \
    asm volatile("ldmatrix.sync.aligned.m8n8.x4.trans.shared.b16 {%0,%1,%2,%3}, [%4];" \
        : "=r"(r0), "=r"(r1), "=r"(r2), "=r"(r3) : "r"(addr))
#define CP_ASYNC16(s, g)                                                      \
    asm volatile("cp.async.cg.shared.global [%0], [%1], 16;" :: "r"(s), "l"(g))
#define CP_COMMIT  asm volatile("cp.async.commit_group;" ::: "memory")
#define CP_WAIT0   asm volatile("cp.async.wait_group 0;" ::: "memory")
#define CP_WAIT2   asm volatile("cp.async.wait_group 2;" ::: "memory")

// ============================================================
// fp32 -> fp16 convert
// ============================================================
__global__ void __launch_bounds__(256) cvt_kernel(
    const float* __restrict__ in, __half* __restrict__ out, int n4)
{
    int i = blockIdx.x * blockDim.x + threadIdx.x;
    int stride = gridDim.x * blockDim.x;
    for (; i < n4; i += stride) {
        float4 v = ((const float4*)in)[i];
        __half2 a = __halves2half2(__float2half_rn(v.x), __float2half_rn(v.y));
        __half2 b = __halves2half2(__float2half_rn(v.z), __float2half_rn(v.w));
        ((__half2*)out)[2 * i + 0] = a;
        ((__half2*)out)[2 * i + 1] = b;
    }
}

// ============================================================
// Warp-MMA fp16 GEMM (single-term): C = ah*bh + bias.
// 4-stage cp.async ring, 2 tiles/stage, 2 CTAs/SM.
// Out: fp16 hi/lo split (q pre-scaled by QSCALE).
// ============================================================
#define BK 32
#define ASTR 40
#define ROWB (ASTR * 2)               // 80 B
#define TILE_BYTES (128 * ROWB)       // 10240
#define STAGE_BYTES (2 * TILE_BYTES)  // 20480: Ah, Bh
#define NSTAGE 4
#define GEMM_SMEM (NSTAGE * STAGE_BYTES)   // 81920

__device__ __forceinline__ void load_stage_async(
    uint32_t sb, int stage,
    const __half* __restrict__ Ahi, const __half* __restrict__ Whi,
    size_t m0, size_t n0, int k0, int tid)
{
#pragma unroll
    for (int i = 0; i < 4; i++) {
        const int arr = i >> 1;                 // 0:Ah 1:Bh
        const int rem = (i & 1) * 256 + tid;    // 0..511
        const int row = rem >> 2;
        const int seg = rem & 3;
        const __half* src = arr ? Whi : Ahi;
        const size_t r0 = arr ? n0 : m0;
        const void* g = src + (r0 + row) * DD + k0 + seg * 8;
        uint32_t s = sb + stage * STAGE_BYTES + arr * TILE_BYTES
                   + row * ROWB + seg * 16;
        CP_ASYNC16(s, g);
    }
}

__global__ void __launch_bounds__(256, 2) mma_gemm_kernel(
    const __half* __restrict__ Ahi, const __half* __restrict__ Whi,
    const float* __restrict__ bias,
    __half* __restrict__ Chi, __half* __restrict__ Clo)
{
    extern __shared__ char sm[];
    const int tid  = threadIdx.x;
    const int wid  = tid >> 5;
    const int lane = tid & 31;
    const int wm   = wid >> 2;
    const int wn   = wid & 3;
    const int g    = lane >> 2;
    const int tig  = lane & 3;
    const int grp  = lane >> 3;

    const size_t m0 = (size_t)blockIdx.y * 128;
    const size_t n0 = (size_t)blockIdx.x * 128;
    const uint32_t sb = smem_u32(sm);
    const float scale = (blockIdx.x < 6) ? QSCALE : 1.0f;

    const uint32_t aoff = (uint32_t)((wm * 64 + (grp & 1) * 8 + (lane & 7)) * ROWB
                                     + ((grp >> 1) * 8) * 2);
    const uint32_t boff = (uint32_t)((wn * 32 + (grp >> 1) * 8 + (lane & 7)) * ROWB
                                     + ((grp & 1) * 8) * 2);

    float acc[4][4][4];
#pragma unroll
    for (int mt = 0; mt < 4; mt++)
#pragma unroll
        for (int nt = 0; nt < 4; nt++)
#pragma unroll
            for (int r = 0; r < 4; r++) acc[mt][nt][r] = 0.f;

    const int NKT = DD / BK;   // 24
    load_stage_async(sb, 0, Ahi, Whi, m0, n0, 0, tid);      CP_COMMIT;
    load_stage_async(sb, 1, Ahi, Whi, m0, n0, BK, tid);     CP_COMMIT;
    load_stage_async(sb, 2, Ahi, Whi, m0, n0, 2 * BK, tid); CP_COMMIT;

    for (int kt = 0; kt < NKT; kt++) {
        CP_WAIT2;
        __syncthreads();
        if (kt + 3 < NKT)
            load_stage_async(sb, (kt + 3) & (NSTAGE - 1),
                             Ahi, Whi, m0, n0, (kt + 3) * BK, tid);
        CP_COMMIT;

        const uint32_t sA_h = sb + (uint32_t)(kt & (NSTAGE - 1)) * STAGE_BYTES;
        const uint32_t sB_h = sA_h + TILE_BYTES;

#pragma unroll
        for (int kk = 0; kk < 2; kk++) {
            const int kb = kk * 32;   // bytes
            uint32_t ah[4][4];
#pragma unroll
            for (int mt = 0; mt < 4; mt++) {
                LDSM_X4(ah[mt][0], ah[mt][1], ah[mt][2], ah[mt][3],
                        sA_h + aoff + mt * 16 * ROWB + kb);
            }
            uint32_t bh[2][4];
#pragma unroll
            for (int ntp = 0; ntp < 2; ntp++) {
                LDSM_X4(bh[ntp][0], bh[ntp][1], bh[ntp][2], bh[ntp][3],
                        sB_h + boff + ntp * 16 * ROWB + kb);
            }
#pragma unroll
            for (int mt = 0; mt < 4; mt++)
#pragma unroll
                for (int ntp = 0; ntp < 2; ntp++) {
                    MMA_F16(acc[mt][2 * ntp],     ah[mt], (&bh[ntp][0]));
                    MMA_F16(acc[mt][2 * ntp + 1], ah[mt], (&bh[ntp][2]));
                }
        }
    }

    // Epilogue: bias, q-scale, fp16 hi/lo split write
#pragma unroll
    for (int mt = 0; mt < 4; mt++) {
        const size_t row = m0 + wm * 64 + mt * 16 + g;
#pragma unroll
        for (int nt = 0; nt < 4; nt++) {
            const size_t col = n0 + wn * 32 + nt * 8 + tig * 2;
            const float b0 = bias[col], b1 = bias[col + 1];
            float v0 = (acc[mt][nt][0] + b0) * scale;
            float v1 = (acc[mt][nt][1] + b1) * scale;
            float v2 = (acc[mt][nt][2] + b0) * scale;
            float v3 = (acc[mt][nt][3] + b1) * scale;
            uint32_t h, l;
            size_t idx = (row * N3 + col) >> 1;
            split_pack_h(v0, v1, h, l);
            ((uint32_t*)Chi)[idx] = h;
            ((uint32_t*)Clo)[idx] = l;
            split_pack_h(v2, v3, h, l);
            idx = ((row + 8) * N3 + col) >> 1;
            ((uint32_t*)Chi)[idx] = h;
            ((uint32_t*)Clo)[idx] = l;
        }
    }
}

// ============================================================
// Flash MMA attention (fp16, 3-term split), 128 queries/block,
// 4 warps, 2 CTAs/SM. K/V double-buffered; V via ldmatrix.trans.
// ============================================================
#define QROWB 144                       // 72 halves * 2B
#define ATT_SMEM (2 * 18432 + 2 * 36864 + 1024)   // 111616

template<int NKEY>
__device__ __forceinline__ void attn_core(
    const __half* __restrict__ qh_g, const __half* __restrict__ ql_g,
    const int* __restrict__ mask, float* __restrict__ out,
    size_t qtok0, size_t ktok0, size_t ts,
    int mask0, int mstride, int h, char* sm)
{
    const int tid = threadIdx.x, wid = tid >> 5, lane = tid & 31;
    const int g = lane >> 2, tig = lane & 3, grp = lane >> 3;
    const uint32_t sb = smem_u32(sm);
    const uint32_t sQh = sb, sQl = sb + 18432;
    float* nm = (float*)(sm + 110592);

    // ---- prologue: Q + chunk0 via cp.async ----
#pragma unroll
    for (int arr = 0; arr < 2; arr++) {
        const __half* src = arr ? ql_g : qh_g;
        uint32_t sq = arr ? sQl : sQh;
#pragma unroll
        for (int it = 0; it < 8; it++) {
            int p = it * 128 + tid;
            int row = p >> 3, seg = p & 7;
            const __half* gp = src + (qtok0 + (size_t)row * ts) * N3
                             + (size_t)h * DH + seg * 8;
            CP_ASYNC16(sq + row * QROWB + seg * 16, gp);
        }
    }
    auto load_chunk = [&](int c) {
        const uint32_t sbase = sb + 36864 + (uint32_t)(c & 1) * 36864;
        const int jb = c * 64;
#pragma unroll
        for (int arr = 0; arr < 2; arr++) {
            const __half* src = arr ? ql_g : qh_g;
#pragma unroll
            for (int it = 0; it < 4; it++) {
                int p = it * 128 + tid;
                int tok = p >> 3, seg = p & 7;
                const __half* base = src
                    + (ktok0 + (size_t)(jb + tok) * ts) * N3 + (size_t)h * DH;
                CP_ASYNC16(sbase + arr * 9216 + tok * QROWB + seg * 16,
                           base + DD + seg * 8);                       // K
                CP_ASYNC16(sbase + 18432 + arr * 9216 + tok * QROWB + seg * 16,
                           base + 2 * DD + seg * 8);                   // V
            }
        }
    };
    load_chunk(0);
    CP_COMMIT;

    for (int j = tid; j < NKEY; j += 128)
        nm[j] = mask[mask0 + j * mstride] ? NEGV : 0.f;

    const uint32_t qA_off = (uint32_t)((wid * 32 + (grp & 1) * 8 + (lane & 7)) * QROWB
                                       + ((grp >> 1) * 8) * 2);
    const uint32_t kB_off = (uint32_t)(((grp >> 1) * 8 + (lane & 7)) * QROWB
                                       + ((grp & 1) * 8) * 2);
    const uint32_t vB_off = (uint32_t)(((grp & 1) * 8 + (lane & 7)) * QROWB
                                       + ((grp >> 1) * 8) * 2);

    float m_[2][2], l_[2][2], O[2][8][4];
#pragma unroll
    for (int a = 0; a < 2; a++)
#pragma unroll
        for (int b = 0; b < 2; b++) { m_[a][b] = -1e30f; l_[a][b] = 0.f; }
#pragma unroll
    for (int a = 0; a < 2; a++)
#pragma unroll
        for (int b = 0; b < 8; b++)
#pragma unroll
            for (int r = 0; r < 4; r++) O[a][b][r] = 0.f;

    const int NC = NKEY / 64;
    for (int c = 0; c < NC; c++) {
        CP_WAIT0;
        __syncthreads();
        if (c + 1 < NC) { load_chunk(c + 1); CP_COMMIT; }

        const uint32_t sK = sb + 36864 + (uint32_t)(c & 1) * 36864;
        const uint32_t sV = sK + 18432;
        const int jb = c * 64;

        // ---- S = Q K^T (3-term) ----
        float S[2][8][4];
#pragma unroll
        for (int a = 0; a < 2; a++)
#pragma unroll
            for (int b = 0; b < 8; b++)
#pragma unroll
                for (int r = 0; r < 4; r++) S[a][b][r] = 0.f;

#pragma unroll
        for (int kt = 0; kt < 4; kt++) {
            uint32_t aqh[2][4], aql[2][4];
#pragma unroll
            for (int mt = 0; mt < 2; mt++) {
                LDSM_X4(aqh[mt][0], aqh[mt][1], aqh[mt][2], aqh[mt][3],
                        sQh + qA_off + mt * 16 * QROWB + kt * 32);
                LDSM_X4(aql[mt][0], aql[mt][1], aql[mt][2], aql[mt][3],
                        sQl + qA_off + mt * 16 * QROWB + kt * 32);
            }
#pragma unroll
            for (int ntp = 0; ntp < 4; ntp++) {
                uint32_t kh[4], kl[4];
                LDSM_X4(kh[0], kh[1], kh[2], kh[3],
                        sK + kB_off + ntp * 16 * QROWB + kt * 32);
                LDSM_X4(kl[0], kl[1], kl[2], kl[3],
                        sK + 9216 + kB_off + ntp * 16 * QROWB + kt * 32);
#pragma unroll
                for (int mt = 0; mt < 2; mt++) {
                    MMA_F16(S[mt][2 * ntp],     aqh[mt], (&kh[0]));
                    MMA_F16(S[mt][2 * ntp],     aqh[mt], (&kl[0]));
                    MMA_F16(S[mt][2 * ntp],     aql[mt], (&kh[0]));
                    MMA_F16(S[mt][2 * ntp + 1], aqh[mt], (&kh[2]));
                    MMA_F16(S[mt][2 * ntp + 1], aqh[mt], (&kl[2]));
                    MMA_F16(S[mt][2 * ntp + 1], aql[mt], (&kh[2]));
                }
            }
        }

        // ---- mask + online softmax ----
#pragma unroll
        for (int mt = 0; mt < 2; mt++)
#pragma unroll
            for (int rh = 0; rh < 2; rh++) {
                float mx = -1e30f;
#pragma unroll
                for (int nt = 0; nt < 8; nt++) {
                    float v0 = S[mt][nt][rh * 2 + 0] + nm[jb + nt * 8 + 2 * tig];
                    float v1 = S[mt][nt][rh * 2 + 1] + nm[jb + nt * 8 + 2 * tig + 1];
                    S[mt][nt][rh * 2 + 0] = v0;
                    S[mt][nt][rh * 2 + 1] = v1;
                    mx = fmaxf(mx, fmaxf(v0, v1));
                }
                mx = fmaxf(mx, __shfl_xor_sync(0xffffffffu, mx, 1));
                mx = fmaxf(mx, __shfl_xor_sync(0xffffffffu, mx, 2));
                float mnew = fmaxf(m_[mt][rh], mx);
                float corr = __expf(m_[mt][rh] - mnew);
                m_[mt][rh] = mnew;
                float ps = 0.f;
#pragma unroll
                for (int nt = 0; nt < 8; nt++) {
                    float p0 = __expf(S[mt][nt][rh * 2 + 0] - mnew);
                    float p1 = __expf(S[mt][nt][rh * 2 + 1] - mnew);
                    S[mt][nt][rh * 2 + 0] = p0;
                    S[mt][nt][rh * 2 + 1] = p1;
                    ps += p0 + p1;
                }
                ps += __shfl_xor_sync(0xffffffffu, ps, 1);
                ps += __shfl_xor_sync(0xffffffffu, ps, 2);
                l_[mt][rh] = l_[mt][rh] * corr + ps;
#pragma unroll
                for (int nt = 0; nt < 8; nt++) {
                    O[mt][nt][rh * 2 + 0] *= corr;
                    O[mt][nt][rh * 2 + 1] *= corr;
                }
            }

        // ---- O += P V (3-term) ----
#pragma unroll
        for (int kt = 0; kt < 4; kt++) {
            uint32_t ph[2][4], pl[2][4];
#pragma unroll
            for (int mt = 0; mt < 2; mt++) {
                split_pack_h(S[mt][2 * kt][0],     S[mt][2 * kt][1],     ph[mt][0], pl[mt][0]);
                split_pack_h(S[mt][2 * kt][2],     S[mt][2 * kt][3],     ph[mt][1], pl[mt][1]);
                split_pack_h(S[mt][2 * kt + 1][0], S[mt][2 * kt + 1][1], ph[mt][2], pl[mt][2]);
                split_pack_h(S[mt][2 * kt + 1][2], S[mt][2 * kt + 1][3], ph[mt][3], pl[mt][3]);
            }
#pragma unroll
            for (int ntp = 0; ntp < 4; ntp++) {
                uint32_t vh[4], vl[4];
                LDSM_X4_T(vh[0], vh[1], vh[2], vh[3],
                          sV + vB_off + kt * 16 * QROWB + ntp * 32);
                LDSM_X4_T(vl[0], vl[1], vl[2], vl[3],
                          sV + 9216 + vB_off + kt * 16 * QROWB + ntp * 32);
#pragma unroll
                for (int mt = 0; mt < 2; mt++) {
                    MMA_F16(O[mt][2 * ntp],     ph[mt], (&vh[0]));
                    MMA_F16(O[mt][2 * ntp],     ph[mt], (&vl[0]));
                    MMA_F16(O[mt][2 * ntp],     pl[mt], (&vh[0]));
                    MMA_F16(O[mt][2 * ntp + 1], ph[mt], (&vh[2]));
                    MMA_F16(O[mt][2 * ntp + 1], ph[mt], (&vl[2]));
                    MMA_F16(O[mt][2 * ntp + 1], pl[mt], (&vh[2]));
                }
            }
        }
    }

    // ---- finalize + write ----
#pragma unroll
    for (int mt = 0; mt < 2; mt++)
#pragma unroll
        for (int rh = 0; rh < 2; rh++) {
            float inv = 1.f / l_[mt][rh];
            int qr = wid * 32 + mt * 16 + g + rh * 8;
            size_t tok = qtok0 + (size_t)qr * ts;
            float* op = out + tok * DD + h * DH;
#pragma unroll
            for (int nt = 0; nt < 8; nt++) {
                float2 o;
                o.x = O[mt][nt][rh * 2 + 0] * inv;
                o.y = O[mt][nt][rh * 2 + 1] * inv;
                *(float2*)(op + nt * 8 + 2 * tig) = o;
            }
        }
}

__global__ void __launch_bounds__(128, 2) row_attn_mma_kernel(
    const __half* __restrict__ qh_g, const __half* __restrict__ ql_g,
    const int* __restrict__ mask, float* __restrict__ out)
{
    extern __shared__ char sm[];
    const int e = blockIdx.x >> 1, qt = blockIdx.x & 1, h = blockIdx.y;
    attn_core<256>(qh_g, ql_g, mask, out,
                   (size_t)e * L_L + qt * 128, (size_t)e * L_L, 1,
                   e * L_L, 1, h, sm);
}

__global__ void __launch_bounds__(128, 2) col_attn_mma_kernel(
    const __half* __restrict__ qh_g, const __half* __restrict__ ql_g,
    const int* __restrict__ mask, float* __restrict__ out)
{
    extern __shared__ char sm[];
    const int l = blockIdx.x, h = blockIdx.y;
    attn_core<128>(qh_g, ql_g, mask, out,
                   (size_t)l, (size_t)l, L_L,
                   l, L_L, h, sm);
}

// ============================================================
// Fused residual-add + LayerNorm (+ optional fp16 convert out)
// ============================================================
__global__ void __launch_bounds__(256) add_ln_kernel(
    const float* __restrict__ a, const float* __restrict__ b,
    const float* __restrict__ g, const float* __restrict__ beta,
    float* __restrict__ dst, __half* __restrict__ hi)
{
    const int m = blockIdx.x;
    const int t = threadIdx.x;
    __shared__ float red[256];

    float v[3];
    float s = 0.f;
#pragma unroll
    for (int r = 0; r < 3; r++) {
        int idx = t + r * 256;
        v[r] = a[(size_t)m * DD + idx] + b[(size_t)m * DD + idx];
        s += v[r];
    }
    red[t] = s;
    __syncthreads();
    for (int o = 128; o > 0; o >>= 1) {
        if (t < o) red[t] += red[t + o];
        __syncthreads();
    }
    const float mu = red[0] * (1.f / DD);
    __syncthreads();

    float sq = 0.f;
#pragma unroll
    for (int r = 0; r < 3; r++) {
        float d = v[r] - mu;
        sq += d * d;
    }
    red[t] = sq;
    __syncthreads();
    for (int o = 128; o > 0; o >>= 1) {
        if (t < o) red[t] += red[t + o];
        __syncthreads();
    }
    const float rstd = rsqrtf(red[0] * (1.f / DD) + EPS);

#pragma unroll
    for (int r = 0; r < 3; r++) {
        int idx = t + r * 256;
        float y = (v[r] - mu) * rstd * g[idx] + beta[idx];
        dst[(size_t)m * DD + idx] = y;
        if (hi) hi[(size_t)m * DD + idx] = __float2half_rn(y);
    }
}

// ============================================================
// Launch
// ============================================================
extern "C" void kernel_launch(void* const* d_in, const int* in_sizes, int n_in,
                              void* d_out, int out_size)
{
    const float* x     = (const float*)d_in[0];
    const float* w_row = (const float*)d_in[1];
    const float* b_row = (const float*)d_in[2];
    const float* w_col = (const float*)d_in[3];
    const float* b_col = (const float*)d_in[4];
    const float* g1    = (const float*)d_in[5];
    const float* beta1 = (const float*)d_in[6];
    const float* g2    = (const float*)d_in[7];
    const float* beta2 = (const float*)d_in[8];
    const int*   mask  = (const int*)d_in[9];
    float* out = (float*)d_out;

    float *qkvf, *att, *out1;
    __half *ahi, *whi;
    cudaGetSymbolAddress((void**)&qkvf, g_qkv);
    cudaGetSymbolAddress((void**)&att,  g_att);
    cudaGetSymbolAddress((void**)&out1, g_out1);
    cudaGetSymbolAddress((void**)&ahi,  g_ahi);
    cudaGetSymbolAddress((void**)&whi,  g_whi);
    __half* qh = (__half*)qkvf;
    __half* ql = qh + (size_t)MROWS * N3;

    cudaFuncSetAttribute(mma_gemm_kernel,
                         cudaFuncAttributeMaxDynamicSharedMemorySize, GEMM_SMEM);
    cudaFuncSetAttribute(row_attn_mma_kernel,
                         cudaFuncAttributeMaxDynamicSharedMemorySize, ATT_SMEM);
    cudaFuncSetAttribute(col_attn_mma_kernel,
                         cudaFuncAttributeMaxDynamicSharedMemorySize, ATT_SMEM);

    const int nA4 = MROWS * DD / 4;
    const int nW4 = N3 * DD / 4;
    dim3 tcg(N3 / 128, MROWS / 128);   // (18, 256)

    // ---- stage 1: row attention ----
    cvt_kernel<<<4096, 256>>>(x, ahi, nA4);
    cvt_kernel<<<1024, 256>>>(w_row, whi, nW4);
    mma_gemm_kernel<<<tcg, 256, GEMM_SMEM>>>(ahi, whi, b_row, qh, ql);
    row_attn_mma_kernel<<<dim3(256, HH), 128, ATT_SMEM>>>(qh, ql, mask, att);
    add_ln_kernel<<<MROWS, 256>>>(x, att, g1, beta1, out1, ahi);

    // ---- stage 2: column attention ----
    cvt_kernel<<<1024, 256>>>(w_col, whi, nW4);
    mma_gemm_kernel<<<tcg, 256, GEMM_SMEM>>>(ahi, whi, b_col, qh, ql);
    col_attn_mma_kernel<<<dim3(L_L, HH), 128, ATT_SMEM>>>(qh, ql, mask, att);
    add_ln_kernel<<<MROWS, 256>>>(out1, att, g2, beta2, out, (__half*)nullptr);
}

// round 13
// speedup vs baseline: 12.9739x; 1.2782x over previous
#include <cuda_runtime.h>
#include <cuda_fp16.h>
#include <math.h>
#include <cstdint>

// Problem constants
#define B_E 128
#define L_L 256
#define HH  12
#define DH  64
#define DD  768           // H*DH
#define N3  2304          // 3*D
#define MROWS (B_E * L_L) // 32768
#define EPS 1e-5f
#define NEGV -10000.0f
#define QSCALE 0.125f     // DH^-0.5

// -------- scratch (allocation-free: __device__ globals) --------
__device__ float g_qkv[(size_t)MROWS * N3];   // fp16 qkv lives in first half
__device__ float g_att[(size_t)MROWS * DD];   // used as fp16
__device__ float g_out1[(size_t)MROWS * DD];
__device__ __half g_ahi[(size_t)MROWS * DD];
__device__ __half g_whi[(size_t)N3 * DD];

// ============================================================
// helpers
// ============================================================
__device__ __forceinline__ uint32_t pack2h(float a, float b) {
    __half2 t = __floats2half2_rn(a, b);
    return *(uint32_t*)&t;
}
__device__ __forceinline__ uint32_t smem_u32(const void* p) {
    uint32_t a;
    asm("{ .reg .u64 t; cvta.to.shared.u64 t, %1; cvt.u32.u64 %0, t; }"
        : "=r"(a) : "l"(p));
    return a;
}

#define MMA_F16(d, a, b)                                                      \
    asm volatile(                                                             \
        "mma.sync.aligned.m16n8k16.row.col.f32.f16.f16.f32 "                  \
        "{%0,%1,%2,%3}, {%4,%5,%6,%7}, {%8,%9}, {%0,%1,%2,%3};"               \
        : "+f"(d[0]), "+f"(d[1]), "+f"(d[2]), "+f"(d[3])                      \
        : "r"(a[0]), "r"(a[1]), "r"(a[2]), "r"(a[3]), "r"(b[0]), "r"(b[1]))

#define LDSM_X4(r0, r1, r2, r3, addr)                                         \
    asm volatile("ldmatrix.sync.aligned.m8n8.x4.shared.b16 {%0,%1,%2,%3}, [%4];" \
        : "=r"(r0), "=r"(r1), "=r"(r2), "=r"(r3) : "r"(addr))
#define LDSM_X4_T(r0, r1, r2, r3, addr)                                       \
    asm volatile("ldmatrix.sync.aligned.m8n8.x4.trans.shared.b16 {%0,%1,%2,%3}, [%4];" \
        : "=r"(r0), "=r"(r1), "=r"(r2), "=r"(r3) : "r"(addr))
#define CP_ASYNC16(s, g)                                                      \
    asm volatile("cp.async.cg.shared.global [%0], [%1], 16;" :: "r"(s), "l"(g))
#define CP_COMMIT  asm volatile("cp.async.commit_group;" ::: "memory")
#define CP_WAIT0   asm volatile("cp.async.wait_group 0;" ::: "memory")
#define CP_WAIT2   asm volatile("cp.async.wait_group 2;" ::: "memory")

// ============================================================
// fp32 -> fp16 convert
// ============================================================
__global__ void __launch_bounds__(256) cvt_kernel(
    const float* __restrict__ in, __half* __restrict__ out, int n4)
{
    int i = blockIdx.x * blockDim.x + threadIdx.x;
    int stride = gridDim.x * blockDim.x;
    for (; i < n4; i += stride) {
        float4 v = ((const float4*)in)[i];
        ((uint32_t*)out)[2 * i + 0] = pack2h(v.x, v.y);
        ((uint32_t*)out)[2 * i + 1] = pack2h(v.z, v.w);
    }
}

// ============================================================
// Warp-MMA fp16 GEMM: C = ah*bh + bias -> fp16 out (q pre-scaled).
// 4-stage cp.async ring, 2 CTAs/SM.
// ============================================================
#define BK 32
#define ASTR 40
#define ROWB (ASTR * 2)               // 80 B
#define TILE_BYTES (128 * ROWB)       // 10240
#define STAGE_BYTES (2 * TILE_BYTES)  // 20480: Ah, Bh
#define NSTAGE 4
#define GEMM_SMEM (NSTAGE * STAGE_BYTES)   // 81920

__device__ __forceinline__ void load_stage_async(
    uint32_t sb, int stage,
    const __half* __restrict__ Ahi, const __half* __restrict__ Whi,
    size_t m0, size_t n0, int k0, int tid)
{
#pragma unroll
    for (int i = 0; i < 4; i++) {
        const int arr = i >> 1;                 // 0:Ah 1:Bh
        const int rem = (i & 1) * 256 + tid;    // 0..511
        const int row = rem >> 2;
        const int seg = rem & 3;
        const __half* src = arr ? Whi : Ahi;
        const size_t r0 = arr ? n0 : m0;
        const void* g = src + (r0 + row) * DD + k0 + seg * 8;
        uint32_t s = sb + stage * STAGE_BYTES + arr * TILE_BYTES
                   + row * ROWB + seg * 16;
        CP_ASYNC16(s, g);
    }
}

__global__ void __launch_bounds__(256, 2) mma_gemm_kernel(
    const __half* __restrict__ Ahi, const __half* __restrict__ Whi,
    const float* __restrict__ bias, __half* __restrict__ Chi)
{
    extern __shared__ char sm[];
    const int tid  = threadIdx.x;
    const int wid  = tid >> 5;
    const int lane = tid & 31;
    const int wm   = wid >> 2;
    const int wn   = wid & 3;
    const int g    = lane >> 2;
    const int tig  = lane & 3;
    const int grp  = lane >> 3;

    const size_t m0 = (size_t)blockIdx.y * 128;
    const size_t n0 = (size_t)blockIdx.x * 128;
    const uint32_t sb = smem_u32(sm);
    const float scale = (blockIdx.x < 6) ? QSCALE : 1.0f;

    const uint32_t aoff = (uint32_t)((wm * 64 + (grp & 1) * 8 + (lane & 7)) * ROWB
                                     + ((grp >> 1) * 8) * 2);
    const uint32_t boff = (uint32_t)((wn * 32 + (grp >> 1) * 8 + (lane & 7)) * ROWB
                                     + ((grp & 1) * 8) * 2);

    float acc[4][4][4];
#pragma unroll
    for (int mt = 0; mt < 4; mt++)
#pragma unroll
        for (int nt = 0; nt < 4; nt++)
#pragma unroll
            for (int r = 0; r < 4; r++) acc[mt][nt][r] = 0.f;

    const int NKT = DD / BK;   // 24
    load_stage_async(sb, 0, Ahi, Whi, m0, n0, 0, tid);      CP_COMMIT;
    load_stage_async(sb, 1, Ahi, Whi, m0, n0, BK, tid);     CP_COMMIT;
    load_stage_async(sb, 2, Ahi, Whi, m0, n0, 2 * BK, tid); CP_COMMIT;

    for (int kt = 0; kt < NKT; kt++) {
        CP_WAIT2;
        __syncthreads();
        if (kt + 3 < NKT)
            load_stage_async(sb, (kt + 3) & (NSTAGE - 1),
                             Ahi, Whi, m0, n0, (kt + 3) * BK, tid);
        CP_COMMIT;

        const uint32_t sA_h = sb + (uint32_t)(kt & (NSTAGE - 1)) * STAGE_BYTES;
        const uint32_t sB_h = sA_h + TILE_BYTES;

#pragma unroll
        for (int kk = 0; kk < 2; kk++) {
            const int kb = kk * 32;   // bytes
            uint32_t ah[4][4];
#pragma unroll
            for (int mt = 0; mt < 4; mt++) {
                LDSM_X4(ah[mt][0], ah[mt][1], ah[mt][2], ah[mt][3],
                        sA_h + aoff + mt * 16 * ROWB + kb);
            }
            uint32_t bh[2][4];
#pragma unroll
            for (int ntp = 0; ntp < 2; ntp++) {
                LDSM_X4(bh[ntp][0], bh[ntp][1], bh[ntp][2], bh[ntp][3],
                        sB_h + boff + ntp * 16 * ROWB + kb);
            }
#pragma unroll
            for (int mt = 0; mt < 4; mt++)
#pragma unroll
                for (int ntp = 0; ntp < 2; ntp++) {
                    MMA_F16(acc[mt][2 * ntp],     ah[mt], (&bh[ntp][0]));
                    MMA_F16(acc[mt][2 * ntp + 1], ah[mt], (&bh[ntp][2]));
                }
        }
    }

    // Epilogue: bias, q-scale, fp16 write
#pragma unroll
    for (int mt = 0; mt < 4; mt++) {
        const size_t row = m0 + wm * 64 + mt * 16 + g;
#pragma unroll
        for (int nt = 0; nt < 4; nt++) {
            const size_t col = n0 + wn * 32 + nt * 8 + tig * 2;
            const float b0 = bias[col], b1 = bias[col + 1];
            ((uint32_t*)Chi)[(row * N3 + col) >> 1] =
                pack2h((acc[mt][nt][0] + b0) * scale, (acc[mt][nt][1] + b1) * scale);
            ((uint32_t*)Chi)[((row + 8) * N3 + col) >> 1] =
                pack2h((acc[mt][nt][2] + b0) * scale, (acc[mt][nt][3] + b1) * scale);
        }
    }
}

// ============================================================
// Flash MMA attention, pure fp16 operands (1-term QK, 1-term PV).
// 128 queries/block, 4 warps, 2 CTAs/SM, K/V double-buffered.
// smem: Q[128][72]; 2 stages x (K,V)[64][72]; nm[256]
// ============================================================
#define QROWB 144                       // 72 halves * 2B
#define ATT_SMEM (18432 + 2 * 36864 + 1024)   // 93184

template<int NKEY>
__device__ __forceinline__ void attn_core(
    const __half* __restrict__ qkv, const int* __restrict__ mask,
    __half* __restrict__ out,
    size_t qtok0, size_t ktok0, size_t ts,
    int mask0, int mstride, int h, char* sm)
{
    const int tid = threadIdx.x, wid = tid >> 5, lane = tid & 31;
    const int g = lane >> 2, tig = lane & 3, grp = lane >> 3;
    const uint32_t sb = smem_u32(sm);
    const uint32_t sQ = sb;
    float* nm = (float*)(sm + 18432 + 2 * 36864);

    // ---- prologue: Q + chunk0 via cp.async ----
#pragma unroll
    for (int it = 0; it < 8; it++) {
        int p = it * 128 + tid;
        int row = p >> 3, seg = p & 7;
        const __half* gp = qkv + (qtok0 + (size_t)row * ts) * N3
                         + (size_t)h * DH + seg * 8;
        CP_ASYNC16(sQ + row * QROWB + seg * 16, gp);
    }
    auto load_chunk = [&](int c) {
        const uint32_t sbase = sb + 18432 + (uint32_t)(c & 1) * 36864;
        const int jb = c * 64;
#pragma unroll
        for (int it = 0; it < 4; it++) {
            int p = it * 128 + tid;
            int tok = p >> 3, seg = p & 7;
            const __half* base = qkv
                + (ktok0 + (size_t)(jb + tok) * ts) * N3 + (size_t)h * DH;
            CP_ASYNC16(sbase + tok * QROWB + seg * 16, base + DD + seg * 8);   // K
            CP_ASYNC16(sbase + 18432 + tok * QROWB + seg * 16,
                       base + 2 * DD + seg * 8);                               // V
        }
    };
    load_chunk(0);
    CP_COMMIT;

    for (int j = tid; j < NKEY; j += 128)
        nm[j] = mask[mask0 + j * mstride] ? NEGV : 0.f;

    const uint32_t qA_off = (uint32_t)((wid * 32 + (grp & 1) * 8 + (lane & 7)) * QROWB
                                       + ((grp >> 1) * 8) * 2);
    const uint32_t kB_off = (uint32_t)(((grp >> 1) * 8 + (lane & 7)) * QROWB
                                       + ((grp & 1) * 8) * 2);
    const uint32_t vB_off = (uint32_t)(((grp & 1) * 8 + (lane & 7)) * QROWB
                                       + ((grp >> 1) * 8) * 2);

    float m_[2][2], l_[2][2], O[2][8][4];
#pragma unroll
    for (int a = 0; a < 2; a++)
#pragma unroll
        for (int b = 0; b < 2; b++) { m_[a][b] = -1e30f; l_[a][b] = 0.f; }
#pragma unroll
    for (int a = 0; a < 2; a++)
#pragma unroll
        for (int b = 0; b < 8; b++)
#pragma unroll
            for (int r = 0; r < 4; r++) O[a][b][r] = 0.f;

    const int NC = NKEY / 64;
    for (int c = 0; c < NC; c++) {
        CP_WAIT0;
        __syncthreads();
        if (c + 1 < NC) { load_chunk(c + 1); CP_COMMIT; }

        const uint32_t sK = sb + 18432 + (uint32_t)(c & 1) * 36864;
        const uint32_t sV = sK + 18432;
        const int jb = c * 64;

        // ---- S = Q K^T ----
        float S[2][8][4];
#pragma unroll
        for (int a = 0; a < 2; a++)
#pragma unroll
            for (int b = 0; b < 8; b++)
#pragma unroll
                for (int r = 0; r < 4; r++) S[a][b][r] = 0.f;

#pragma unroll
        for (int kt = 0; kt < 4; kt++) {
            uint32_t aq[2][4];
#pragma unroll
            for (int mt = 0; mt < 2; mt++) {
                LDSM_X4(aq[mt][0], aq[mt][1], aq[mt][2], aq[mt][3],
                        sQ + qA_off + mt * 16 * QROWB + kt * 32);
            }
#pragma unroll
            for (int ntp = 0; ntp < 4; ntp++) {
                uint32_t kh[4];
                LDSM_X4(kh[0], kh[1], kh[2], kh[3],
                        sK + kB_off + ntp * 16 * QROWB + kt * 32);
#pragma unroll
                for (int mt = 0; mt < 2; mt++) {
                    MMA_F16(S[mt][2 * ntp],     aq[mt], (&kh[0]));
                    MMA_F16(S[mt][2 * ntp + 1], aq[mt], (&kh[2]));
                }
            }
        }

        // ---- mask + online softmax ----
#pragma unroll
        for (int mt = 0; mt < 2; mt++)
#pragma unroll
            for (int rh = 0; rh < 2; rh++) {
                float mx = -1e30f;
#pragma unroll
                for (int nt = 0; nt < 8; nt++) {
                    float v0 = S[mt][nt][rh * 2 + 0] + nm[jb + nt * 8 + 2 * tig];
                    float v1 = S[mt][nt][rh * 2 + 1] + nm[jb + nt * 8 + 2 * tig + 1];
                    S[mt][nt][rh * 2 + 0] = v0;
                    S[mt][nt][rh * 2 + 1] = v1;
                    mx = fmaxf(mx, fmaxf(v0, v1));
                }
                mx = fmaxf(mx, __shfl_xor_sync(0xffffffffu, mx, 1));
                mx = fmaxf(mx, __shfl_xor_sync(0xffffffffu, mx, 2));
                float mnew = fmaxf(m_[mt][rh], mx);
                float corr = __expf(m_[mt][rh] - mnew);
                m_[mt][rh] = mnew;
                float ps = 0.f;
#pragma unroll
                for (int nt = 0; nt < 8; nt++) {
                    float p0 = __expf(S[mt][nt][rh * 2 + 0] - mnew);
                    float p1 = __expf(S[mt][nt][rh * 2 + 1] - mnew);
                    S[mt][nt][rh * 2 + 0] = p0;
                    S[mt][nt][rh * 2 + 1] = p1;
                    ps += p0 + p1;
                }
                ps += __shfl_xor_sync(0xffffffffu, ps, 1);
                ps += __shfl_xor_sync(0xffffffffu, ps, 2);
                l_[mt][rh] = l_[mt][rh] * corr + ps;
#pragma unroll
                for (int nt = 0; nt < 8; nt++) {
                    O[mt][nt][rh * 2 + 0] *= corr;
                    O[mt][nt][rh * 2 + 1] *= corr;
                }
            }

        // ---- O += P V ----
#pragma unroll
        for (int kt = 0; kt < 4; kt++) {
            uint32_t ph[2][4];
#pragma unroll
            for (int mt = 0; mt < 2; mt++) {
                ph[mt][0] = pack2h(S[mt][2 * kt][0],     S[mt][2 * kt][1]);
                ph[mt][1] = pack2h(S[mt][2 * kt][2],     S[mt][2 * kt][3]);
                ph[mt][2] = pack2h(S[mt][2 * kt + 1][0], S[mt][2 * kt + 1][1]);
                ph[mt][3] = pack2h(S[mt][2 * kt + 1][2], S[mt][2 * kt + 1][3]);
            }
#pragma unroll
            for (int ntp = 0; ntp < 4; ntp++) {
                uint32_t vh[4];
                LDSM_X4_T(vh[0], vh[1], vh[2], vh[3],
                          sV + vB_off + kt * 16 * QROWB + ntp * 32);
#pragma unroll
                for (int mt = 0; mt < 2; mt++) {
                    MMA_F16(O[mt][2 * ntp],     ph[mt], (&vh[0]));
                    MMA_F16(O[mt][2 * ntp + 1], ph[mt], (&vh[2]));
                }
            }
        }
    }

    // ---- finalize + write fp16 ----
#pragma unroll
    for (int mt = 0; mt < 2; mt++)
#pragma unroll
        for (int rh = 0; rh < 2; rh++) {
            float inv = 1.f / l_[mt][rh];
            int qr = wid * 32 + mt * 16 + g + rh * 8;
            size_t tok = qtok0 + (size_t)qr * ts;
            __half* op = out + tok * DD + h * DH;
#pragma unroll
            for (int nt = 0; nt < 8; nt++) {
                *(uint32_t*)(op + nt * 8 + 2 * tig) =
                    pack2h(O[mt][nt][rh * 2 + 0] * inv, O[mt][nt][rh * 2 + 1] * inv);
            }
        }
}

__global__ void __launch_bounds__(128, 2) row_attn_mma_kernel(
    const __half* __restrict__ qkv, const int* __restrict__ mask,
    __half* __restrict__ out)
{
    extern __shared__ char sm[];
    const int e = blockIdx.x >> 1, qt = blockIdx.x & 1, h = blockIdx.y;
    attn_core<256>(qkv, mask, out,
                   (size_t)e * L_L + qt * 128, (size_t)e * L_L, 1,
                   e * L_L, 1, h, sm);
}

__global__ void __launch_bounds__(128, 2) col_attn_mma_kernel(
    const __half* __restrict__ qkv, const int* __restrict__ mask,
    __half* __restrict__ out)
{
    extern __shared__ char sm[];
    const int l = blockIdx.x, h = blockIdx.y;
    attn_core<128>(qkv, mask, out,
                   (size_t)l, (size_t)l, L_L,
                   l, L_L, h, sm);
}

// ============================================================
// Fused residual-add + LayerNorm, shuffle reduction (2 barriers).
// b (attention output) is fp16. Optional fp16 convert out.
// ============================================================
__global__ void __launch_bounds__(256) add_ln_kernel(
    const float* __restrict__ a, const __half* __restrict__ b,
    const float* __restrict__ g, const float* __restrict__ beta,
    float* __restrict__ dst, __half* __restrict__ hi)
{
    const int m = blockIdx.x;
    const int t = threadIdx.x;
    const int lane = t & 31, wid = t >> 5;
    __shared__ float red[8], red2[8], bc[2];

    float v[3];
    float s = 0.f, sq = 0.f;
#pragma unroll
    for (int r = 0; r < 3; r++) {
        int idx = t + r * 256;
        v[r] = a[(size_t)m * DD + idx] + __half2float(b[(size_t)m * DD + idx]);
        s += v[r];
        sq += v[r] * v[r];
    }
#pragma unroll
    for (int o = 16; o > 0; o >>= 1) {
        s  += __shfl_xor_sync(0xffffffffu, s, o);
        sq += __shfl_xor_sync(0xffffffffu, sq, o);
    }
    if (lane == 0) { red[wid] = s; red2[wid] = sq; }
    __syncthreads();
    if (wid == 0) {
        float ws = (lane < 8) ? red[lane]  : 0.f;
        float wq = (lane < 8) ? red2[lane] : 0.f;
#pragma unroll
        for (int o = 4; o > 0; o >>= 1) {
            ws += __shfl_xor_sync(0xffffffffu, ws, o);
            wq += __shfl_xor_sync(0xffffffffu, wq, o);
        }
        if (lane == 0) { bc[0] = ws * (1.f / DD); bc[1] = wq * (1.f / DD); }
    }
    __syncthreads();
    const float mu   = bc[0];
    const float rstd = rsqrtf(bc[1] - mu * mu + EPS);

#pragma unroll
    for (int r = 0; r < 3; r++) {
        int idx = t + r * 256;
        float y = (v[r] - mu) * rstd * g[idx] + beta[idx];
        dst[(size_t)m * DD + idx] = y;
        if (hi) hi[(size_t)m * DD + idx] = __float2half_rn(y);
    }
}

// ============================================================
// Launch
// ============================================================
extern "C" void kernel_launch(void* const* d_in, const int* in_sizes, int n_in,
                              void* d_out, int out_size)
{
    const float* x     = (const float*)d_in[0];
    const float* w_row = (const float*)d_in[1];
    const float* b_row = (const float*)d_in[2];
    const float* w_col = (const float*)d_in[3];
    const float* b_col = (const float*)d_in[4];
    const float* g1    = (const float*)d_in[5];
    const float* beta1 = (const float*)d_in[6];
    const float* g2    = (const float*)d_in[7];
    const float* beta2 = (const float*)d_in[8];
    const int*   mask  = (const int*)d_in[9];
    float* out = (float*)d_out;

    float *qkvf, *attf, *out1;
    __half *ahi, *whi;
    cudaGetSymbolAddress((void**)&qkvf, g_qkv);
    cudaGetSymbolAddress((void**)&attf, g_att);
    cudaGetSymbolAddress((void**)&out1, g_out1);
    cudaGetSymbolAddress((void**)&ahi,  g_ahi);
    cudaGetSymbolAddress((void**)&whi,  g_whi);
    __half* qh  = (__half*)qkvf;
    __half* att = (__half*)attf;

    cudaFuncSetAttribute(mma_gemm_kernel,
                         cudaFuncAttributeMaxDynamicSharedMemorySize, GEMM_SMEM);
    cudaFuncSetAttribute(row_attn_mma_kernel,
                         cudaFuncAttributeMaxDynamicSharedMemorySize, ATT_SMEM);
    cudaFuncSetAttribute(col_attn_mma_kernel,
                         cudaFuncAttributeMaxDynamicSharedMemorySize, ATT_SMEM);

    const int nA4 = MROWS * DD / 4;
    const int nW4 = N3 * DD / 4;
    dim3 tcg(N3 / 128, MROWS / 128);   // (18, 256)

    // ---- stage 1: row attention ----
    cvt_kernel<<<4096, 256>>>(x, ahi, nA4);
    cvt_kernel<<<1024, 256>>>(w_row, whi, nW4);
    mma_gemm_kernel<<<tcg, 256, GEMM_SMEM>>>(ahi, whi, b_row, qh);
    row_attn_mma_kernel<<<dim3(256, HH), 128, ATT_SMEM>>>(qh, mask, att);
    add_ln_kernel<<<MROWS, 256>>>(x, att, g1, beta1, out1, ahi);

    // ---- stage 2: column attention ----
    cvt_kernel<<<1024, 256>>>(w_col, whi, nW4);
    mma_gemm_kernel<<<tcg, 256, GEMM_SMEM>>>(ahi, whi, b_col, qh);
    col_attn_mma_kernel<<<dim3(L_L, HH), 128, ATT_SMEM>>>(qh, mask, att);
    add_ln_kernel<<<MROWS, 256>>>(out1, att, g2, beta2, out, (__half*)nullptr);
}

// round 14
// speedup vs baseline: 14.2294x; 1.0968x over previous
#include <cuda_runtime.h>
#include <cuda_fp16.h>
#include <math.h>
#include <cstdint>

// Problem constants
#define B_E 128
#define L_L 256
#define HH  12
#define DH  64
#define DD  768           // H*DH
#define N3  2304          // 3*D
#define MROWS (B_E * L_L) // 32768
#define EPS 1e-5f
#define NEGV -10000.0f
#define QSCALE 0.125f     // DH^-0.5

// -------- scratch (allocation-free: __device__ globals) --------
__device__ float g_qkv[(size_t)MROWS * N3];   // fp16 qkv lives in first half
__device__ float g_att[(size_t)MROWS * DD];   // used as fp16
__device__ float g_out1[(size_t)MROWS * DD];
__device__ __half g_ahi[(size_t)MROWS * DD];
__device__ __half g_whi[(size_t)N3 * DD];

// ============================================================
// helpers
// ============================================================
__device__ __forceinline__ uint32_t pack2h(float a, float b) {
    __half2 t = __floats2half2_rn(a, b);
    return *(uint32_t*)&t;
}
__device__ __forceinline__ uint32_t smem_u32(const void* p) {
    uint32_t a;
    asm("{ .reg .u64 t; cvta.to.shared.u64 t, %1; cvt.u32.u64 %0, t; }"
        : "=r"(a) : "l"(p));
    return a;
}

#define MMA_F16(d, a, b)                                                      \
    asm volatile(                                                             \
        "mma.sync.aligned.m16n8k16.row.col.f32.f16.f16.f32 "                  \
        "{%0,%1,%2,%3}, {%4,%5,%6,%7}, {%8,%9}, {%0,%1,%2,%3};"               \
        : "+f"(d[0]), "+f"(d[1]), "+f"(d[2]), "+f"(d[3])                      \
        : "r"(a[0]), "r"(a[1]), "r"(a[2]), "r"(a[3]), "r"(b[0]), "r"(b[1]))

#define LDSM_X4(r0, r1, r2, r3, addr)                                         \
    asm volatile("ldmatrix.sync.aligned.m8n8.x4.shared.b16 {%0,%1,%2,%3}, [%4];" \
        : "=r"(r0), "=r"(r1), "=r"(r2), "=r"(r3) : "r"(addr))
#define LDSM_X4_T(r0, r1, r2, r3, addr)                                       \
    asm volatile("ldmatrix.sync.aligned.m8n8.x4.trans.shared.b16 {%0,%1,%2,%3}, [%4];" \
        : "=r"(r0), "=r"(r1), "=r"(r2), "=r"(r3) : "r"(addr))
#define CP_ASYNC16(s, g)                                                      \
    asm volatile("cp.async.cg.shared.global [%0], [%1], 16;" :: "r"(s), "l"(g))
#define CP_COMMIT  asm volatile("cp.async.commit_group;" ::: "memory")
#define CP_WAIT0   asm volatile("cp.async.wait_group 0;" ::: "memory")
#define CP_WAIT2   asm volatile("cp.async.wait_group 2;" ::: "memory")

// ============================================================
// fp32 -> fp16 convert
// ============================================================
__global__ void __launch_bounds__(256) cvt_kernel(
    const float* __restrict__ in, __half* __restrict__ out, int n4)
{
    int i = blockIdx.x * blockDim.x + threadIdx.x;
    int stride = gridDim.x * blockDim.x;
    for (; i < n4; i += stride) {
        float4 v = ((const float4*)in)[i];
        ((uint32_t*)out)[2 * i + 0] = pack2h(v.x, v.y);
        ((uint32_t*)out)[2 * i + 1] = pack2h(v.z, v.w);
    }
}

// ============================================================
// Warp-MMA fp16 GEMM: C = ah*bh + bias -> fp16 out (q pre-scaled).
// 4 warps (2x2), 64x64 warp tiles (halves redundant smem reads:
// A x2, B x2 vs previous A x4, B x2). 4-stage cp.async ring, 2 CTAs/SM.
// ============================================================
#define BK 32
#define ASTR 40
#define ROWB (ASTR * 2)               // 80 B
#define TILE_BYTES (128 * ROWB)       // 10240
#define STAGE_BYTES (2 * TILE_BYTES)  // 20480: Ah, Bh
#define NSTAGE 4
#define GEMM_SMEM (NSTAGE * STAGE_BYTES)   // 81920

__device__ __forceinline__ void load_stage_async(
    uint32_t sb, int stage,
    const __half* __restrict__ Ahi, const __half* __restrict__ Whi,
    size_t m0, size_t n0, int k0, int tid)
{
#pragma unroll
    for (int i = 0; i < 8; i++) {
        const int arr = i >> 2;                 // 0:Ah 1:Bh
        const int rem = (i & 3) * 128 + tid;    // 0..511
        const int row = rem >> 2;
        const int seg = rem & 3;
        const __half* src = arr ? Whi : Ahi;
        const size_t r0 = arr ? n0 : m0;
        const void* g = src + (r0 + row) * DD + k0 + seg * 8;
        uint32_t s = sb + stage * STAGE_BYTES + arr * TILE_BYTES
                   + row * ROWB + seg * 16;
        CP_ASYNC16(s, g);
    }
}

__global__ void __launch_bounds__(128, 2) mma_gemm_kernel(
    const __half* __restrict__ Ahi, const __half* __restrict__ Whi,
    const float* __restrict__ bias, __half* __restrict__ Chi)
{
    extern __shared__ char sm[];
    const int tid  = threadIdx.x;
    const int wid  = tid >> 5;
    const int lane = tid & 31;
    const int wm   = wid >> 1;        // 0..1  (64 rows)
    const int wn   = wid & 1;         // 0..1  (64 cols)
    const int g    = lane >> 2;
    const int tig  = lane & 3;
    const int grp  = lane >> 3;

    const size_t m0 = (size_t)blockIdx.y * 128;
    const size_t n0 = (size_t)blockIdx.x * 128;
    const uint32_t sb = smem_u32(sm);
    const float scale = (blockIdx.x < 6) ? QSCALE : 1.0f;

    const uint32_t aoff = (uint32_t)((wm * 64 + (grp & 1) * 8 + (lane & 7)) * ROWB
                                     + ((grp >> 1) * 8) * 2);
    const uint32_t boff = (uint32_t)((wn * 64 + (grp >> 1) * 8 + (lane & 7)) * ROWB
                                     + ((grp & 1) * 8) * 2);

    float acc[4][8][4];
#pragma unroll
    for (int mt = 0; mt < 4; mt++)
#pragma unroll
        for (int nt = 0; nt < 8; nt++)
#pragma unroll
            for (int r = 0; r < 4; r++) acc[mt][nt][r] = 0.f;

    const int NKT = DD / BK;   // 24
    load_stage_async(sb, 0, Ahi, Whi, m0, n0, 0, tid);      CP_COMMIT;
    load_stage_async(sb, 1, Ahi, Whi, m0, n0, BK, tid);     CP_COMMIT;
    load_stage_async(sb, 2, Ahi, Whi, m0, n0, 2 * BK, tid); CP_COMMIT;

    for (int kt = 0; kt < NKT; kt++) {
        CP_WAIT2;
        __syncthreads();
        if (kt + 3 < NKT)
            load_stage_async(sb, (kt + 3) & (NSTAGE - 1),
                             Ahi, Whi, m0, n0, (kt + 3) * BK, tid);
        CP_COMMIT;

        const uint32_t sA_h = sb + (uint32_t)(kt & (NSTAGE - 1)) * STAGE_BYTES;
        const uint32_t sB_h = sA_h + TILE_BYTES;

#pragma unroll
        for (int kk = 0; kk < 2; kk++) {
            const int kb = kk * 32;   // bytes
            uint32_t ah[4][4];
#pragma unroll
            for (int mt = 0; mt < 4; mt++) {
                LDSM_X4(ah[mt][0], ah[mt][1], ah[mt][2], ah[mt][3],
                        sA_h + aoff + mt * 16 * ROWB + kb);
            }
            uint32_t bh[4][4];
#pragma unroll
            for (int ntp = 0; ntp < 4; ntp++) {
                LDSM_X4(bh[ntp][0], bh[ntp][1], bh[ntp][2], bh[ntp][3],
                        sB_h + boff + ntp * 16 * ROWB + kb);
            }
#pragma unroll
            for (int mt = 0; mt < 4; mt++)
#pragma unroll
                for (int ntp = 0; ntp < 4; ntp++) {
                    MMA_F16(acc[mt][2 * ntp],     ah[mt], (&bh[ntp][0]));
                    MMA_F16(acc[mt][2 * ntp + 1], ah[mt], (&bh[ntp][2]));
                }
        }
    }

    // Epilogue: bias, q-scale, fp16 write
#pragma unroll
    for (int mt = 0; mt < 4; mt++) {
        const size_t row = m0 + wm * 64 + mt * 16 + g;
#pragma unroll
        for (int nt = 0; nt < 8; nt++) {
            const size_t col = n0 + wn * 64 + nt * 8 + tig * 2;
            const float b0 = bias[col], b1 = bias[col + 1];
            ((uint32_t*)Chi)[(row * N3 + col) >> 1] =
                pack2h((acc[mt][nt][0] + b0) * scale, (acc[mt][nt][1] + b1) * scale);
            ((uint32_t*)Chi)[((row + 8) * N3 + col) >> 1] =
                pack2h((acc[mt][nt][2] + b0) * scale, (acc[mt][nt][3] + b1) * scale);
        }
    }
}

// ============================================================
// Flash MMA attention, pure fp16 operands (1-term QK, 1-term PV).
// 128 queries/block, 4 warps, 2 CTAs/SM, K/V double-buffered.
// ============================================================
#define QROWB 144                       // 72 halves * 2B
#define ATT_SMEM (18432 + 2 * 36864 + 1024)   // 93184

template<int NKEY>
__device__ __forceinline__ void attn_core(
    const __half* __restrict__ qkv, const int* __restrict__ mask,
    __half* __restrict__ out,
    size_t qtok0, size_t ktok0, size_t ts,
    int mask0, int mstride, int h, char* sm)
{
    const int tid = threadIdx.x, wid = tid >> 5, lane = tid & 31;
    const int g = lane >> 2, tig = lane & 3, grp = lane >> 3;
    const uint32_t sb = smem_u32(sm);
    const uint32_t sQ = sb;
    float* nm = (float*)(sm + 18432 + 2 * 36864);

    // ---- prologue: Q + chunk0 via cp.async ----
#pragma unroll
    for (int it = 0; it < 8; it++) {
        int p = it * 128 + tid;
        int row = p >> 3, seg = p & 7;
        const __half* gp = qkv + (qtok0 + (size_t)row * ts) * N3
                         + (size_t)h * DH + seg * 8;
        CP_ASYNC16(sQ + row * QROWB + seg * 16, gp);
    }
    auto load_chunk = [&](int c) {
        const uint32_t sbase = sb + 18432 + (uint32_t)(c & 1) * 36864;
        const int jb = c * 64;
#pragma unroll
        for (int it = 0; it < 4; it++) {
            int p = it * 128 + tid;
            int tok = p >> 3, seg = p & 7;
            const __half* base = qkv
                + (ktok0 + (size_t)(jb + tok) * ts) * N3 + (size_t)h * DH;
            CP_ASYNC16(sbase + tok * QROWB + seg * 16, base + DD + seg * 8);   // K
            CP_ASYNC16(sbase + 18432 + tok * QROWB + seg * 16,
                       base + 2 * DD + seg * 8);                               // V
        }
    };
    load_chunk(0);
    CP_COMMIT;

    for (int j = tid; j < NKEY; j += 128)
        nm[j] = mask[mask0 + j * mstride] ? NEGV : 0.f;

    const uint32_t qA_off = (uint32_t)((wid * 32 + (grp & 1) * 8 + (lane & 7)) * QROWB
                                       + ((grp >> 1) * 8) * 2);
    const uint32_t kB_off = (uint32_t)(((grp >> 1) * 8 + (lane & 7)) * QROWB
                                       + ((grp & 1) * 8) * 2);
    const uint32_t vB_off = (uint32_t)(((grp & 1) * 8 + (lane & 7)) * QROWB
                                       + ((grp >> 1) * 8) * 2);

    float m_[2][2], l_[2][2], O[2][8][4];
#pragma unroll
    for (int a = 0; a < 2; a++)
#pragma unroll
        for (int b = 0; b < 2; b++) { m_[a][b] = -1e30f; l_[a][b] = 0.f; }
#pragma unroll
    for (int a = 0; a < 2; a++)
#pragma unroll
        for (int b = 0; b < 8; b++)
#pragma unroll
            for (int r = 0; r < 4; r++) O[a][b][r] = 0.f;

    const int NC = NKEY / 64;
    for (int c = 0; c < NC; c++) {
        CP_WAIT0;
        __syncthreads();
        if (c + 1 < NC) { load_chunk(c + 1); CP_COMMIT; }

        const uint32_t sK = sb + 18432 + (uint32_t)(c & 1) * 36864;
        const uint32_t sV = sK + 18432;
        const int jb = c * 64;

        // ---- S = Q K^T ----
        float S[2][8][4];
#pragma unroll
        for (int a = 0; a < 2; a++)
#pragma unroll
            for (int b = 0; b < 8; b++)
#pragma unroll
                for (int r = 0; r < 4; r++) S[a][b][r] = 0.f;

#pragma unroll
        for (int kt = 0; kt < 4; kt++) {
            uint32_t aq[2][4];
#pragma unroll
            for (int mt = 0; mt < 2; mt++) {
                LDSM_X4(aq[mt][0], aq[mt][1], aq[mt][2], aq[mt][3],
                        sQ + qA_off + mt * 16 * QROWB + kt * 32);
            }
#pragma unroll
            for (int ntp = 0; ntp < 4; ntp++) {
                uint32_t kh[4];
                LDSM_X4(kh[0], kh[1], kh[2], kh[3],
                        sK + kB_off + ntp * 16 * QROWB + kt * 32);
#pragma unroll
                for (int mt = 0; mt < 2; mt++) {
                    MMA_F16(S[mt][2 * ntp],     aq[mt], (&kh[0]));
                    MMA_F16(S[mt][2 * ntp + 1], aq[mt], (&kh[2]));
                }
            }
        }

        // ---- mask + online softmax ----
#pragma unroll
        for (int mt = 0; mt < 2; mt++)
#pragma unroll
            for (int rh = 0; rh < 2; rh++) {
                float mx = -1e30f;
#pragma unroll
                for (int nt = 0; nt < 8; nt++) {
                    float v0 = S[mt][nt][rh * 2 + 0] + nm[jb + nt * 8 + 2 * tig];
                    float v1 = S[mt][nt][rh * 2 + 1] + nm[jb + nt * 8 + 2 * tig + 1];
                    S[mt][nt][rh * 2 + 0] = v0;
                    S[mt][nt][rh * 2 + 1] = v1;
                    mx = fmaxf(mx, fmaxf(v0, v1));
                }
                mx = fmaxf(mx, __shfl_xor_sync(0xffffffffu, mx, 1));
                mx = fmaxf(mx, __shfl_xor_sync(0xffffffffu, mx, 2));
                float mnew = fmaxf(m_[mt][rh], mx);
                float corr = __expf(m_[mt][rh] - mnew);
                m_[mt][rh] = mnew;
                float ps = 0.f;
#pragma unroll
                for (int nt = 0; nt < 8; nt++) {
                    float p0 = __expf(S[mt][nt][rh * 2 + 0] - mnew);
                    float p1 = __expf(S[mt][nt][rh * 2 + 1] - mnew);
                    S[mt][nt][rh * 2 + 0] = p0;
                    S[mt][nt][rh * 2 + 1] = p1;
                    ps += p0 + p1;
                }
                ps += __shfl_xor_sync(0xffffffffu, ps, 1);
                ps += __shfl_xor_sync(0xffffffffu, ps, 2);
                l_[mt][rh] = l_[mt][rh] * corr + ps;
#pragma unroll
                for (int nt = 0; nt < 8; nt++) {
                    O[mt][nt][rh * 2 + 0] *= corr;
                    O[mt][nt][rh * 2 + 1] *= corr;
                }
            }

        // ---- O += P V ----
#pragma unroll
        for (int kt = 0; kt < 4; kt++) {
            uint32_t ph[2][4];
#pragma unroll
            for (int mt = 0; mt < 2; mt++) {
                ph[mt][0] = pack2h(S[mt][2 * kt][0],     S[mt][2 * kt][1]);
                ph[mt][1] = pack2h(S[mt][2 * kt][2],     S[mt][2 * kt][3]);
                ph[mt][2] = pack2h(S[mt][2 * kt + 1][0], S[mt][2 * kt + 1][1]);
                ph[mt][3] = pack2h(S[mt][2 * kt + 1][2], S[mt][2 * kt + 1][3]);
            }
#pragma unroll
            for (int ntp = 0; ntp < 4; ntp++) {
                uint32_t vh[4];
                LDSM_X4_T(vh[0], vh[1], vh[2], vh[3],
                          sV + vB_off + kt * 16 * QROWB + ntp * 32);
#pragma unroll
                for (int mt = 0; mt < 2; mt++) {
                    MMA_F16(O[mt][2 * ntp],     ph[mt], (&vh[0]));
                    MMA_F16(O[mt][2 * ntp + 1], ph[mt], (&vh[2]));
                }
            }
        }
    }

    // ---- finalize + write fp16 ----
#pragma unroll
    for (int mt = 0; mt < 2; mt++)
#pragma unroll
        for (int rh = 0; rh < 2; rh++) {
            float inv = 1.f / l_[mt][rh];
            int qr = wid * 32 + mt * 16 + g + rh * 8;
            size_t tok = qtok0 + (size_t)qr * ts;
            __half* op = out + tok * DD + h * DH;
#pragma unroll
            for (int nt = 0; nt < 8; nt++) {
                *(uint32_t*)(op + nt * 8 + 2 * tig) =
                    pack2h(O[mt][nt][rh * 2 + 0] * inv, O[mt][nt][rh * 2 + 1] * inv);
            }
        }
}

__global__ void __launch_bounds__(128, 2) row_attn_mma_kernel(
    const __half* __restrict__ qkv, const int* __restrict__ mask,
    __half* __restrict__ out)
{
    extern __shared__ char sm[];
    const int e = blockIdx.x >> 1, qt = blockIdx.x & 1, h = blockIdx.y;
    attn_core<256>(qkv, mask, out,
                   (size_t)e * L_L + qt * 128, (size_t)e * L_L, 1,
                   e * L_L, 1, h, sm);
}

__global__ void __launch_bounds__(128, 2) col_attn_mma_kernel(
    const __half* __restrict__ qkv, const int* __restrict__ mask,
    __half* __restrict__ out)
{
    extern __shared__ char sm[];
    const int l = blockIdx.x, h = blockIdx.y;
    attn_core<128>(qkv, mask, out,
                   (size_t)l, (size_t)l, L_L,
                   l, L_L, h, sm);
}

// ============================================================
// Fused residual-add + LayerNorm, shuffle reduction (2 barriers).
// b (attention output) is fp16. Optional fp16 convert out.
// ============================================================
__global__ void __launch_bounds__(256) add_ln_kernel(
    const float* __restrict__ a, const __half* __restrict__ b,
    const float* __restrict__ g, const float* __restrict__ beta,
    float* __restrict__ dst, __half* __restrict__ hi)
{
    const int m = blockIdx.x;
    const int t = threadIdx.x;
    const int lane = t & 31, wid = t >> 5;
    __shared__ float red[8], red2[8], bc[2];

    float v[3];
    float s = 0.f, sq = 0.f;
#pragma unroll
    for (int r = 0; r < 3; r++) {
        int idx = t + r * 256;
        v[r] = a[(size_t)m * DD + idx] + __half2float(b[(size_t)m * DD + idx]);
        s += v[r];
        sq += v[r] * v[r];
    }
#pragma unroll
    for (int o = 16; o > 0; o >>= 1) {
        s  += __shfl_xor_sync(0xffffffffu, s, o);
        sq += __shfl_xor_sync(0xffffffffu, sq, o);
    }
    if (lane == 0) { red[wid] = s; red2[wid] = sq; }
    __syncthreads();
    if (wid == 0) {
        float ws = (lane < 8) ? red[lane]  : 0.f;
        float wq = (lane < 8) ? red2[lane] : 0.f;
#pragma unroll
        for (int o = 4; o > 0; o >>= 1) {
            ws += __shfl_xor_sync(0xffffffffu, ws, o);
            wq += __shfl_xor_sync(0xffffffffu, wq, o);
        }
        if (lane == 0) { bc[0] = ws * (1.f / DD); bc[1] = wq * (1.f / DD); }
    }
    __syncthreads();
    const float mu   = bc[0];
    const float rstd = rsqrtf(bc[1] - mu * mu + EPS);

#pragma unroll
    for (int r = 0; r < 3; r++) {
        int idx = t + r * 256;
        float y = (v[r] - mu) * rstd * g[idx] + beta[idx];
        dst[(size_t)m * DD + idx] = y;
        if (hi) hi[(size_t)m * DD + idx] = __float2half_rn(y);
    }
}

// ============================================================
// Launch
// ============================================================
extern "C" void kernel_launch(void* const* d_in, const int* in_sizes, int n_in,
                              void* d_out, int out_size)
{
    const float* x     = (const float*)d_in[0];
    const float* w_row = (const float*)d_in[1];
    const float* b_row = (const float*)d_in[2];
    const float* w_col = (const float*)d_in[3];
    const float* b_col = (const float*)d_in[4];
    const float* g1    = (const float*)d_in[5];
    const float* beta1 = (const float*)d_in[6];
    const float* g2    = (const float*)d_in[7];
    const float* beta2 = (const float*)d_in[8];
    const int*   mask  = (const int*)d_in[9];
    float* out = (float*)d_out;

    float *qkvf, *attf, *out1;
    __half *ahi, *whi;
    cudaGetSymbolAddress((void**)&qkvf, g_qkv);
    cudaGetSymbolAddress((void**)&attf, g_att);
    cudaGetSymbolAddress((void**)&out1, g_out1);
    cudaGetSymbolAddress((void**)&ahi,  g_ahi);
    cudaGetSymbolAddress((void**)&whi,  g_whi);
    __half* qh  = (__half*)qkvf;
    __half* att = (__half*)attf;

    cudaFuncSetAttribute(mma_gemm_kernel,
                         cudaFuncAttributeMaxDynamicSharedMemorySize, GEMM_SMEM);
    cudaFuncSetAttribute(row_attn_mma_kernel,
                         cudaFuncAttributeMaxDynamicSharedMemorySize, ATT_SMEM);
    cudaFuncSetAttribute(col_attn_mma_kernel,
                         cudaFuncAttributeMaxDynamicSharedMemorySize, ATT_SMEM);

    const int nA4 = MROWS * DD / 4;
    const int nW4 = N3 * DD / 4;
    dim3 tcg(N3 / 128, MROWS / 128);   // (18, 256)

    // ---- stage 1: row attention ----
    cvt_kernel<<<4096, 256>>>(x, ahi, nA4);
    cvt_kernel<<<1024, 256>>>(w_row, whi, nW4);
    mma_gemm_kernel<<<tcg, 128, GEMM_SMEM>>>(ahi, whi, b_row, qh);
    row_attn_mma_kernel<<<dim3(256, HH), 128, ATT_SMEM>>>(qh, mask, att);
    add_ln_kernel<<<MROWS, 256>>>(x, att, g1, beta1, out1, ahi);

    // ---- stage 2: column attention ----
    cvt_kernel<<<1024, 256>>>(w_col, whi, nW4);
    mma_gemm_kernel<<<tcg, 128, GEMM_SMEM>>>(ahi, whi, b_col, qh);
    col_attn_mma_kernel<<<dim3(L_L, HH), 128, ATT_SMEM>>>(qh, mask, att);
    add_ln_kernel<<<MROWS, 256>>>(out1, att, g2, beta2, out, (__half*)nullptr);
}